// round 8
// baseline (speedup 1.0000x reference)
#include <cuda_runtime.h>
#include <math.h>
#include <stdint.h>

#define NEGC 1.0e9f
typedef unsigned long long ull;

// ==================== static scratch ====================
__device__ float g_epart[64 * 128];
__device__ float g_emean[128];
__device__ float g_Bmat[4096 * 128];
__device__ float g_qz[512 * 128];
__device__ float g_U[2 * 512 * 1024];
__device__ float g_qhn[4 * 8 * 128 * 128];
__device__ float g_qhnT[4 * 8 * 128 * 128];
__device__ float g_S[512 * 4096];
__device__ float g_Gpart[8 * 512 * 128];
__device__ float g_ET[128 * 32000];          // E transposed (fp32)
__device__ float g_SEpart[148 * 128 * 128];  // per-block partials (compact rows)
__device__ float g_SEsum[148 * 128];
__device__ int   g_SEmt[148];
__device__ int   g_midx[512];
__device__ int   g_mpos[512];
__device__ int   g_mcount;

// ---- f32x2 helpers ----
__device__ __forceinline__ ull pk2(float lo, float hi) {
    ull r; asm("mov.b64 %0, {%1, %2};" : "=l"(r) : "f"(lo), "f"(hi)); return r;
}
__device__ __forceinline__ void fma2(ull &d, ull a, ull b) {
    asm("fma.rn.f32x2 %0, %1, %2, %3;" : "=l"(d) : "l"(a), "l"(b), "l"(d));
}
__device__ __forceinline__ void upk(ull v, float &lo, float &hi) {
    asm("mov.b64 {%0, %1}, %2;" : "=f"(lo), "=f"(hi) : "l"(v));
}

// ---- FMA-pipe exp (no MUFU). Valid for |x| < ~80. ----
__device__ __forceinline__ float fexp(float x) {
    float z = x * 1.4426950408889634f;
    float m = z + 12582912.0f;
    int ni = __float_as_int(m) - 0x4B400000;
    float f = z - (m - 12582912.0f);
    float p = 0.0013333558f;
    p = fmaf(p, f, 0.0096181291f);
    p = fmaf(p, f, 0.0555041087f);
    p = fmaf(p, f, 0.2402265070f);
    p = fmaf(p, f, 0.6931471806f);
    p = fmaf(p, f, 1.0f);
    return p * __int_as_float((ni + 127) << 23);
}
__device__ __forceinline__ float fexp_s(float x) { return fexp(fmaxf(x, -80.f)); }

// ==================== setup ====================
__global__ void k_emean_part(const float* __restrict__ E) {
    int b = blockIdx.x, t = threadIdx.x;
    int d = t & 127, h = t >> 7;
    float s = 0.f;
    for (int v = b * 500 + h; v < b * 500 + 500; v += 2) s += E[v * 128 + d];
    __shared__ float sh[256];
    sh[t] = s; __syncthreads();
    if (t < 128) g_epart[b * 128 + t] = sh[t] + sh[t + 128];
}
__global__ void k_emean_red() {
    int t = threadIdx.x;
    float s = 0.f;
    for (int b = 0; b < 64; b++) s += g_epart[b * 128 + t];
    g_emean[t] = s * (1.0f / 32000.0f);
}

__global__ void k_bmat(const float* __restrict__ T) {
    int idx = blockIdx.x * 256 + threadIdx.x;
    if (idx >= 4096 * 128) return;
    int r = idx >> 7, col = idx & 127;
    float val;
    if (r < 2048) {
        int k = r >> 10, c = (r >> 7) & 7, b = r & 127;
        val = T[((k * 128 + col) * 128 + b) * 8 + c];
    } else {
        int r2 = r - 2048;
        int k = r2 >> 10, c = (r2 >> 7) & 7, a = r2 & 127;
        val = T[((k * 128 + a) * 128 + col) * 8 + c];
    }
    g_Bmat[idx] = val;
}

__global__ void k_transE(const float* __restrict__ E) {
    __shared__ float tile[128][33];
    int v0 = blockIdx.x * 128, d0 = blockIdx.y * 32, t = threadIdx.x;
    for (int idx = t; idx < 4096; idx += 256) {
        int r = idx >> 5, c = idx & 31;
        tile[r][c] = E[(size_t)(v0 + r) * 128 + d0 + c];
    }
    __syncthreads();
    for (int idx = t; idx < 4096; idx += 256) {
        int d = idx >> 7, vv = idx & 127;
        g_ET[(size_t)(d0 + d) * 32000 + v0 + vv] = tile[vv][d];
    }
}

__global__ void k_midx(const int* __restrict__ mask, const int* __restrict__ mmask) {
    __shared__ int pref[512];
    int t = threadIdx.x;
    int f = (mmask[t] != 0 && mask[t] != 0) ? 1 : 0;
    pref[t] = f;
    __syncthreads();
    for (int o = 1; o < 512; o <<= 1) {
        int v = (t >= o) ? pref[t - o] : 0;
        __syncthreads();
        pref[t] += v;
        __syncthreads();
    }
    if (f) { int pos = pref[t] - 1; g_midx[pos] = t; g_mpos[t] = pos; }
    else g_mpos[t] = -1;
    if (t == 511) g_mcount = pref[511];
}

__device__ __forceinline__ float softmax128(float raw, float* r1, float* r2) {
    int lane = threadIdx.x & 31, w = threadIdx.x >> 5;
    float m = raw;
    #pragma unroll
    for (int o = 16; o; o >>= 1) m = fmaxf(m, __shfl_xor_sync(~0u, m, o));
    if (lane == 0) r1[w] = m;
    __syncthreads();
    m = fmaxf(fmaxf(r1[0], r1[1]), fmaxf(r1[2], r1[3]));
    float e = fexp_s(raw - m), s = e;
    #pragma unroll
    for (int o = 16; o; o >>= 1) s += __shfl_xor_sync(~0u, s, o);
    if (lane == 0) r2[w] = s;
    __syncthreads();
    return e / (r2[0] + r2[1] + r2[2] + r2[3]);
}

__global__ void k_init_qz(const float* __restrict__ x, const int* __restrict__ mask,
                          const int* __restrict__ mmask) {
    int zi = blockIdx.x, a = threadIdx.x;
    __shared__ float r1[4], r2[4];
    float keep = mask[zi] ? 1.f : 0.f;
    float mm = (float)mmask[zi];
    float raw = (x[zi * 128 + a] * (1.f - mm) + g_emean[a] * mm) * keep;
    float p = softmax128(raw, r1, r2);
    g_qz[zi * 128 + a] = p * keep;
}

// ==================== small FFMA GEMMs ====================
__global__ void __launch_bounds__(256) k_nn64(const float* __restrict__ T, int which) {
    const float *A, *B; float *C;
    int lda, ldb, ldc, ksteps, kb;
    if (which == 0) {
        int kk = blockIdx.z;
        A = g_qz; lda = 128; B = T + kk * 131072; ldb = 1024;
        C = g_U + (size_t)kk * 524288; ldc = 1024; ksteps = 8; kb = 0;
    } else {
        int ks = blockIdx.z;
        A = g_S; lda = 4096; B = g_Bmat; ldb = 128;
        C = g_Gpart + (size_t)ks * 65536; ldc = 128; ksteps = 32; kb = ks * 512;
    }
    int m0 = blockIdx.y * 64, n0 = blockIdx.x * 64;
    __shared__ float As[16][68], Bs[16][64];
    int t = threadIdx.x, tm = t >> 4, tn = t & 15;
    ull acc[4][2];
    #pragma unroll
    for (int i = 0; i < 4; i++) { acc[i][0] = pk2(0.f, 0.f); acc[i][1] = pk2(0.f, 0.f); }
    for (int s = 0; s < ksteps; s++) {
        int k0 = kb + s * 16;
        { int r = t >> 2, c4 = (t & 3) * 4;
          float4 av = *(const float4*)&A[(size_t)(m0 + r) * lda + k0 + c4];
          As[c4][r] = av.x; As[c4 + 1][r] = av.y; As[c4 + 2][r] = av.z; As[c4 + 3][r] = av.w; }
        { int r = t >> 4, c4 = (t & 15) * 4;
          *(float4*)&Bs[r][c4] = *(const float4*)&B[(size_t)(k0 + r) * ldb + n0 + c4]; }
        __syncthreads();
        #pragma unroll
        for (int p = 0; p < 16; p++) {
            float4 a = *(const float4*)&As[p][tm * 4];
            float4 b = *(const float4*)&Bs[p][tn * 4];
            ull b01 = pk2(b.x, b.y), b23 = pk2(b.z, b.w);
            ull a0 = pk2(a.x, a.x), a1 = pk2(a.y, a.y), a2 = pk2(a.z, a.z), a3 = pk2(a.w, a.w);
            fma2(acc[0][0], a0, b01); fma2(acc[0][1], a0, b23);
            fma2(acc[1][0], a1, b01); fma2(acc[1][1], a1, b23);
            fma2(acc[2][0], a2, b01); fma2(acc[2][1], a2, b23);
            fma2(acc[3][0], a3, b01); fma2(acc[3][1], a3, b23);
        }
        __syncthreads();
    }
    #pragma unroll
    for (int i = 0; i < 4; i++) {
        float c0, c1, c2, c3;
        upk(acc[i][0], c0, c1); upk(acc[i][1], c2, c3);
        *(float4*)&C[(size_t)(m0 + tm * 4 + i) * ldc + n0 + tn * 4] = make_float4(c0, c1, c2, c3);
    }
}

__global__ void __launch_bounds__(256) k_F(const int* __restrict__ mask) {
    int zi = blockIdx.x, z = zi >> 7, i = zi & 127;
    int t = threadIdx.x;
    __shared__ float U_sh[2][1024];
    __shared__ float qz_sh[32][129];
    __shared__ float qh_sh[8][128];
    __shared__ float smax[8], ssum[8];
    for (int idx = t; idx < 2048; idx += 256) {
        int k = idx >> 10, bc = idx & 1023;
        U_sh[k][bc] = g_U[((size_t)k * 512 + zi) * 1024 + bc];
    }
    int j = t & 127, ch = t >> 7;
    int ksel = (j > i) ? 0 : 1;
    float a0 = 0.f, a1 = 0.f, a2 = 0.f, a3 = 0.f;
    const float* qzb = g_qz + z * 128 * 128;
    for (int b0 = 0; b0 < 128; b0 += 32) {
        __syncthreads();
        #pragma unroll
        for (int e = 0; e < 16; e++) {
            int lin = t + e * 256;
            int jj = lin >> 5, col = lin & 31;
            qz_sh[col][jj] = qzb[jj * 128 + b0 + col];
        }
        __syncthreads();
        #pragma unroll 8
        for (int bb = 0; bb < 32; bb++) {
            float qv = qz_sh[bb][j];
            float4 u4 = *(const float4*)&U_sh[ksel][(b0 + bb) * 8 + ch * 4];
            a0 += qv * u4.x; a1 += qv * u4.y; a2 += qv * u4.z; a3 += qv * u4.w;
        }
    }
    bool vi = mask[z * 128 + i] != 0, vj = mask[z * 128 + j] != 0;
    if (i == j || !vi || !vj) { a0 = a1 = a2 = a3 = -NEGC; }
    qh_sh[ch * 4 + 0][j] = a0; qh_sh[ch * 4 + 1][j] = a1;
    qh_sh[ch * 4 + 2][j] = a2; qh_sh[ch * 4 + 3][j] = a3;
    __syncthreads();
    int w = t >> 5, lane = t & 31;
    float v0 = qh_sh[w][lane], v1 = qh_sh[w][lane + 32];
    float v2 = qh_sh[w][lane + 64], v3 = qh_sh[w][lane + 96];
    float mx = fmaxf(fmaxf(v0, v1), fmaxf(v2, v3));
    #pragma unroll
    for (int o = 16; o; o >>= 1) mx = fmaxf(mx, __shfl_xor_sync(~0u, mx, o));
    float sum = fexp_s(v0 - mx) + fexp_s(v1 - mx) + fexp_s(v2 - mx) + fexp_s(v3 - mx);
    #pragma unroll
    for (int o = 16; o; o >>= 1) sum += __shfl_xor_sync(~0u, sum, o);
    if (lane == 0) { smax[w] = mx; ssum[w] = sum; }
    __syncthreads();
    float vals[4] = {a0, a1, a2, a3};
    #pragma unroll
    for (int hh = 0; hh < 4; hh++) {
        int h = ch * 4 + hh;
        float p = fexp_s(vals[hh] - smax[h]) / ssum[h];
        g_qhn[(((z * 8 + h) * 128 + i) << 7) + j] = p;
        g_qhnT[(((z * 8 + h) * 128 + j) << 7) + i] = p;
    }
}

__global__ void __launch_bounds__(256) k_S() {
    int zi = blockIdx.x, z = zi >> 7, i = zi & 127;
    int t = threadIdx.x;
    __shared__ float wT[128][36];
    __shared__ float qzc[32][128];
    for (int idx = t; idx < 4096; idx += 256) {
        int r = idx & 31, j = idx >> 5;
        float v; bool m;
        if (r < 16) {
            int k = r >> 3, c = r & 7;
            v = g_qhn[(((z * 8 + c) * 128 + i) << 7) + j];
            m = (k == 0) ? (j > i) : (j < i);
        } else {
            int r2 = r - 16, k = r2 >> 3, c = r2 & 7;
            v = g_qhnT[(((z * 8 + c) * 128 + i) << 7) + j];
            m = (k == 0) ? (j < i) : (j > i);
        }
        wT[j][r] = m ? v : 0.f;
    }
    int tm = t >> 5, tn = t & 31;
    ull acc[4][2];
    #pragma unroll
    for (int q = 0; q < 4; q++) { acc[q][0] = pk2(0.f, 0.f); acc[q][1] = pk2(0.f, 0.f); }
    for (int j0 = 0; j0 < 128; j0 += 32) {
        __syncthreads();
        for (int idx = t; idx < 4096; idx += 256) {
            int jl = idx >> 7, b = idx & 127;
            qzc[jl][b] = g_qz[((z * 128) + j0 + jl) * 128 + b];
        }
        __syncthreads();
        #pragma unroll 8
        for (int jl = 0; jl < 32; jl++) {
            float4 wv = *(const float4*)&wT[j0 + jl][tm * 4];
            float4 qv = *(const float4*)&qzc[jl][tn * 4];
            ull q01 = pk2(qv.x, qv.y), q23 = pk2(qv.z, qv.w);
            ull w0 = pk2(wv.x, wv.x), w1 = pk2(wv.y, wv.y), w2 = pk2(wv.z, wv.z), w3 = pk2(wv.w, wv.w);
            fma2(acc[0][0], w0, q01); fma2(acc[0][1], w0, q23);
            fma2(acc[1][0], w1, q01); fma2(acc[1][1], w1, q23);
            fma2(acc[2][0], w2, q01); fma2(acc[2][1], w2, q23);
            fma2(acc[3][0], w3, q01); fma2(acc[3][1], w3, q23);
        }
    }
    #pragma unroll
    for (int q = 0; q < 4; q++) {
        int r = tm * 4 + q;
        int base = (r < 16) ? r * 128 : 2048 + (r - 16) * 128;
        float c0, c1, c2, c3;
        upk(acc[q][0], c0, c1); upk(acc[q][1], c2, c3);
        *(float4*)&g_S[(size_t)zi * 4096 + base + tn * 4] = make_float4(c0, c1, c2, c3);
    }
}

__global__ void k_zupd(const float* __restrict__ x, const int* __restrict__ mask,
                       const int* __restrict__ mmask, int useSE) {
    int zi = blockIdx.x, d = threadIdx.x;
    __shared__ float r1[4], r2[4];
    __shared__ int smt[148];
    if (useSE) {
        for (int q = d; q < 148; q += 128) smt[q] = g_SEmt[q];
    }
    __syncthreads();
    float g = 0.f;
    #pragma unroll
    for (int p = 0; p < 8; p++) g += g_Gpart[((size_t)p * 512 + zi) * 128 + d];
    float mm = (float)mmask[zi];
    float se = 0.f;
    if (mm != 0.f) {
        if (useSE) {
            int pos = g_mpos[zi];
            if (pos >= 0) {
                int mt = pos >> 7, row = pos & 127;
                float num = 0.f, den = 0.f;
                for (int bb = 0; bb < 148; bb++) {
                    if (smt[bb] == mt) {
                        num += g_SEpart[((size_t)bb * 128 + row) * 128 + d];
                        den += g_SEsum[bb * 128 + row];
                    }
                }
                se = num / den;
            }
        } else se = g_emean[d];
    }
    float raw = x[zi * 128 + d] * (1.f - mm) + se * mm + g;
    float keep = mask[zi] ? 1.f : 0.f;
    float p_ = softmax128(raw, r1, r2);
    g_qz[zi * 128 + d] = p_ * keep;
}

// ==================== fused SE: v-tile 128, 8m x 8v microtile (1 B/MAC) ====================
#define QZT_OFF 0                         // [128 d][132 m]
#define ETD_OFF (128 * 132)               // [128 d][132 v]  (v tile = 128)
#define EVD_OFF (ETD_OFF + 128 * 132)     // [64 v][132 d]   (per half)
#define PS_OFF  (EVD_OFF + 64 * 132)      // [128 m][68 v]   (per half)
#define SEF_SMEM ((PS_OFF + 128 * 68) * 4)

__global__ void __launch_bounds__(256) k_sef(const float* __restrict__ E) {
    int count = g_mcount;
    if (count == 0) return;
    int ntiles = (count + 127) >> 7;
    int b = blockIdx.x;
    int mt = (b * ntiles) / 148;
    int gb0 = (mt * 148 + ntiles - 1) / ntiles;
    int gb1 = ((mt + 1) * 148 + ntiles - 1) / ntiles;
    int gsz = gb1 - gb0, li = b - gb0;
    int ustart = (li * 250) / gsz;
    int ucount = ((li + 1) * 250) / gsz - ustart;
    int m0 = mt * 128;

    extern __shared__ float sm[];
    float* qzT = sm + QZT_OFF;
    float* Etd = sm + ETD_OFF;
    float* Evd = sm + EVD_OFF;
    float* Ps  = sm + PS_OFF;
    int t = threadIdx.x;

    // load qz (compacted rows) transposed: qzT[d][m]
    {
        int m = t >> 1, d0 = (t & 1) * 64;
        int pos = m0 + m;
        int zi = (pos < count) ? g_midx[pos] : 0;
        const float* src = g_qz + (size_t)zi * 128 + d0;
        #pragma unroll
        for (int q = 0; q < 16; q++) {
            float4 v = *(const float4*)(src + q * 4);
            qzT[(d0 + q * 4 + 0) * 132 + m] = v.x;
            qzT[(d0 + q * 4 + 1) * 132 + m] = v.y;
            qzT[(d0 + q * 4 + 2) * 132 + m] = v.z;
            qzT[(d0 + q * 4 + 3) * 132 + m] = v.w;
        }
    }

    int tm1 = t >> 4, tv8 = t & 15;        // GEMM1: 8m x 8v  (128m x 128v)
    int tmg = t >> 4, tdg = t & 15;        // GEMM2: 8m x 8d
    ull acc[8][4];
    #pragma unroll
    for (int i = 0; i < 8; i++)
        #pragma unroll
        for (int q = 0; q < 4; q++) acc[i][q] = pk2(0.f, 0.f);
    float psum[8];
    #pragma unroll
    for (int i = 0; i < 8; i++) psum[i] = 0.f;

    for (int tile = 0; tile < ucount; tile++) {
        int vg = (ustart + tile) * 128;
        __syncthreads();   // protect Etd/Evd from previous tile's readers
        // load Etd[d][0..128)
        {
            int d = t >> 1, vq = (t & 1) * 64;
            const float* src = g_ET + (size_t)d * 32000 + vg + vq;
            float* dst = Etd + d * 132 + vq;
            #pragma unroll
            for (int q = 0; q < 16; q++) *(float4*)(dst + q * 4) = *(const float4*)(src + q * 4);
        }
        // load Evd half0 (rows vg..vg+63)
        {
            int v = t >> 2, dq = (t & 3) * 32;
            const float* src = E + (size_t)(vg + v) * 128 + dq;
            float* dst = Evd + v * 132 + dq;
            #pragma unroll
            for (int q = 0; q < 8; q++) *(float4*)(dst + q * 4) = *(const float4*)(src + q * 4);
        }
        __syncthreads();
        // GEMM1: L[8m][8v]
        ull L[8][4];
        #pragma unroll
        for (int i = 0; i < 8; i++)
            #pragma unroll
            for (int q = 0; q < 4; q++) L[i][q] = pk2(0.f, 0.f);
        #pragma unroll 2
        for (int d = 0; d < 128; d++) {
            float4 a0 = *(const float4*)&qzT[d * 132 + tm1 * 8];
            float4 a1 = *(const float4*)&qzT[d * 132 + tm1 * 8 + 4];
            float4 b0 = *(const float4*)&Etd[d * 132 + tv8 * 8];
            float4 b1 = *(const float4*)&Etd[d * 132 + tv8 * 8 + 4];
            ull bb[4] = {pk2(b0.x, b0.y), pk2(b0.z, b0.w), pk2(b1.x, b1.y), pk2(b1.z, b1.w)};
            float av[8] = {a0.x, a0.y, a0.z, a0.w, a1.x, a1.y, a1.z, a1.w};
            #pragma unroll
            for (int i = 0; i < 8; i++) {
                ull ai = pk2(av[i], av[i]);
                fma2(L[i][0], ai, bb[0]); fma2(L[i][1], ai, bb[1]);
                fma2(L[i][2], ai, bb[2]); fma2(L[i][3], ai, bb[3]);
            }
        }
        // exp in place + psum
        #pragma unroll
        for (int i = 0; i < 8; i++)
            #pragma unroll
            for (int q = 0; q < 4; q++) {
                float e0, e1;
                upk(L[i][q], e0, e1);
                e0 = fexp(e0); e1 = fexp(e1);
                psum[i] += e0 + e1;
                L[i][q] = pk2(e0, e1);
            }
        // half 0: threads with tv8<8 own v_local = tv8*8..+7 -> write Ps[m][v]
        if (tv8 < 8) {
            #pragma unroll
            for (int i = 0; i < 8; i++) {
                float e0, e1, e2, e3, e4, e5, e6, e7;
                upk(L[i][0], e0, e1); upk(L[i][1], e2, e3);
                upk(L[i][2], e4, e5); upk(L[i][3], e6, e7);
                float* dst = Ps + (tm1 * 8 + i) * 68 + tv8 * 8;
                *(float4*)dst       = make_float4(e0, e1, e2, e3);
                *(float4*)(dst + 4) = make_float4(e4, e5, e6, e7);
            }
        }
        __syncthreads();
        // GEMM2 half0
        #pragma unroll 4
        for (int v = 0; v < 64; v++) {
            const float* pr = Ps + v;
            float4 b0 = *(const float4*)&Evd[v * 132 + tdg * 8];
            float4 b1 = *(const float4*)&Evd[v * 132 + tdg * 8 + 4];
            ull bb[4] = {pk2(b0.x, b0.y), pk2(b0.z, b0.w), pk2(b1.x, b1.y), pk2(b1.z, b1.w)};
            #pragma unroll
            for (int i = 0; i < 8; i++) {
                float a = pr[(tmg * 8 + i) * 68];
                ull ai = pk2(a, a);
                fma2(acc[i][0], ai, bb[0]); fma2(acc[i][1], ai, bb[1]);
                fma2(acc[i][2], ai, bb[2]); fma2(acc[i][3], ai, bb[3]);
            }
        }
        __syncthreads();
        // load Evd half1 + write Ps half1
        {
            int v = t >> 2, dq = (t & 3) * 32;
            const float* src = E + (size_t)(vg + 64 + v) * 128 + dq;
            float* dst = Evd + v * 132 + dq;
            #pragma unroll
            for (int q = 0; q < 8; q++) *(float4*)(dst + q * 4) = *(const float4*)(src + q * 4);
        }
        if (tv8 >= 8) {
            #pragma unroll
            for (int i = 0; i < 8; i++) {
                float e0, e1, e2, e3, e4, e5, e6, e7;
                upk(L[i][0], e0, e1); upk(L[i][1], e2, e3);
                upk(L[i][2], e4, e5); upk(L[i][3], e6, e7);
                float* dst = Ps + (tm1 * 8 + i) * 68 + (tv8 - 8) * 8;
                *(float4*)dst       = make_float4(e0, e1, e2, e3);
                *(float4*)(dst + 4) = make_float4(e4, e5, e6, e7);
            }
        }
        __syncthreads();
        // GEMM2 half1
        #pragma unroll 4
        for (int v = 0; v < 64; v++) {
            const float* pr = Ps + v;
            float4 b0 = *(const float4*)&Evd[v * 132 + tdg * 8];
            float4 b1 = *(const float4*)&Evd[v * 132 + tdg * 8 + 4];
            ull bb[4] = {pk2(b0.x, b0.y), pk2(b0.z, b0.w), pk2(b1.x, b1.y), pk2(b1.z, b1.w)};
            #pragma unroll
            for (int i = 0; i < 8; i++) {
                float a = pr[(tmg * 8 + i) * 68];
                ull ai = pk2(a, a);
                fma2(acc[i][0], ai, bb[0]); fma2(acc[i][1], ai, bb[1]);
                fma2(acc[i][2], ai, bb[2]); fma2(acc[i][3], ai, bb[3]);
            }
        }
    }
    // write acc to per-block partial slot
    #pragma unroll
    for (int i = 0; i < 8; i++) {
        float f[8];
        upk(acc[i][0], f[0], f[1]); upk(acc[i][1], f[2], f[3]);
        upk(acc[i][2], f[4], f[5]); upk(acc[i][3], f[6], f[7]);
        size_t base = ((size_t)b * 128 + tmg * 8 + i) * 128 + tdg * 8;
        *(float4*)&g_SEpart[base]     = make_float4(f[0], f[1], f[2], f[3]);
        *(float4*)&g_SEpart[base + 4] = make_float4(f[4], f[5], f[6], f[7]);
    }
    // reduce psum across the 16 v-groups (reuse Etd area: [128 m][17])
    __syncthreads();
    float* red = Etd;
    #pragma unroll
    for (int i = 0; i < 8; i++) red[(tm1 * 8 + i) * 17 + tv8] = psum[i];
    __syncthreads();
    if (t < 128) {
        float s = 0.f;
        #pragma unroll
        for (int q = 0; q < 16; q++) s += red[t * 17 + q];
        g_SEsum[b * 128 + t] = s;
    }
    if (t == 0) g_SEmt[b] = mt;
}

// ==================== final out = qz @ E^T ====================
__global__ void __launch_bounds__(256) k_msg(const float* __restrict__ E, float* __restrict__ out) {
    __shared__ float As[8][128], Bs[8][128];
    int t = threadIdx.x;
    int m0 = blockIdx.y * 128, n0 = blockIdx.x * 128;
    int row = t >> 1, kq = (t & 1) * 4;
    int tm = t >> 4, tn = t & 15;
    ull acc[8][4];
    #pragma unroll
    for (int i = 0; i < 8; i++)
        #pragma unroll
        for (int q = 0; q < 4; q++) acc[i][q] = pk2(0.f, 0.f);
    for (int s = 0; s < 16; s++) {
        int k0 = s * 8;
        float4 av = *(const float4*)&g_qz[(m0 + row) * 128 + k0 + kq];
        float4 bv = *(const float4*)&E[(size_t)(n0 + row) * 128 + k0 + kq];
        __syncthreads();
        As[kq][row] = av.x; As[kq + 1][row] = av.y; As[kq + 2][row] = av.z; As[kq + 3][row] = av.w;
        Bs[kq][row] = bv.x; Bs[kq + 1][row] = bv.y; Bs[kq + 2][row] = bv.z; Bs[kq + 3][row] = bv.w;
        __syncthreads();
        #pragma unroll
        for (int p = 0; p < 8; p++) {
            float4 a0 = *(const float4*)&As[p][tm * 8], a1 = *(const float4*)&As[p][tm * 8 + 4];
            float4 b0 = *(const float4*)&Bs[p][tn * 8], b1 = *(const float4*)&Bs[p][tn * 8 + 4];
            ull bb[4] = {pk2(b0.x, b0.y), pk2(b0.z, b0.w), pk2(b1.x, b1.y), pk2(b1.z, b1.w)};
            float avv[8] = {a0.x, a0.y, a0.z, a0.w, a1.x, a1.y, a1.z, a1.w};
            #pragma unroll
            for (int i = 0; i < 8; i++) {
                ull ai = pk2(avv[i], avv[i]);
                fma2(acc[i][0], ai, bb[0]); fma2(acc[i][1], ai, bb[1]);
                fma2(acc[i][2], ai, bb[2]); fma2(acc[i][3], ai, bb[3]);
            }
        }
    }
    #pragma unroll
    for (int i = 0; i < 8; i++) {
        float f[8];
        upk(acc[i][0], f[0], f[1]); upk(acc[i][1], f[2], f[3]);
        upk(acc[i][2], f[4], f[5]); upk(acc[i][3], f[6], f[7]);
        size_t base = (size_t)(m0 + tm * 8 + i) * 32000 + n0 + tn * 8;
        *(float4*)&out[base] = make_float4(f[0], f[1], f[2], f[3]);
        *(float4*)&out[base + 4] = make_float4(f[4], f[5], f[6], f[7]);
    }
}

// ==================== launch ====================
extern "C" void kernel_launch(void* const* d_in, const int* in_sizes, int n_in,
                              void* d_out, int out_size) {
    const float* x    = (const float*)d_in[0];
    const int*   mask = (const int*)d_in[1];
    const float* E    = (const float*)d_in[2];
    const int*   mm   = (const int*)d_in[3];
    const float* T    = (const float*)d_in[4];
    float* out = (float*)d_out;

    cudaFuncSetAttribute(k_sef, cudaFuncAttributeMaxDynamicSharedMemorySize, SEF_SMEM);

    k_emean_part<<<64, 256>>>(E);
    k_emean_red<<<1, 128>>>();
    k_bmat<<<2048, 256>>>(T);
    k_transE<<<dim3(250, 4), 256>>>(E);
    k_midx<<<1, 512>>>(mask, mm);
    k_init_qz<<<512, 128>>>(x, mask, mm);
    for (int it = 0; it < 4; it++) {
        k_nn64<<<dim3(16, 8, 2), 256>>>(T, 0);     // U = qz @ T[k]
        k_F<<<512, 256>>>(mask);                   // F + softmax -> qhn, qhnT
        k_S<<<512, 256>>>();                       // s1|s2 -> S
        k_nn64<<<dim3(2, 8, 8), 256>>>(T, 1);      // Gpart = S @ Bmat
        k_zupd<<<512, 128>>>(x, mask, mm, it > 0); // z update (+compact SE combine)
        if (it < 3) k_sef<<<148, 256, SEF_SMEM>>>(E);      // fused SE, masked rows only
        else        k_msg<<<dim3(250, 4), 256>>>(E, out);  // final output
    }
}

// round 9
// speedup vs baseline: 1.0688x; 1.0688x over previous
#include <cuda_runtime.h>
#include <math.h>
#include <stdint.h>

#define NEGC 1.0e9f
typedef unsigned long long ull;

// ==================== static scratch ====================
__device__ float g_epart[64 * 128];
__device__ float g_emean[128];
__device__ float g_Bmat[4096 * 128];
__device__ float g_qz[512 * 128];
__device__ float g_U[2 * 512 * 1024];
__device__ float g_qhn[4 * 8 * 128 * 128];
__device__ float g_qhnT[4 * 8 * 128 * 128];
__device__ float g_S[512 * 4096];
__device__ float g_Gpart[8 * 512 * 128];
__device__ float g_ET[128 * 32000];          // E transposed (fp32)
__device__ float g_SEpart[148 * 128 * 128];  // per-block partials (compact rows)
__device__ float g_SEsum[148 * 128];
__device__ int   g_SEmt[148];
__device__ int   g_midx[512];
__device__ int   g_mpos[512];
__device__ int   g_mcount;

// ---- f32x2 helpers ----
__device__ __forceinline__ ull pk2(float lo, float hi) {
    ull r; asm("mov.b64 %0, {%1, %2};" : "=l"(r) : "f"(lo), "f"(hi)); return r;
}
__device__ __forceinline__ void fma2(ull &d, ull a, ull b) {
    asm("fma.rn.f32x2 %0, %1, %2, %3;" : "=l"(d) : "l"(a), "l"(b), "l"(d));
}
__device__ __forceinline__ void upk(ull v, float &lo, float &hi) {
    asm("mov.b64 {%0, %1}, %2;" : "=f"(lo), "=f"(hi) : "l"(v));
}

// ---- FMA-pipe exp (no MUFU). Valid for |x| < ~80. ----
__device__ __forceinline__ float fexp(float x) {
    float z = x * 1.4426950408889634f;
    float m = z + 12582912.0f;
    int ni = __float_as_int(m) - 0x4B400000;
    float f = z - (m - 12582912.0f);
    float p = 0.0013333558f;
    p = fmaf(p, f, 0.0096181291f);
    p = fmaf(p, f, 0.0555041087f);
    p = fmaf(p, f, 0.2402265070f);
    p = fmaf(p, f, 0.6931471806f);
    p = fmaf(p, f, 1.0f);
    return p * __int_as_float((ni + 127) << 23);
}
__device__ __forceinline__ float fexp_s(float x) { return fexp(fmaxf(x, -80.f)); }

// ==================== setup ====================
__global__ void k_emean_part(const float* __restrict__ E) {
    int b = blockIdx.x, t = threadIdx.x;
    int d = t & 127, h = t >> 7;
    float s = 0.f;
    for (int v = b * 500 + h; v < b * 500 + 500; v += 2) s += E[v * 128 + d];
    __shared__ float sh[256];
    sh[t] = s; __syncthreads();
    if (t < 128) g_epart[b * 128 + t] = sh[t] + sh[t + 128];
}
__global__ void k_emean_red() {
    int t = threadIdx.x;
    float s = 0.f;
    for (int b = 0; b < 64; b++) s += g_epart[b * 128 + t];
    g_emean[t] = s * (1.0f / 32000.0f);
}

__global__ void k_bmat(const float* __restrict__ T) {
    int idx = blockIdx.x * 256 + threadIdx.x;
    if (idx >= 4096 * 128) return;
    int r = idx >> 7, col = idx & 127;
    float val;
    if (r < 2048) {
        int k = r >> 10, c = (r >> 7) & 7, b = r & 127;
        val = T[((k * 128 + col) * 128 + b) * 8 + c];
    } else {
        int r2 = r - 2048;
        int k = r2 >> 10, c = (r2 >> 7) & 7, a = r2 & 127;
        val = T[((k * 128 + a) * 128 + col) * 8 + c];
    }
    g_Bmat[idx] = val;
}

__global__ void k_transE(const float* __restrict__ E) {
    __shared__ float tile[128][33];
    int v0 = blockIdx.x * 128, d0 = blockIdx.y * 32, t = threadIdx.x;
    for (int idx = t; idx < 4096; idx += 256) {
        int r = idx >> 5, c = idx & 31;
        tile[r][c] = E[(size_t)(v0 + r) * 128 + d0 + c];
    }
    __syncthreads();
    for (int idx = t; idx < 4096; idx += 256) {
        int d = idx >> 7, vv = idx & 127;
        g_ET[(size_t)(d0 + d) * 32000 + v0 + vv] = tile[vv][d];
    }
}

__global__ void k_midx(const int* __restrict__ mask, const int* __restrict__ mmask) {
    __shared__ int pref[512];
    int t = threadIdx.x;
    int f = (mmask[t] != 0 && mask[t] != 0) ? 1 : 0;
    pref[t] = f;
    __syncthreads();
    for (int o = 1; o < 512; o <<= 1) {
        int v = (t >= o) ? pref[t - o] : 0;
        __syncthreads();
        pref[t] += v;
        __syncthreads();
    }
    if (f) { int pos = pref[t] - 1; g_midx[pos] = t; g_mpos[t] = pos; }
    else g_mpos[t] = -1;
    if (t == 511) g_mcount = pref[511];
}

__device__ __forceinline__ float softmax128(float raw, float* r1, float* r2) {
    int lane = threadIdx.x & 31, w = threadIdx.x >> 5;
    float m = raw;
    #pragma unroll
    for (int o = 16; o; o >>= 1) m = fmaxf(m, __shfl_xor_sync(~0u, m, o));
    if (lane == 0) r1[w] = m;
    __syncthreads();
    m = fmaxf(fmaxf(r1[0], r1[1]), fmaxf(r1[2], r1[3]));
    float e = fexp_s(raw - m), s = e;
    #pragma unroll
    for (int o = 16; o; o >>= 1) s += __shfl_xor_sync(~0u, s, o);
    if (lane == 0) r2[w] = s;
    __syncthreads();
    return e / (r2[0] + r2[1] + r2[2] + r2[3]);
}

__global__ void k_init_qz(const float* __restrict__ x, const int* __restrict__ mask,
                          const int* __restrict__ mmask) {
    int zi = blockIdx.x, a = threadIdx.x;
    __shared__ float r1[4], r2[4];
    float keep = mask[zi] ? 1.f : 0.f;
    float mm = (float)mmask[zi];
    float raw = (x[zi * 128 + a] * (1.f - mm) + g_emean[a] * mm) * keep;
    float p = softmax128(raw, r1, r2);
    g_qz[zi * 128 + a] = p * keep;
}

// ==================== small FFMA GEMMs ====================
__global__ void __launch_bounds__(256) k_nn64(const float* __restrict__ T, int which) {
    const float *A, *B; float *C;
    int lda, ldb, ldc, ksteps, kb;
    if (which == 0) {
        int kk = blockIdx.z;
        A = g_qz; lda = 128; B = T + kk * 131072; ldb = 1024;
        C = g_U + (size_t)kk * 524288; ldc = 1024; ksteps = 8; kb = 0;
    } else {
        int ks = blockIdx.z;
        A = g_S; lda = 4096; B = g_Bmat; ldb = 128;
        C = g_Gpart + (size_t)ks * 65536; ldc = 128; ksteps = 32; kb = ks * 512;
    }
    int m0 = blockIdx.y * 64, n0 = blockIdx.x * 64;
    __shared__ float As[16][68], Bs[16][64];
    int t = threadIdx.x, tm = t >> 4, tn = t & 15;
    ull acc[4][2];
    #pragma unroll
    for (int i = 0; i < 4; i++) { acc[i][0] = pk2(0.f, 0.f); acc[i][1] = pk2(0.f, 0.f); }
    for (int s = 0; s < ksteps; s++) {
        int k0 = kb + s * 16;
        { int r = t >> 2, c4 = (t & 3) * 4;
          float4 av = *(const float4*)&A[(size_t)(m0 + r) * lda + k0 + c4];
          As[c4][r] = av.x; As[c4 + 1][r] = av.y; As[c4 + 2][r] = av.z; As[c4 + 3][r] = av.w; }
        { int r = t >> 4, c4 = (t & 15) * 4;
          *(float4*)&Bs[r][c4] = *(const float4*)&B[(size_t)(k0 + r) * ldb + n0 + c4]; }
        __syncthreads();
        #pragma unroll
        for (int p = 0; p < 16; p++) {
            float4 a = *(const float4*)&As[p][tm * 4];
            float4 b = *(const float4*)&Bs[p][tn * 4];
            ull b01 = pk2(b.x, b.y), b23 = pk2(b.z, b.w);
            ull a0 = pk2(a.x, a.x), a1 = pk2(a.y, a.y), a2 = pk2(a.z, a.z), a3 = pk2(a.w, a.w);
            fma2(acc[0][0], a0, b01); fma2(acc[0][1], a0, b23);
            fma2(acc[1][0], a1, b01); fma2(acc[1][1], a1, b23);
            fma2(acc[2][0], a2, b01); fma2(acc[2][1], a2, b23);
            fma2(acc[3][0], a3, b01); fma2(acc[3][1], a3, b23);
        }
        __syncthreads();
    }
    #pragma unroll
    for (int i = 0; i < 4; i++) {
        float c0, c1, c2, c3;
        upk(acc[i][0], c0, c1); upk(acc[i][1], c2, c3);
        *(float4*)&C[(size_t)(m0 + tm * 4 + i) * ldc + n0 + tn * 4] = make_float4(c0, c1, c2, c3);
    }
}

__global__ void __launch_bounds__(256) k_F(const int* __restrict__ mask) {
    int zi = blockIdx.x, z = zi >> 7, i = zi & 127;
    int t = threadIdx.x;
    __shared__ float U_sh[2][1024];
    __shared__ float qz_sh[32][129];
    __shared__ float qh_sh[8][128];
    __shared__ float smax[8], ssum[8];
    for (int idx = t; idx < 2048; idx += 256) {
        int k = idx >> 10, bc = idx & 1023;
        U_sh[k][bc] = g_U[((size_t)k * 512 + zi) * 1024 + bc];
    }
    int j = t & 127, ch = t >> 7;
    int ksel = (j > i) ? 0 : 1;
    float a0 = 0.f, a1 = 0.f, a2 = 0.f, a3 = 0.f;
    const float* qzb = g_qz + z * 128 * 128;
    for (int b0 = 0; b0 < 128; b0 += 32) {
        __syncthreads();
        #pragma unroll
        for (int e = 0; e < 16; e++) {
            int lin = t + e * 256;
            int jj = lin >> 5, col = lin & 31;
            qz_sh[col][jj] = qzb[jj * 128 + b0 + col];
        }
        __syncthreads();
        #pragma unroll 8
        for (int bb = 0; bb < 32; bb++) {
            float qv = qz_sh[bb][j];
            float4 u4 = *(const float4*)&U_sh[ksel][(b0 + bb) * 8 + ch * 4];
            a0 += qv * u4.x; a1 += qv * u4.y; a2 += qv * u4.z; a3 += qv * u4.w;
        }
    }
    bool vi = mask[z * 128 + i] != 0, vj = mask[z * 128 + j] != 0;
    if (i == j || !vi || !vj) { a0 = a1 = a2 = a3 = -NEGC; }
    qh_sh[ch * 4 + 0][j] = a0; qh_sh[ch * 4 + 1][j] = a1;
    qh_sh[ch * 4 + 2][j] = a2; qh_sh[ch * 4 + 3][j] = a3;
    __syncthreads();
    int w = t >> 5, lane = t & 31;
    float v0 = qh_sh[w][lane], v1 = qh_sh[w][lane + 32];
    float v2 = qh_sh[w][lane + 64], v3 = qh_sh[w][lane + 96];
    float mx = fmaxf(fmaxf(v0, v1), fmaxf(v2, v3));
    #pragma unroll
    for (int o = 16; o; o >>= 1) mx = fmaxf(mx, __shfl_xor_sync(~0u, mx, o));
    float sum = fexp_s(v0 - mx) + fexp_s(v1 - mx) + fexp_s(v2 - mx) + fexp_s(v3 - mx);
    #pragma unroll
    for (int o = 16; o; o >>= 1) sum += __shfl_xor_sync(~0u, sum, o);
    if (lane == 0) { smax[w] = mx; ssum[w] = sum; }
    __syncthreads();
    float vals[4] = {a0, a1, a2, a3};
    #pragma unroll
    for (int hh = 0; hh < 4; hh++) {
        int h = ch * 4 + hh;
        float p = fexp_s(vals[hh] - smax[h]) / ssum[h];
        g_qhn[(((z * 8 + h) * 128 + i) << 7) + j] = p;
        g_qhnT[(((z * 8 + h) * 128 + j) << 7) + i] = p;
    }
}

__global__ void __launch_bounds__(256) k_S() {
    int zi = blockIdx.x, z = zi >> 7, i = zi & 127;
    int t = threadIdx.x;
    __shared__ float wT[128][36];
    __shared__ float qzc[32][128];
    for (int idx = t; idx < 4096; idx += 256) {
        int r = idx & 31, j = idx >> 5;
        float v; bool m;
        if (r < 16) {
            int k = r >> 3, c = r & 7;
            v = g_qhn[(((z * 8 + c) * 128 + i) << 7) + j];
            m = (k == 0) ? (j > i) : (j < i);
        } else {
            int r2 = r - 16, k = r2 >> 3, c = r2 & 7;
            v = g_qhnT[(((z * 8 + c) * 128 + i) << 7) + j];
            m = (k == 0) ? (j < i) : (j > i);
        }
        wT[j][r] = m ? v : 0.f;
    }
    int tm = t >> 5, tn = t & 31;
    ull acc[4][2];
    #pragma unroll
    for (int q = 0; q < 4; q++) { acc[q][0] = pk2(0.f, 0.f); acc[q][1] = pk2(0.f, 0.f); }
    for (int j0 = 0; j0 < 128; j0 += 32) {
        __syncthreads();
        for (int idx = t; idx < 4096; idx += 256) {
            int jl = idx >> 7, b = idx & 127;
            qzc[jl][b] = g_qz[((z * 128) + j0 + jl) * 128 + b];
        }
        __syncthreads();
        #pragma unroll 8
        for (int jl = 0; jl < 32; jl++) {
            float4 wv = *(const float4*)&wT[j0 + jl][tm * 4];
            float4 qv = *(const float4*)&qzc[jl][tn * 4];
            ull q01 = pk2(qv.x, qv.y), q23 = pk2(qv.z, qv.w);
            ull w0 = pk2(wv.x, wv.x), w1 = pk2(wv.y, wv.y), w2 = pk2(wv.z, wv.z), w3 = pk2(wv.w, wv.w);
            fma2(acc[0][0], w0, q01); fma2(acc[0][1], w0, q23);
            fma2(acc[1][0], w1, q01); fma2(acc[1][1], w1, q23);
            fma2(acc[2][0], w2, q01); fma2(acc[2][1], w2, q23);
            fma2(acc[3][0], w3, q01); fma2(acc[3][1], w3, q23);
        }
    }
    #pragma unroll
    for (int q = 0; q < 4; q++) {
        int r = tm * 4 + q;
        int base = (r < 16) ? r * 128 : 2048 + (r - 16) * 128;
        float c0, c1, c2, c3;
        upk(acc[q][0], c0, c1); upk(acc[q][1], c2, c3);
        *(float4*)&g_S[(size_t)zi * 4096 + base + tn * 4] = make_float4(c0, c1, c2, c3);
    }
}

__global__ void k_zupd(const float* __restrict__ x, const int* __restrict__ mask,
                       const int* __restrict__ mmask, int useSE) {
    int zi = blockIdx.x, d = threadIdx.x;
    __shared__ float r1[4], r2[4];
    __shared__ int smt[148];
    if (useSE) {
        for (int q = d; q < 148; q += 128) smt[q] = g_SEmt[q];
    }
    __syncthreads();
    float g = 0.f;
    #pragma unroll
    for (int p = 0; p < 8; p++) g += g_Gpart[((size_t)p * 512 + zi) * 128 + d];
    float mm = (float)mmask[zi];
    float se = 0.f;
    if (mm != 0.f) {
        if (useSE) {
            int pos = g_mpos[zi];
            if (pos >= 0) {
                int mt = pos >> 7, row = pos & 127;
                float num = 0.f, den = 0.f;
                for (int bb = 0; bb < 148; bb++) {
                    if (smt[bb] == mt) {
                        num += g_SEpart[((size_t)bb * 128 + row) * 128 + d];
                        den += g_SEsum[bb * 128 + row];
                    }
                }
                se = num / den;
            }
        } else se = g_emean[d];
    }
    float raw = x[zi * 128 + d] * (1.f - mm) + se * mm + g;
    float keep = mask[zi] ? 1.f : 0.f;
    float p_ = softmax128(raw, r1, r2);
    g_qz[zi * 128 + d] = p_ * keep;
}

// ==================== fused SE on compacted masked rows (R7 layout) ====================
#define QZT_OFF 0                      // [128 d][132 m]
#define ETD_OFF (128 * 132)            // [128 d][68 v]
#define EVD_OFF (ETD_OFF + 128 * 68)   // [64 v][132 d]
#define PS_OFF  (EVD_OFF + 64 * 132)   // [64 v][132 m]
#define SEF_SMEM ((PS_OFF + 64 * 132) * 4)

__global__ void __launch_bounds__(256) k_sef(const float* __restrict__ E) {
    int count = g_mcount;
    if (count == 0) return;
    int ntiles = (count + 127) >> 7;
    int b = blockIdx.x;
    int mt = (b * ntiles) / 148;
    int gb0 = (mt * 148 + ntiles - 1) / ntiles;
    int gb1 = ((mt + 1) * 148 + ntiles - 1) / ntiles;
    int gsz = gb1 - gb0, li = b - gb0;
    int ustart = (li * 500) / gsz;
    int ucount = ((li + 1) * 500) / gsz - ustart;
    int m0 = mt * 128;

    extern __shared__ float sm[];
    float* qzT = sm + QZT_OFF;
    float* Etd = sm + ETD_OFF;
    float* Evd = sm + EVD_OFF;
    float* Ps  = sm + PS_OFF;
    int t = threadIdx.x;

    {
        int m = t >> 1, d0 = (t & 1) * 64;
        int pos = m0 + m;
        int zi = (pos < count) ? g_midx[pos] : 0;
        const float* src = g_qz + (size_t)zi * 128 + d0;
        #pragma unroll
        for (int q = 0; q < 16; q++) {
            float4 v = *(const float4*)(src + q * 4);
            qzT[(d0 + q * 4 + 0) * 132 + m] = v.x;
            qzT[(d0 + q * 4 + 1) * 132 + m] = v.y;
            qzT[(d0 + q * 4 + 2) * 132 + m] = v.z;
            qzT[(d0 + q * 4 + 3) * 132 + m] = v.w;
        }
    }

    int tm1 = t >> 4, tv = t & 15;          // GEMM1: 8m x 4v
    int tmg = t >> 4, tdg = t & 15;         // GEMM2: 8m x 8d
    ull acc[8][4];
    #pragma unroll
    for (int i = 0; i < 8; i++)
        #pragma unroll
        for (int q = 0; q < 4; q++) acc[i][q] = pk2(0.f, 0.f);
    float psum[8];
    #pragma unroll
    for (int i = 0; i < 8; i++) psum[i] = 0.f;

    for (int tile = 0; tile < ucount; tile++) {
        int vg = (ustart + tile) * 64;
        __syncthreads();
        {
            int d = t >> 1, vq = (t & 1) * 32;
            const float* src = g_ET + (size_t)d * 32000 + vg + vq;
            float* dst = Etd + d * 68 + vq;
            #pragma unroll
            for (int q = 0; q < 8; q++) *(float4*)(dst + q * 4) = *(const float4*)(src + q * 4);
        }
        {
            int v = t >> 2, dq = (t & 3) * 32;
            const float* src = E + (size_t)(vg + v) * 128 + dq;
            float* dst = Evd + v * 132 + dq;
            #pragma unroll
            for (int q = 0; q < 8; q++) *(float4*)(dst + q * 4) = *(const float4*)(src + q * 4);
        }
        __syncthreads();
        // GEMM1: L[8m][4v]
        ull L[8][2];
        #pragma unroll
        for (int i = 0; i < 8; i++) { L[i][0] = pk2(0.f, 0.f); L[i][1] = pk2(0.f, 0.f); }
        #pragma unroll 4
        for (int d = 0; d < 128; d++) {
            float4 a0 = *(const float4*)&qzT[d * 132 + tm1 * 8];
            float4 a1 = *(const float4*)&qzT[d * 132 + tm1 * 8 + 4];
            float4 bq = *(const float4*)&Etd[d * 68 + tv * 4];
            ull b01 = pk2(bq.x, bq.y), b23 = pk2(bq.z, bq.w);
            float av[8] = {a0.x, a0.y, a0.z, a0.w, a1.x, a1.y, a1.z, a1.w};
            #pragma unroll
            for (int i = 0; i < 8; i++) {
                ull ai = pk2(av[i], av[i]);
                fma2(L[i][0], ai, b01); fma2(L[i][1], ai, b23);
            }
        }
        // exp + write P^T[v][m] + rowsum partials
        #pragma unroll
        for (int i = 0; i < 8; i++) {
            float e0, e1, e2, e3;
            upk(L[i][0], e0, e1); upk(L[i][1], e2, e3);
            e0 = fexp(e0); e1 = fexp(e1); e2 = fexp(e2); e3 = fexp(e3);
            psum[i] += e0 + e1 + e2 + e3;
            int m = tm1 * 8 + i;
            Ps[(tv * 4 + 0) * 132 + m] = e0;
            Ps[(tv * 4 + 1) * 132 + m] = e1;
            Ps[(tv * 4 + 2) * 132 + m] = e2;
            Ps[(tv * 4 + 3) * 132 + m] = e3;
        }
        __syncthreads();
        // GEMM2: acc[8m][8d] += P^T' @ Evd
        #pragma unroll 4
        for (int v = 0; v < 64; v++) {
            float4 a0 = *(const float4*)&Ps[v * 132 + tmg * 8];
            float4 a1 = *(const float4*)&Ps[v * 132 + tmg * 8 + 4];
            float4 b0 = *(const float4*)&Evd[v * 132 + tdg * 8];
            float4 b1 = *(const float4*)&Evd[v * 132 + tdg * 8 + 4];
            ull bb[4] = {pk2(b0.x, b0.y), pk2(b0.z, b0.w), pk2(b1.x, b1.y), pk2(b1.z, b1.w)};
            float av[8] = {a0.x, a0.y, a0.z, a0.w, a1.x, a1.y, a1.z, a1.w};
            #pragma unroll
            for (int i = 0; i < 8; i++) {
                ull ai = pk2(av[i], av[i]);
                fma2(acc[i][0], ai, bb[0]); fma2(acc[i][1], ai, bb[1]);
                fma2(acc[i][2], ai, bb[2]); fma2(acc[i][3], ai, bb[3]);
            }
        }
    }
    #pragma unroll
    for (int i = 0; i < 8; i++) {
        float f[8];
        upk(acc[i][0], f[0], f[1]); upk(acc[i][1], f[2], f[3]);
        upk(acc[i][2], f[4], f[5]); upk(acc[i][3], f[6], f[7]);
        size_t base = ((size_t)b * 128 + tmg * 8 + i) * 128 + tdg * 8;
        *(float4*)&g_SEpart[base]     = make_float4(f[0], f[1], f[2], f[3]);
        *(float4*)&g_SEpart[base + 4] = make_float4(f[4], f[5], f[6], f[7]);
    }
    __syncthreads();
    float* red = Etd;
    #pragma unroll
    for (int i = 0; i < 8; i++) red[(tm1 * 8 + i) * 17 + tv] = psum[i];
    __syncthreads();
    if (t < 128) {
        float s = 0.f;
        #pragma unroll
        for (int q = 0; q < 16; q++) s += red[t * 17 + q];
        g_SEsum[b * 128 + t] = s;
    }
    if (t == 0) g_SEmt[b] = mt;
}

// ==================== final out = qz @ E^T ====================
__global__ void __launch_bounds__(256) k_msg(const float* __restrict__ E, float* __restrict__ out) {
    __shared__ float As[8][128], Bs[8][128];
    int t = threadIdx.x;
    int m0 = blockIdx.y * 128, n0 = blockIdx.x * 128;
    int row = t >> 1, kq = (t & 1) * 4;
    int tm = t >> 4, tn = t & 15;
    ull acc[8][4];
    #pragma unroll
    for (int i = 0; i < 8; i++)
        #pragma unroll
        for (int q = 0; q < 4; q++) acc[i][q] = pk2(0.f, 0.f);
    for (int s = 0; s < 16; s++) {
        int k0 = s * 8;
        float4 av = *(const float4*)&g_qz[(m0 + row) * 128 + k0 + kq];
        float4 bv = *(const float4*)&E[(size_t)(n0 + row) * 128 + k0 + kq];
        __syncthreads();
        As[kq][row] = av.x; As[kq + 1][row] = av.y; As[kq + 2][row] = av.z; As[kq + 3][row] = av.w;
        Bs[kq][row] = bv.x; Bs[kq + 1][row] = bv.y; Bs[kq + 2][row] = bv.z; Bs[kq + 3][row] = bv.w;
        __syncthreads();
        #pragma unroll
        for (int p = 0; p < 8; p++) {
            float4 a0 = *(const float4*)&As[p][tm * 8], a1 = *(const float4*)&As[p][tm * 8 + 4];
            float4 b0 = *(const float4*)&Bs[p][tn * 8], b1 = *(const float4*)&Bs[p][tn * 8 + 4];
            ull bb[4] = {pk2(b0.x, b0.y), pk2(b0.z, b0.w), pk2(b1.x, b1.y), pk2(b1.z, b1.w)};
            float avv[8] = {a0.x, a0.y, a0.z, a0.w, a1.x, a1.y, a1.z, a1.w};
            #pragma unroll
            for (int i = 0; i < 8; i++) {
                ull ai = pk2(avv[i], avv[i]);
                fma2(acc[i][0], ai, bb[0]); fma2(acc[i][1], ai, bb[1]);
                fma2(acc[i][2], ai, bb[2]); fma2(acc[i][3], ai, bb[3]);
            }
        }
    }
    #pragma unroll
    for (int i = 0; i < 8; i++) {
        float f[8];
        upk(acc[i][0], f[0], f[1]); upk(acc[i][1], f[2], f[3]);
        upk(acc[i][2], f[4], f[5]); upk(acc[i][3], f[6], f[7]);
        size_t base = (size_t)(m0 + tm * 8 + i) * 32000 + n0 + tn * 8;
        *(float4*)&out[base] = make_float4(f[0], f[1], f[2], f[3]);
        *(float4*)&out[base + 4] = make_float4(f[4], f[5], f[6], f[7]);
    }
}

// ==================== launch ====================
extern "C" void kernel_launch(void* const* d_in, const int* in_sizes, int n_in,
                              void* d_out, int out_size) {
    const float* x    = (const float*)d_in[0];
    const int*   mask = (const int*)d_in[1];
    const float* E    = (const float*)d_in[2];
    const int*   mm   = (const int*)d_in[3];
    const float* T    = (const float*)d_in[4];
    float* out = (float*)d_out;

    cudaFuncSetAttribute(k_sef, cudaFuncAttributeMaxDynamicSharedMemorySize, SEF_SMEM);

    k_emean_part<<<64, 256>>>(E);
    k_emean_red<<<1, 128>>>();
    k_bmat<<<2048, 256>>>(T);
    k_transE<<<dim3(250, 4), 256>>>(E);
    k_midx<<<1, 512>>>(mask, mm);
    k_init_qz<<<512, 128>>>(x, mask, mm);
    for (int it = 0; it < 4; it++) {
        k_nn64<<<dim3(16, 8, 2), 256>>>(T, 0);     // U = qz @ T[k]
        k_F<<<512, 256>>>(mask);                   // F + softmax -> qhn, qhnT
        k_S<<<512, 256>>>();                       // s1|s2 -> S
        k_nn64<<<dim3(2, 8, 8), 256>>>(T, 1);      // Gpart = S @ Bmat
        k_zupd<<<512, 128>>>(x, mask, mm, it > 0); // z update (+compact SE combine)
        if (it < 3) k_sef<<<148, 256, SEF_SMEM>>>(E);      // fused SE, masked rows only
        else        k_msg<<<dim3(250, 4), 256>>>(E, out);  // final output
    }
}

// round 10
// speedup vs baseline: 1.0712x; 1.0022x over previous
#include <cuda_runtime.h>
#include <math.h>
#include <stdint.h>

#define NEGC 1.0e9f
typedef unsigned long long ull;

// ==================== static scratch ====================
__device__ float g_epart[64 * 128];
__device__ float g_emean[128];
__device__ float g_Bmat[4096 * 128];
__device__ float g_qz[512 * 128];
__device__ float g_U[2 * 512 * 1024];
__device__ float g_qhn[4 * 8 * 128 * 128];
__device__ float g_qhnT[4 * 8 * 128 * 128];
__device__ float g_S[512 * 4096];
__device__ float g_Gpart[8 * 512 * 128];
__device__ float g_ET[128 * 32000];          // E transposed (fp32)
__device__ float g_SEpart[148 * 128 * 128];  // per-block partials (compact rows)
__device__ float g_SEsum[148 * 128];
__device__ int   g_SEmt[148];
__device__ int   g_midx[512];
__device__ int   g_mpos[512];
__device__ int   g_mcount;

// ---- f32x2 helpers ----
__device__ __forceinline__ ull pk2(float lo, float hi) {
    ull r; asm("mov.b64 %0, {%1, %2};" : "=l"(r) : "f"(lo), "f"(hi)); return r;
}
__device__ __forceinline__ void fma2(ull &d, ull a, ull b) {
    asm("fma.rn.f32x2 %0, %1, %2, %3;" : "=l"(d) : "l"(a), "l"(b), "l"(d));
}
__device__ __forceinline__ void upk(ull v, float &lo, float &hi) {
    asm("mov.b64 {%0, %1}, %2;" : "=f"(lo), "=f"(hi) : "l"(v));
}

// ---- FMA-pipe exp (no MUFU). Valid for |x| < ~80. ----
__device__ __forceinline__ float fexp(float x) {
    float z = x * 1.4426950408889634f;
    float m = z + 12582912.0f;
    int ni = __float_as_int(m) - 0x4B400000;
    float f = z - (m - 12582912.0f);
    float p = 0.0013333558f;
    p = fmaf(p, f, 0.0096181291f);
    p = fmaf(p, f, 0.0555041087f);
    p = fmaf(p, f, 0.2402265070f);
    p = fmaf(p, f, 0.6931471806f);
    p = fmaf(p, f, 1.0f);
    return p * __int_as_float((ni + 127) << 23);
}
__device__ __forceinline__ float fexp_s(float x) { return fexp(fmaxf(x, -80.f)); }

// ==================== setup ====================
__global__ void k_emean_part(const float* __restrict__ E) {
    int b = blockIdx.x, t = threadIdx.x;
    int d = t & 127, h = t >> 7;
    float s = 0.f;
    for (int v = b * 500 + h; v < b * 500 + 500; v += 2) s += E[v * 128 + d];
    __shared__ float sh[256];
    sh[t] = s; __syncthreads();
    if (t < 128) g_epart[b * 128 + t] = sh[t] + sh[t + 128];
}
__global__ void k_emean_red() {
    int t = threadIdx.x;
    float s = 0.f;
    for (int b = 0; b < 64; b++) s += g_epart[b * 128 + t];
    g_emean[t] = s * (1.0f / 32000.0f);
}

__global__ void k_bmat(const float* __restrict__ T) {
    int idx = blockIdx.x * 256 + threadIdx.x;
    if (idx >= 4096 * 128) return;
    int r = idx >> 7, col = idx & 127;
    float val;
    if (r < 2048) {
        int k = r >> 10, c = (r >> 7) & 7, b = r & 127;
        val = T[((k * 128 + col) * 128 + b) * 8 + c];
    } else {
        int r2 = r - 2048;
        int k = r2 >> 10, c = (r2 >> 7) & 7, a = r2 & 127;
        val = T[((k * 128 + a) * 128 + col) * 8 + c];
    }
    g_Bmat[idx] = val;
}

__global__ void k_transE(const float* __restrict__ E) {
    __shared__ float tile[128][33];
    int v0 = blockIdx.x * 128, d0 = blockIdx.y * 32, t = threadIdx.x;
    for (int idx = t; idx < 4096; idx += 256) {
        int r = idx >> 5, c = idx & 31;
        tile[r][c] = E[(size_t)(v0 + r) * 128 + d0 + c];
    }
    __syncthreads();
    for (int idx = t; idx < 4096; idx += 256) {
        int d = idx >> 7, vv = idx & 127;
        g_ET[(size_t)(d0 + d) * 32000 + v0 + vv] = tile[vv][d];
    }
}

__global__ void k_midx(const int* __restrict__ mask, const int* __restrict__ mmask) {
    __shared__ int pref[512];
    int t = threadIdx.x;
    int f = (mmask[t] != 0 && mask[t] != 0) ? 1 : 0;
    pref[t] = f;
    __syncthreads();
    for (int o = 1; o < 512; o <<= 1) {
        int v = (t >= o) ? pref[t - o] : 0;
        __syncthreads();
        pref[t] += v;
        __syncthreads();
    }
    if (f) { int pos = pref[t] - 1; g_midx[pos] = t; g_mpos[t] = pos; }
    else g_mpos[t] = -1;
    if (t == 511) g_mcount = pref[511];
}

__device__ __forceinline__ float softmax128(float raw, float* r1, float* r2) {
    int lane = threadIdx.x & 31, w = threadIdx.x >> 5;
    float m = raw;
    #pragma unroll
    for (int o = 16; o; o >>= 1) m = fmaxf(m, __shfl_xor_sync(~0u, m, o));
    if (lane == 0) r1[w] = m;
    __syncthreads();
    m = fmaxf(fmaxf(r1[0], r1[1]), fmaxf(r1[2], r1[3]));
    float e = fexp_s(raw - m), s = e;
    #pragma unroll
    for (int o = 16; o; o >>= 1) s += __shfl_xor_sync(~0u, s, o);
    if (lane == 0) r2[w] = s;
    __syncthreads();
    return e / (r2[0] + r2[1] + r2[2] + r2[3]);
}

__global__ void k_init_qz(const float* __restrict__ x, const int* __restrict__ mask,
                          const int* __restrict__ mmask) {
    int zi = blockIdx.x, a = threadIdx.x;
    __shared__ float r1[4], r2[4];
    float keep = mask[zi] ? 1.f : 0.f;
    float mm = (float)mmask[zi];
    float raw = (x[zi * 128 + a] * (1.f - mm) + g_emean[a] * mm) * keep;
    float p = softmax128(raw, r1, r2);
    g_qz[zi * 128 + a] = p * keep;
}

// ==================== small FFMA GEMMs ====================
__global__ void __launch_bounds__(256) k_nn64(const float* __restrict__ T, int which) {
    const float *A, *B; float *C;
    int lda, ldb, ldc, ksteps, kb;
    if (which == 0) {
        int kk = blockIdx.z;
        A = g_qz; lda = 128; B = T + kk * 131072; ldb = 1024;
        C = g_U + (size_t)kk * 524288; ldc = 1024; ksteps = 8; kb = 0;
    } else {
        int ks = blockIdx.z;
        A = g_S; lda = 4096; B = g_Bmat; ldb = 128;
        C = g_Gpart + (size_t)ks * 65536; ldc = 128; ksteps = 32; kb = ks * 512;
    }
    int m0 = blockIdx.y * 64, n0 = blockIdx.x * 64;
    __shared__ float As[16][68], Bs[16][64];
    int t = threadIdx.x, tm = t >> 4, tn = t & 15;
    ull acc[4][2];
    #pragma unroll
    for (int i = 0; i < 4; i++) { acc[i][0] = pk2(0.f, 0.f); acc[i][1] = pk2(0.f, 0.f); }
    for (int s = 0; s < ksteps; s++) {
        int k0 = kb + s * 16;
        { int r = t >> 2, c4 = (t & 3) * 4;
          float4 av = *(const float4*)&A[(size_t)(m0 + r) * lda + k0 + c4];
          As[c4][r] = av.x; As[c4 + 1][r] = av.y; As[c4 + 2][r] = av.z; As[c4 + 3][r] = av.w; }
        { int r = t >> 4, c4 = (t & 15) * 4;
          *(float4*)&Bs[r][c4] = *(const float4*)&B[(size_t)(k0 + r) * ldb + n0 + c4]; }
        __syncthreads();
        #pragma unroll
        for (int p = 0; p < 16; p++) {
            float4 a = *(const float4*)&As[p][tm * 4];
            float4 b = *(const float4*)&Bs[p][tn * 4];
            ull b01 = pk2(b.x, b.y), b23 = pk2(b.z, b.w);
            ull a0 = pk2(a.x, a.x), a1 = pk2(a.y, a.y), a2 = pk2(a.z, a.z), a3 = pk2(a.w, a.w);
            fma2(acc[0][0], a0, b01); fma2(acc[0][1], a0, b23);
            fma2(acc[1][0], a1, b01); fma2(acc[1][1], a1, b23);
            fma2(acc[2][0], a2, b01); fma2(acc[2][1], a2, b23);
            fma2(acc[3][0], a3, b01); fma2(acc[3][1], a3, b23);
        }
        __syncthreads();
    }
    #pragma unroll
    for (int i = 0; i < 4; i++) {
        float c0, c1, c2, c3;
        upk(acc[i][0], c0, c1); upk(acc[i][1], c2, c3);
        *(float4*)&C[(size_t)(m0 + tm * 4 + i) * ldc + n0 + tn * 4] = make_float4(c0, c1, c2, c3);
    }
}

__global__ void __launch_bounds__(256) k_F(const int* __restrict__ mask) {
    int zi = blockIdx.x, z = zi >> 7, i = zi & 127;
    int t = threadIdx.x;
    __shared__ float U_sh[2][1024];
    __shared__ float qz_sh[32][129];
    __shared__ float qh_sh[8][128];
    __shared__ float smax[8], ssum[8];
    for (int idx = t; idx < 2048; idx += 256) {
        int k = idx >> 10, bc = idx & 1023;
        U_sh[k][bc] = g_U[((size_t)k * 512 + zi) * 1024 + bc];
    }
    int j = t & 127, ch = t >> 7;
    int ksel = (j > i) ? 0 : 1;
    float a0 = 0.f, a1 = 0.f, a2 = 0.f, a3 = 0.f;
    const float* qzb = g_qz + z * 128 * 128;
    for (int b0 = 0; b0 < 128; b0 += 32) {
        __syncthreads();
        #pragma unroll
        for (int e = 0; e < 16; e++) {
            int lin = t + e * 256;
            int jj = lin >> 5, col = lin & 31;
            qz_sh[col][jj] = qzb[jj * 128 + b0 + col];
        }
        __syncthreads();
        #pragma unroll 8
        for (int bb = 0; bb < 32; bb++) {
            float qv = qz_sh[bb][j];
            float4 u4 = *(const float4*)&U_sh[ksel][(b0 + bb) * 8 + ch * 4];
            a0 += qv * u4.x; a1 += qv * u4.y; a2 += qv * u4.z; a3 += qv * u4.w;
        }
    }
    bool vi = mask[z * 128 + i] != 0, vj = mask[z * 128 + j] != 0;
    if (i == j || !vi || !vj) { a0 = a1 = a2 = a3 = -NEGC; }
    qh_sh[ch * 4 + 0][j] = a0; qh_sh[ch * 4 + 1][j] = a1;
    qh_sh[ch * 4 + 2][j] = a2; qh_sh[ch * 4 + 3][j] = a3;
    __syncthreads();
    int w = t >> 5, lane = t & 31;
    float v0 = qh_sh[w][lane], v1 = qh_sh[w][lane + 32];
    float v2 = qh_sh[w][lane + 64], v3 = qh_sh[w][lane + 96];
    float mx = fmaxf(fmaxf(v0, v1), fmaxf(v2, v3));
    #pragma unroll
    for (int o = 16; o; o >>= 1) mx = fmaxf(mx, __shfl_xor_sync(~0u, mx, o));
    float sum = fexp_s(v0 - mx) + fexp_s(v1 - mx) + fexp_s(v2 - mx) + fexp_s(v3 - mx);
    #pragma unroll
    for (int o = 16; o; o >>= 1) sum += __shfl_xor_sync(~0u, sum, o);
    if (lane == 0) { smax[w] = mx; ssum[w] = sum; }
    __syncthreads();
    float vals[4] = {a0, a1, a2, a3};
    #pragma unroll
    for (int hh = 0; hh < 4; hh++) {
        int h = ch * 4 + hh;
        float p = fexp_s(vals[hh] - smax[h]) / ssum[h];
        g_qhn[(((z * 8 + h) * 128 + i) << 7) + j] = p;
        g_qhnT[(((z * 8 + h) * 128 + j) << 7) + i] = p;
    }
}

__global__ void __launch_bounds__(256) k_S() {
    int zi = blockIdx.x, z = zi >> 7, i = zi & 127;
    int t = threadIdx.x;
    __shared__ float wT[128][36];
    __shared__ float qzc[32][128];
    for (int idx = t; idx < 4096; idx += 256) {
        int r = idx & 31, j = idx >> 5;
        float v; bool m;
        if (r < 16) {
            int k = r >> 3, c = r & 7;
            v = g_qhn[(((z * 8 + c) * 128 + i) << 7) + j];
            m = (k == 0) ? (j > i) : (j < i);
        } else {
            int r2 = r - 16, k = r2 >> 3, c = r2 & 7;
            v = g_qhnT[(((z * 8 + c) * 128 + i) << 7) + j];
            m = (k == 0) ? (j < i) : (j > i);
        }
        wT[j][r] = m ? v : 0.f;
    }
    int tm = t >> 5, tn = t & 31;
    ull acc[4][2];
    #pragma unroll
    for (int q = 0; q < 4; q++) { acc[q][0] = pk2(0.f, 0.f); acc[q][1] = pk2(0.f, 0.f); }
    for (int j0 = 0; j0 < 128; j0 += 32) {
        __syncthreads();
        for (int idx = t; idx < 4096; idx += 256) {
            int jl = idx >> 7, b = idx & 127;
            qzc[jl][b] = g_qz[((z * 128) + j0 + jl) * 128 + b];
        }
        __syncthreads();
        #pragma unroll 8
        for (int jl = 0; jl < 32; jl++) {
            float4 wv = *(const float4*)&wT[j0 + jl][tm * 4];
            float4 qv = *(const float4*)&qzc[jl][tn * 4];
            ull q01 = pk2(qv.x, qv.y), q23 = pk2(qv.z, qv.w);
            ull w0 = pk2(wv.x, wv.x), w1 = pk2(wv.y, wv.y), w2 = pk2(wv.z, wv.z), w3 = pk2(wv.w, wv.w);
            fma2(acc[0][0], w0, q01); fma2(acc[0][1], w0, q23);
            fma2(acc[1][0], w1, q01); fma2(acc[1][1], w1, q23);
            fma2(acc[2][0], w2, q01); fma2(acc[2][1], w2, q23);
            fma2(acc[3][0], w3, q01); fma2(acc[3][1], w3, q23);
        }
    }
    #pragma unroll
    for (int q = 0; q < 4; q++) {
        int r = tm * 4 + q;
        int base = (r < 16) ? r * 128 : 2048 + (r - 16) * 128;
        float c0, c1, c2, c3;
        upk(acc[q][0], c0, c1); upk(acc[q][1], c2, c3);
        *(float4*)&g_S[(size_t)zi * 4096 + base + tn * 4] = make_float4(c0, c1, c2, c3);
    }
}

__global__ void k_zupd(const float* __restrict__ x, const int* __restrict__ mask,
                       const int* __restrict__ mmask, int useSE) {
    int zi = blockIdx.x, d = threadIdx.x;
    __shared__ float r1[4], r2[4];
    __shared__ int smt[148];
    if (useSE) {
        for (int q = d; q < 148; q += 128) smt[q] = g_SEmt[q];
    }
    __syncthreads();
    float g = 0.f;
    #pragma unroll
    for (int p = 0; p < 8; p++) g += g_Gpart[((size_t)p * 512 + zi) * 128 + d];
    float mm = (float)mmask[zi];
    float se = 0.f;
    if (mm != 0.f) {
        if (useSE) {
            int pos = g_mpos[zi];
            if (pos >= 0) {
                int mt = pos >> 7, row = pos & 127;
                float num = 0.f, den = 0.f;
                for (int bb = 0; bb < 148; bb++) {
                    if (smt[bb] == mt) {
                        num += g_SEpart[((size_t)bb * 128 + row) * 128 + d];
                        den += g_SEsum[bb * 128 + row];
                    }
                }
                se = num / den;
            }
        } else se = g_emean[d];
    }
    float raw = x[zi * 128 + d] * (1.f - mm) + se * mm + g;
    float keep = mask[zi] ? 1.f : 0.f;
    float p_ = softmax128(raw, r1, r2);
    g_qz[zi * 128 + d] = p_ * keep;
}

// ==================== fused SE on compacted masked rows (R7 layout) ====================
#define QZT_OFF 0                      // [128 d][132 m]
#define ETD_OFF (128 * 132)            // [128 d][68 v]
#define EVD_OFF (ETD_OFF + 128 * 68)   // [64 v][132 d]
#define PS_OFF  (EVD_OFF + 64 * 132)   // [64 v][132 m]
#define SEF_SMEM ((PS_OFF + 64 * 132) * 4)

__global__ void __launch_bounds__(256) k_sef(const float* __restrict__ E) {
    int count = g_mcount;
    if (count == 0) return;
    int ntiles = (count + 127) >> 7;
    int b = blockIdx.x;
    int mt = (b * ntiles) / 148;
    int gb0 = (mt * 148 + ntiles - 1) / ntiles;
    int gb1 = ((mt + 1) * 148 + ntiles - 1) / ntiles;
    int gsz = gb1 - gb0, li = b - gb0;
    int ustart = (li * 500) / gsz;
    int ucount = ((li + 1) * 500) / gsz - ustart;
    int m0 = mt * 128;

    extern __shared__ float sm[];
    float* qzT = sm + QZT_OFF;
    float* Etd = sm + ETD_OFF;
    float* Evd = sm + EVD_OFF;
    float* Ps  = sm + PS_OFF;
    int t = threadIdx.x;

    {
        int m = t >> 1, d0 = (t & 1) * 64;
        int pos = m0 + m;
        int zi = (pos < count) ? g_midx[pos] : 0;
        const float* src = g_qz + (size_t)zi * 128 + d0;
        #pragma unroll
        for (int q = 0; q < 16; q++) {
            float4 v = *(const float4*)(src + q * 4);
            qzT[(d0 + q * 4 + 0) * 132 + m] = v.x;
            qzT[(d0 + q * 4 + 1) * 132 + m] = v.y;
            qzT[(d0 + q * 4 + 2) * 132 + m] = v.z;
            qzT[(d0 + q * 4 + 3) * 132 + m] = v.w;
        }
    }

    int tm1 = t >> 4, tv = t & 15;          // GEMM1: 8m x 4v
    int tmg = t >> 4, tdg = t & 15;         // GEMM2: 8m x 8d
    ull acc[8][4];
    #pragma unroll
    for (int i = 0; i < 8; i++)
        #pragma unroll
        for (int q = 0; q < 4; q++) acc[i][q] = pk2(0.f, 0.f);
    float psum[8];
    #pragma unroll
    for (int i = 0; i < 8; i++) psum[i] = 0.f;

    for (int tile = 0; tile < ucount; tile++) {
        int vg = (ustart + tile) * 64;
        __syncthreads();
        {
            int d = t >> 1, vq = (t & 1) * 32;
            const float* src = g_ET + (size_t)d * 32000 + vg + vq;
            float* dst = Etd + d * 68 + vq;
            #pragma unroll
            for (int q = 0; q < 8; q++) *(float4*)(dst + q * 4) = *(const float4*)(src + q * 4);
        }
        {
            int v = t >> 2, dq = (t & 3) * 32;
            const float* src = E + (size_t)(vg + v) * 128 + dq;
            float* dst = Evd + v * 132 + dq;
            #pragma unroll
            for (int q = 0; q < 8; q++) *(float4*)(dst + q * 4) = *(const float4*)(src + q * 4);
        }
        __syncthreads();
        // GEMM1: L[8m][4v]
        ull L[8][2];
        #pragma unroll
        for (int i = 0; i < 8; i++) { L[i][0] = pk2(0.f, 0.f); L[i][1] = pk2(0.f, 0.f); }
        #pragma unroll 4
        for (int d = 0; d < 128; d++) {
            float4 a0 = *(const float4*)&qzT[d * 132 + tm1 * 8];
            float4 a1 = *(const float4*)&qzT[d * 132 + tm1 * 8 + 4];
            float4 bq = *(const float4*)&Etd[d * 68 + tv * 4];
            ull b01 = pk2(bq.x, bq.y), b23 = pk2(bq.z, bq.w);
            float av[8] = {a0.x, a0.y, a0.z, a0.w, a1.x, a1.y, a1.z, a1.w};
            #pragma unroll
            for (int i = 0; i < 8; i++) {
                ull ai = pk2(av[i], av[i]);
                fma2(L[i][0], ai, b01); fma2(L[i][1], ai, b23);
            }
        }
        // exp + write P^T[v][m] + rowsum partials
        #pragma unroll
        for (int i = 0; i < 8; i++) {
            float e0, e1, e2, e3;
            upk(L[i][0], e0, e1); upk(L[i][1], e2, e3);
            e0 = fexp(e0); e1 = fexp(e1); e2 = fexp(e2); e3 = fexp(e3);
            psum[i] += e0 + e1 + e2 + e3;
            int m = tm1 * 8 + i;
            Ps[(tv * 4 + 0) * 132 + m] = e0;
            Ps[(tv * 4 + 1) * 132 + m] = e1;
            Ps[(tv * 4 + 2) * 132 + m] = e2;
            Ps[(tv * 4 + 3) * 132 + m] = e3;
        }
        __syncthreads();
        // GEMM2: acc[8m][8d] += P^T' @ Evd
        #pragma unroll 4
        for (int v = 0; v < 64; v++) {
            float4 a0 = *(const float4*)&Ps[v * 132 + tmg * 8];
            float4 a1 = *(const float4*)&Ps[v * 132 + tmg * 8 + 4];
            float4 b0 = *(const float4*)&Evd[v * 132 + tdg * 8];
            float4 b1 = *(const float4*)&Evd[v * 132 + tdg * 8 + 4];
            ull bb[4] = {pk2(b0.x, b0.y), pk2(b0.z, b0.w), pk2(b1.x, b1.y), pk2(b1.z, b1.w)};
            float av[8] = {a0.x, a0.y, a0.z, a0.w, a1.x, a1.y, a1.z, a1.w};
            #pragma unroll
            for (int i = 0; i < 8; i++) {
                ull ai = pk2(av[i], av[i]);
                fma2(acc[i][0], ai, bb[0]); fma2(acc[i][1], ai, bb[1]);
                fma2(acc[i][2], ai, bb[2]); fma2(acc[i][3], ai, bb[3]);
            }
        }
    }
    #pragma unroll
    for (int i = 0; i < 8; i++) {
        float f[8];
        upk(acc[i][0], f[0], f[1]); upk(acc[i][1], f[2], f[3]);
        upk(acc[i][2], f[4], f[5]); upk(acc[i][3], f[6], f[7]);
        size_t base = ((size_t)b * 128 + tmg * 8 + i) * 128 + tdg * 8;
        *(float4*)&g_SEpart[base]     = make_float4(f[0], f[1], f[2], f[3]);
        *(float4*)&g_SEpart[base + 4] = make_float4(f[4], f[5], f[6], f[7]);
    }
    __syncthreads();
    float* red = Etd;
    #pragma unroll
    for (int i = 0; i < 8; i++) red[(tm1 * 8 + i) * 17 + tv] = psum[i];
    __syncthreads();
    if (t < 128) {
        float s = 0.f;
        #pragma unroll
        for (int q = 0; q < 16; q++) s += red[t * 17 + q];
        g_SEsum[b * 128 + t] = s;
    }
    if (t == 0) g_SEmt[b] = mt;
}

// ==================== final out = qz @ E^T ====================
__global__ void __launch_bounds__(256) k_msg(const float* __restrict__ E, float* __restrict__ out) {
    __shared__ float As[8][128], Bs[8][128];
    int t = threadIdx.x;
    int m0 = blockIdx.y * 128, n0 = blockIdx.x * 128;
    int row = t >> 1, kq = (t & 1) * 4;
    int tm = t >> 4, tn = t & 15;
    ull acc[8][4];
    #pragma unroll
    for (int i = 0; i < 8; i++)
        #pragma unroll
        for (int q = 0; q < 4; q++) acc[i][q] = pk2(0.f, 0.f);
    for (int s = 0; s < 16; s++) {
        int k0 = s * 8;
        float4 av = *(const float4*)&g_qz[(m0 + row) * 128 + k0 + kq];
        float4 bv = *(const float4*)&E[(size_t)(n0 + row) * 128 + k0 + kq];
        __syncthreads();
        As[kq][row] = av.x; As[kq + 1][row] = av.y; As[kq + 2][row] = av.z; As[kq + 3][row] = av.w;
        Bs[kq][row] = bv.x; Bs[kq + 1][row] = bv.y; Bs[kq + 2][row] = bv.z; Bs[kq + 3][row] = bv.w;
        __syncthreads();
        #pragma unroll
        for (int p = 0; p < 8; p++) {
            float4 a0 = *(const float4*)&As[p][tm * 8], a1 = *(const float4*)&As[p][tm * 8 + 4];
            float4 b0 = *(const float4*)&Bs[p][tn * 8], b1 = *(const float4*)&Bs[p][tn * 8 + 4];
            ull bb[4] = {pk2(b0.x, b0.y), pk2(b0.z, b0.w), pk2(b1.x, b1.y), pk2(b1.z, b1.w)};
            float avv[8] = {a0.x, a0.y, a0.z, a0.w, a1.x, a1.y, a1.z, a1.w};
            #pragma unroll
            for (int i = 0; i < 8; i++) {
                ull ai = pk2(avv[i], avv[i]);
                fma2(acc[i][0], ai, bb[0]); fma2(acc[i][1], ai, bb[1]);
                fma2(acc[i][2], ai, bb[2]); fma2(acc[i][3], ai, bb[3]);
            }
        }
    }
    #pragma unroll
    for (int i = 0; i < 8; i++) {
        float f[8];
        upk(acc[i][0], f[0], f[1]); upk(acc[i][1], f[2], f[3]);
        upk(acc[i][2], f[4], f[5]); upk(acc[i][3], f[6], f[7]);
        size_t base = (size_t)(m0 + tm * 8 + i) * 32000 + n0 + tn * 8;
        *(float4*)&out[base] = make_float4(f[0], f[1], f[2], f[3]);
        *(float4*)&out[base + 4] = make_float4(f[4], f[5], f[6], f[7]);
    }
}

// ==================== launch (fork/join: k_sef overlaps next iter's chain) ====================
extern "C" void kernel_launch(void* const* d_in, const int* in_sizes, int n_in,
                              void* d_out, int out_size) {
    const float* x    = (const float*)d_in[0];
    const int*   mask = (const int*)d_in[1];
    const float* E    = (const float*)d_in[2];
    const int*   mm   = (const int*)d_in[3];
    const float* T    = (const float*)d_in[4];
    float* out = (float*)d_out;

    static cudaStream_t s2 = nullptr;
    static cudaEvent_t eF = nullptr, eJ = nullptr;
    if (!s2) {
        cudaStreamCreate(&s2);
        cudaEventCreateWithFlags(&eF, cudaEventDisableTiming);
        cudaEventCreateWithFlags(&eJ, cudaEventDisableTiming);
        cudaFuncSetAttribute(k_sef, cudaFuncAttributeMaxDynamicSharedMemorySize, SEF_SMEM);
    }
    cudaStream_t s0 = 0;

    // fork s2: transE runs parallel to emean/bmat/midx/init_qz
    cudaEventRecord(eF, s0);
    cudaStreamWaitEvent(s2, eF, 0);
    k_transE<<<dim3(250, 4), 256, 0, s2>>>(E);

    k_emean_part<<<64, 256, 0, s0>>>(E);
    k_emean_red<<<1, 128, 0, s0>>>();
    k_bmat<<<2048, 256, 0, s0>>>(T);
    k_midx<<<1, 512, 0, s0>>>(mask, mm);
    k_init_qz<<<512, 128, 0, s0>>>(x, mask, mm);

    for (int it = 0; it < 4; it++) {
        // H/Z-message chain on s0 (reads qz_it; independent of SEpart)
        k_nn64<<<dim3(16, 8, 2), 256, 0, s0>>>(T, 0);
        k_F<<<512, 256, 0, s0>>>(mask);
        k_S<<<512, 256, 0, s0>>>();
        k_nn64<<<dim3(2, 8, 8), 256, 0, s0>>>(T, 1);
        // join: zupd needs SEpart from k_sef(it-1) running on s2
        if (it > 0) cudaStreamWaitEvent(s0, eJ, 0);
        k_zupd<<<512, 128, 0, s0>>>(x, mask, mm, it > 0);
        if (it < 3) {
            // fork k_sef(qz_{it+1}) onto s2 — overlaps next iteration's chain
            cudaEventRecord(eF, s0);
            cudaStreamWaitEvent(s2, eF, 0);
            k_sef<<<148, 256, SEF_SMEM, s2>>>(E);
            cudaEventRecord(eJ, s2);
        } else {
            k_msg<<<dim3(250, 4), 256, 0, s0>>>(E, out);
        }
    }
}

// round 11
// speedup vs baseline: 1.0916x; 1.0191x over previous
#include <cuda_runtime.h>
#include <math.h>
#include <stdint.h>

#define NEGC 1.0e9f
typedef unsigned long long ull;

// ==================== static scratch ====================
__device__ float g_epart[64 * 128];
__device__ float g_emean[128];
__device__ float g_Bmat[4096 * 128];
__device__ float g_qz[512 * 128];
__device__ float g_U[2 * 512 * 1024];
__device__ float g_qhn[4 * 8 * 128 * 128];
__device__ float g_qhnT[4 * 8 * 128 * 128];
__device__ float g_S[512 * 4096];
__device__ float g_Gpart[8 * 512 * 128];
__device__ float g_ET[128 * 32000];          // E transposed (fp32)
__device__ float g_SEpart[148 * 128 * 128];  // per-block partials (compact rows)
__device__ float g_SEsum[148 * 128];
__device__ float g_SE[512 * 128];            // dense reduced SE (compact rows)
__device__ int   g_midx[512];
__device__ int   g_mpos[512];
__device__ int   g_mcount;

// ---- f32x2 helpers ----
__device__ __forceinline__ ull pk2(float lo, float hi) {
    ull r; asm("mov.b64 %0, {%1, %2};" : "=l"(r) : "f"(lo), "f"(hi)); return r;
}
__device__ __forceinline__ void fma2(ull &d, ull a, ull b) {
    asm("fma.rn.f32x2 %0, %1, %2, %3;" : "=l"(d) : "l"(a), "l"(b), "l"(d));
}
__device__ __forceinline__ void upk(ull v, float &lo, float &hi) {
    asm("mov.b64 {%0, %1}, %2;" : "=f"(lo), "=f"(hi) : "l"(v));
}

// ---- FMA-pipe exp (no MUFU). Valid for |x| < ~80. ----
__device__ __forceinline__ float fexp(float x) {
    float z = x * 1.4426950408889634f;
    float m = z + 12582912.0f;
    int ni = __float_as_int(m) - 0x4B400000;
    float f = z - (m - 12582912.0f);
    float p = 0.0013333558f;
    p = fmaf(p, f, 0.0096181291f);
    p = fmaf(p, f, 0.0555041087f);
    p = fmaf(p, f, 0.2402265070f);
    p = fmaf(p, f, 0.6931471806f);
    p = fmaf(p, f, 1.0f);
    return p * __int_as_float((ni + 127) << 23);
}
__device__ __forceinline__ float fexp_s(float x) { return fexp(fmaxf(x, -80.f)); }

// ==================== setup ====================
__global__ void k_emean_part(const float* __restrict__ E) {
    int b = blockIdx.x, t = threadIdx.x;
    int d = t & 127, h = t >> 7;
    float s = 0.f;
    for (int v = b * 500 + h; v < b * 500 + 500; v += 2) s += E[v * 128 + d];
    __shared__ float sh[256];
    sh[t] = s; __syncthreads();
    if (t < 128) g_epart[b * 128 + t] = sh[t] + sh[t + 128];
}
__global__ void k_emean_red() {
    int t = threadIdx.x;
    float s = 0.f;
    for (int b = 0; b < 64; b++) s += g_epart[b * 128 + t];
    g_emean[t] = s * (1.0f / 32000.0f);
}

__global__ void k_bmat(const float* __restrict__ T) {
    int idx = blockIdx.x * 256 + threadIdx.x;
    if (idx >= 4096 * 128) return;
    int r = idx >> 7, col = idx & 127;
    float val;
    if (r < 2048) {
        int k = r >> 10, c = (r >> 7) & 7, b = r & 127;
        val = T[((k * 128 + col) * 128 + b) * 8 + c];
    } else {
        int r2 = r - 2048;
        int k = r2 >> 10, c = (r2 >> 7) & 7, a = r2 & 127;
        val = T[((k * 128 + a) * 128 + col) * 8 + c];
    }
    g_Bmat[idx] = val;
}

__global__ void k_transE(const float* __restrict__ E) {
    __shared__ float tile[128][33];
    int v0 = blockIdx.x * 128, d0 = blockIdx.y * 32, t = threadIdx.x;
    for (int idx = t; idx < 4096; idx += 256) {
        int r = idx >> 5, c = idx & 31;
        tile[r][c] = E[(size_t)(v0 + r) * 128 + d0 + c];
    }
    __syncthreads();
    for (int idx = t; idx < 4096; idx += 256) {
        int d = idx >> 7, vv = idx & 127;
        g_ET[(size_t)(d0 + d) * 32000 + v0 + vv] = tile[vv][d];
    }
}

__global__ void k_midx(const int* __restrict__ mask, const int* __restrict__ mmask) {
    __shared__ int pref[512];
    int t = threadIdx.x;
    int f = (mmask[t] != 0 && mask[t] != 0) ? 1 : 0;
    pref[t] = f;
    __syncthreads();
    for (int o = 1; o < 512; o <<= 1) {
        int v = (t >= o) ? pref[t - o] : 0;
        __syncthreads();
        pref[t] += v;
        __syncthreads();
    }
    if (f) { int pos = pref[t] - 1; g_midx[pos] = t; g_mpos[t] = pos; }
    else g_mpos[t] = -1;
    if (t == 511) g_mcount = pref[511];
}

__device__ __forceinline__ float softmax128(float raw, float* r1, float* r2) {
    int lane = threadIdx.x & 31, w = threadIdx.x >> 5;
    float m = raw;
    #pragma unroll
    for (int o = 16; o; o >>= 1) m = fmaxf(m, __shfl_xor_sync(~0u, m, o));
    if (lane == 0) r1[w] = m;
    __syncthreads();
    m = fmaxf(fmaxf(r1[0], r1[1]), fmaxf(r1[2], r1[3]));
    float e = fexp_s(raw - m), s = e;
    #pragma unroll
    for (int o = 16; o; o >>= 1) s += __shfl_xor_sync(~0u, s, o);
    if (lane == 0) r2[w] = s;
    __syncthreads();
    return e / (r2[0] + r2[1] + r2[2] + r2[3]);
}

__global__ void k_init_qz(const float* __restrict__ x, const int* __restrict__ mask,
                          const int* __restrict__ mmask) {
    int zi = blockIdx.x, a = threadIdx.x;
    __shared__ float r1[4], r2[4];
    float keep = mask[zi] ? 1.f : 0.f;
    float mm = (float)mmask[zi];
    float raw = (x[zi * 128 + a] * (1.f - mm) + g_emean[a] * mm) * keep;
    float p = softmax128(raw, r1, r2);
    g_qz[zi * 128 + a] = p * keep;
}

// ==================== small FFMA GEMMs ====================
__global__ void __launch_bounds__(256) k_nn64(const float* __restrict__ T, int which) {
    const float *A, *B; float *C;
    int lda, ldb, ldc, ksteps, kb;
    if (which == 0) {
        int kk = blockIdx.z;
        A = g_qz; lda = 128; B = T + kk * 131072; ldb = 1024;
        C = g_U + (size_t)kk * 524288; ldc = 1024; ksteps = 8; kb = 0;
    } else {
        int ks = blockIdx.z;
        A = g_S; lda = 4096; B = g_Bmat; ldb = 128;
        C = g_Gpart + (size_t)ks * 65536; ldc = 128; ksteps = 32; kb = ks * 512;
    }
    int m0 = blockIdx.y * 64, n0 = blockIdx.x * 64;
    __shared__ float As[16][68], Bs[16][64];
    int t = threadIdx.x, tm = t >> 4, tn = t & 15;
    ull acc[4][2];
    #pragma unroll
    for (int i = 0; i < 4; i++) { acc[i][0] = pk2(0.f, 0.f); acc[i][1] = pk2(0.f, 0.f); }
    for (int s = 0; s < ksteps; s++) {
        int k0 = kb + s * 16;
        { int r = t >> 2, c4 = (t & 3) * 4;
          float4 av = *(const float4*)&A[(size_t)(m0 + r) * lda + k0 + c4];
          As[c4][r] = av.x; As[c4 + 1][r] = av.y; As[c4 + 2][r] = av.z; As[c4 + 3][r] = av.w; }
        { int r = t >> 4, c4 = (t & 15) * 4;
          *(float4*)&Bs[r][c4] = *(const float4*)&B[(size_t)(k0 + r) * ldb + n0 + c4]; }
        __syncthreads();
        #pragma unroll
        for (int p = 0; p < 16; p++) {
            float4 a = *(const float4*)&As[p][tm * 4];
            float4 b = *(const float4*)&Bs[p][tn * 4];
            ull b01 = pk2(b.x, b.y), b23 = pk2(b.z, b.w);
            ull a0 = pk2(a.x, a.x), a1 = pk2(a.y, a.y), a2 = pk2(a.z, a.z), a3 = pk2(a.w, a.w);
            fma2(acc[0][0], a0, b01); fma2(acc[0][1], a0, b23);
            fma2(acc[1][0], a1, b01); fma2(acc[1][1], a1, b23);
            fma2(acc[2][0], a2, b01); fma2(acc[2][1], a2, b23);
            fma2(acc[3][0], a3, b01); fma2(acc[3][1], a3, b23);
        }
        __syncthreads();
    }
    #pragma unroll
    for (int i = 0; i < 4; i++) {
        float c0, c1, c2, c3;
        upk(acc[i][0], c0, c1); upk(acc[i][1], c2, c3);
        *(float4*)&C[(size_t)(m0 + tm * 4 + i) * ldc + n0 + tn * 4] = make_float4(c0, c1, c2, c3);
    }
}

__global__ void __launch_bounds__(256) k_F(const int* __restrict__ mask) {
    int zi = blockIdx.x, z = zi >> 7, i = zi & 127;
    int t = threadIdx.x;
    __shared__ float U_sh[2][1024];
    __shared__ float qz_sh[32][129];
    __shared__ float qh_sh[8][128];
    __shared__ float smax[8], ssum[8];
    for (int idx = t; idx < 2048; idx += 256) {
        int k = idx >> 10, bc = idx & 1023;
        U_sh[k][bc] = g_U[((size_t)k * 512 + zi) * 1024 + bc];
    }
    int j = t & 127, ch = t >> 7;
    int ksel = (j > i) ? 0 : 1;
    float a0 = 0.f, a1 = 0.f, a2 = 0.f, a3 = 0.f;
    const float* qzb = g_qz + z * 128 * 128;
    for (int b0 = 0; b0 < 128; b0 += 32) {
        __syncthreads();
        #pragma unroll
        for (int e = 0; e < 16; e++) {
            int lin = t + e * 256;
            int jj = lin >> 5, col = lin & 31;
            qz_sh[col][jj] = qzb[jj * 128 + b0 + col];
        }
        __syncthreads();
        #pragma unroll 8
        for (int bb = 0; bb < 32; bb++) {
            float qv = qz_sh[bb][j];
            float4 u4 = *(const float4*)&U_sh[ksel][(b0 + bb) * 8 + ch * 4];
            a0 += qv * u4.x; a1 += qv * u4.y; a2 += qv * u4.z; a3 += qv * u4.w;
        }
    }
    bool vi = mask[z * 128 + i] != 0, vj = mask[z * 128 + j] != 0;
    if (i == j || !vi || !vj) { a0 = a1 = a2 = a3 = -NEGC; }
    qh_sh[ch * 4 + 0][j] = a0; qh_sh[ch * 4 + 1][j] = a1;
    qh_sh[ch * 4 + 2][j] = a2; qh_sh[ch * 4 + 3][j] = a3;
    __syncthreads();
    int w = t >> 5, lane = t & 31;
    float v0 = qh_sh[w][lane], v1 = qh_sh[w][lane + 32];
    float v2 = qh_sh[w][lane + 64], v3 = qh_sh[w][lane + 96];
    float mx = fmaxf(fmaxf(v0, v1), fmaxf(v2, v3));
    #pragma unroll
    for (int o = 16; o; o >>= 1) mx = fmaxf(mx, __shfl_xor_sync(~0u, mx, o));
    float sum = fexp_s(v0 - mx) + fexp_s(v1 - mx) + fexp_s(v2 - mx) + fexp_s(v3 - mx);
    #pragma unroll
    for (int o = 16; o; o >>= 1) sum += __shfl_xor_sync(~0u, sum, o);
    if (lane == 0) { smax[w] = mx; ssum[w] = sum; }
    __syncthreads();
    float vals[4] = {a0, a1, a2, a3};
    #pragma unroll
    for (int hh = 0; hh < 4; hh++) {
        int h = ch * 4 + hh;
        float p = fexp_s(vals[hh] - smax[h]) / ssum[h];
        g_qhn[(((z * 8 + h) * 128 + i) << 7) + j] = p;
        g_qhnT[(((z * 8 + h) * 128 + j) << 7) + i] = p;
    }
}

__global__ void __launch_bounds__(256) k_S() {
    int zi = blockIdx.x, z = zi >> 7, i = zi & 127;
    int t = threadIdx.x;
    __shared__ float wT[128][36];
    __shared__ float qzc[32][128];
    for (int idx = t; idx < 4096; idx += 256) {
        int r = idx & 31, j = idx >> 5;
        float v; bool m;
        if (r < 16) {
            int k = r >> 3, c = r & 7;
            v = g_qhn[(((z * 8 + c) * 128 + i) << 7) + j];
            m = (k == 0) ? (j > i) : (j < i);
        } else {
            int r2 = r - 16, k = r2 >> 3, c = r2 & 7;
            v = g_qhnT[(((z * 8 + c) * 128 + i) << 7) + j];
            m = (k == 0) ? (j < i) : (j > i);
        }
        wT[j][r] = m ? v : 0.f;
    }
    int tm = t >> 5, tn = t & 31;
    ull acc[4][2];
    #pragma unroll
    for (int q = 0; q < 4; q++) { acc[q][0] = pk2(0.f, 0.f); acc[q][1] = pk2(0.f, 0.f); }
    for (int j0 = 0; j0 < 128; j0 += 32) {
        __syncthreads();
        for (int idx = t; idx < 4096; idx += 256) {
            int jl = idx >> 7, b = idx & 127;
            qzc[jl][b] = g_qz[((z * 128) + j0 + jl) * 128 + b];
        }
        __syncthreads();
        #pragma unroll 8
        for (int jl = 0; jl < 32; jl++) {
            float4 wv = *(const float4*)&wT[j0 + jl][tm * 4];
            float4 qv = *(const float4*)&qzc[jl][tn * 4];
            ull q01 = pk2(qv.x, qv.y), q23 = pk2(qv.z, qv.w);
            ull w0 = pk2(wv.x, wv.x), w1 = pk2(wv.y, wv.y), w2 = pk2(wv.z, wv.z), w3 = pk2(wv.w, wv.w);
            fma2(acc[0][0], w0, q01); fma2(acc[0][1], w0, q23);
            fma2(acc[1][0], w1, q01); fma2(acc[1][1], w1, q23);
            fma2(acc[2][0], w2, q01); fma2(acc[2][1], w2, q23);
            fma2(acc[3][0], w3, q01); fma2(acc[3][1], w3, q23);
        }
    }
    #pragma unroll
    for (int q = 0; q < 4; q++) {
        int r = tm * 4 + q;
        int base = (r < 16) ? r * 128 : 2048 + (r - 16) * 128;
        float c0, c1, c2, c3;
        upk(acc[q][0], c0, c1); upk(acc[q][1], c2, c3);
        *(float4*)&g_S[(size_t)zi * 4096 + base + tn * 4] = make_float4(c0, c1, c2, c3);
    }
}

// ---- reduce per-block SE partials into dense g_SE (runs on side stream) ----
__global__ void k_sered() {
    int count = g_mcount;
    int pos = blockIdx.x;
    if (pos >= count) return;
    int ntiles = (count + 127) >> 7;
    int mt = pos >> 7, row = pos & 127;
    int gb0 = (mt * 148 + ntiles - 1) / ntiles;
    int gb1 = ((mt + 1) * 148 + ntiles - 1) / ntiles;
    int d = threadIdx.x;
    float num = 0.f, den = 0.f;
    for (int bb = gb0; bb < gb1; bb++) {
        num += g_SEpart[((size_t)bb * 128 + row) * 128 + d];
        den += g_SEsum[bb * 128 + row];
    }
    g_SE[pos * 128 + d] = num / den;
}

// ---- Z update: dense SE read, unary mix, softmax ----
__global__ void k_zupd(const float* __restrict__ x, const int* __restrict__ mask,
                       const int* __restrict__ mmask, int useSE) {
    int zi = blockIdx.x, d = threadIdx.x;
    __shared__ float r1[4], r2[4];
    float g = 0.f;
    #pragma unroll
    for (int p = 0; p < 8; p++) g += g_Gpart[((size_t)p * 512 + zi) * 128 + d];
    float mm = (float)mmask[zi];
    float se = 0.f;
    if (mm != 0.f) {
        if (useSE) {
            int pos = g_mpos[zi];
            if (pos >= 0) se = g_SE[pos * 128 + d];
        } else se = g_emean[d];
    }
    float raw = x[zi * 128 + d] * (1.f - mm) + se * mm + g;
    float keep = mask[zi] ? 1.f : 0.f;
    float p_ = softmax128(raw, r1, r2);
    g_qz[zi * 128 + d] = p_ * keep;
}

// ==================== fused SE: v-tile 128, 8m x 8v GEMM1 (1 B/MAC), Ps in [v][m] ====
#define QZT_OFF 0                         // [128 d][132 m]
#define ETD_OFF (128 * 132)               // [128 d][132 v]  (v-tile = 128)
#define EVD_OFF (ETD_OFF + 128 * 132)     // [64 v][132 d]   (per half)
#define PS_OFF  (EVD_OFF + 64 * 132)      // [64 v][132 m]   (per half)
#define SEF_SMEM ((PS_OFF + 64 * 132) * 4)

__global__ void __launch_bounds__(256) k_sef(const float* __restrict__ E) {
    int count = g_mcount;
    if (count == 0) return;
    int ntiles = (count + 127) >> 7;
    int b = blockIdx.x;
    int mt = (b * ntiles) / 148;
    int gb0 = (mt * 148 + ntiles - 1) / ntiles;
    int gb1 = ((mt + 1) * 148 + ntiles - 1) / ntiles;
    int gsz = gb1 - gb0, li = b - gb0;
    int ustart = (li * 250) / gsz;
    int ucount = ((li + 1) * 250) / gsz - ustart;
    int m0 = mt * 128;

    extern __shared__ float sm[];
    float* qzT = sm + QZT_OFF;
    float* Etd = sm + ETD_OFF;
    float* Evd = sm + EVD_OFF;
    float* Ps  = sm + PS_OFF;
    int t = threadIdx.x;

    // load qz (compacted rows) transposed: qzT[d][m]
    {
        int m = t >> 1, d0 = (t & 1) * 64;
        int pos = m0 + m;
        int zi = (pos < count) ? g_midx[pos] : 0;
        const float* src = g_qz + (size_t)zi * 128 + d0;
        #pragma unroll
        for (int q = 0; q < 16; q++) {
            float4 v = *(const float4*)(src + q * 4);
            qzT[(d0 + q * 4 + 0) * 132 + m] = v.x;
            qzT[(d0 + q * 4 + 1) * 132 + m] = v.y;
            qzT[(d0 + q * 4 + 2) * 132 + m] = v.z;
            qzT[(d0 + q * 4 + 3) * 132 + m] = v.w;
        }
    }

    int tm1 = t >> 4, tv8 = t & 15;        // GEMM1: 8m x 8v
    int tmg = t >> 4, tdg = t & 15;        // GEMM2: 8m x 8d
    ull acc[8][4];
    #pragma unroll
    for (int i = 0; i < 8; i++)
        #pragma unroll
        for (int q = 0; q < 4; q++) acc[i][q] = pk2(0.f, 0.f);
    float psum[8];
    #pragma unroll
    for (int i = 0; i < 8; i++) psum[i] = 0.f;

    for (int tile = 0; tile < ucount; tile++) {
        int vg = (ustart + tile) * 128;
        __syncthreads();   // protect Etd/Evd/Ps from previous tile's readers
        // load Etd[d][0..128)
        {
            int d = t >> 1, vq = (t & 1) * 64;
            const float* src = g_ET + (size_t)d * 32000 + vg + vq;
            float* dst = Etd + d * 132 + vq;
            #pragma unroll
            for (int q = 0; q < 16; q++) *(float4*)(dst + q * 4) = *(const float4*)(src + q * 4);
        }
        // load Evd half0
        {
            int v = t >> 2, dq = (t & 3) * 32;
            const float* src = E + (size_t)(vg + v) * 128 + dq;
            float* dst = Evd + v * 132 + dq;
            #pragma unroll
            for (int q = 0; q < 8; q++) *(float4*)(dst + q * 4) = *(const float4*)(src + q * 4);
        }
        __syncthreads();
        // GEMM1: L[8m][8v], 16 floats LDS per 64 MACs
        ull L[8][4];
        #pragma unroll
        for (int i = 0; i < 8; i++)
            #pragma unroll
            for (int q = 0; q < 4; q++) L[i][q] = pk2(0.f, 0.f);
        #pragma unroll 2
        for (int d = 0; d < 128; d++) {
            float4 a0 = *(const float4*)&qzT[d * 132 + tm1 * 8];
            float4 a1 = *(const float4*)&qzT[d * 132 + tm1 * 8 + 4];
            float4 b0 = *(const float4*)&Etd[d * 132 + tv8 * 8];
            float4 b1 = *(const float4*)&Etd[d * 132 + tv8 * 8 + 4];
            ull bb[4] = {pk2(b0.x, b0.y), pk2(b0.z, b0.w), pk2(b1.x, b1.y), pk2(b1.z, b1.w)};
            float av[8] = {a0.x, a0.y, a0.z, a0.w, a1.x, a1.y, a1.z, a1.w};
            #pragma unroll
            for (int i = 0; i < 8; i++) {
                ull ai = pk2(av[i], av[i]);
                fma2(L[i][0], ai, bb[0]); fma2(L[i][1], ai, bb[1]);
                fma2(L[i][2], ai, bb[2]); fma2(L[i][3], ai, bb[3]);
            }
        }
        // exp in place + psum
        #pragma unroll
        for (int i = 0; i < 8; i++)
            #pragma unroll
            for (int q = 0; q < 4; q++) {
                float e0, e1;
                upk(L[i][q], e0, e1);
                e0 = fexp(e0); e1 = fexp(e1);
                psum[i] += e0 + e1;
                L[i][q] = pk2(e0, e1);
            }
        // Ps half0 [v][m]: threads tv8<8 own v = tv8*8 + (0..7)
        if (tv8 < 8) {
            #pragma unroll
            for (int i = 0; i < 8; i++) {
                int m = tm1 * 8 + i;
                float e[8];
                upk(L[i][0], e[0], e[1]); upk(L[i][1], e[2], e[3]);
                upk(L[i][2], e[4], e[5]); upk(L[i][3], e[6], e[7]);
                #pragma unroll
                for (int j = 0; j < 8; j++) Ps[(tv8 * 8 + j) * 132 + m] = e[j];
            }
        }
        __syncthreads();
        // GEMM2 half0
        #pragma unroll 4
        for (int v = 0; v < 64; v++) {
            float4 a0 = *(const float4*)&Ps[v * 132 + tmg * 8];
            float4 a1 = *(const float4*)&Ps[v * 132 + tmg * 8 + 4];
            float4 b0 = *(const float4*)&Evd[v * 132 + tdg * 8];
            float4 b1 = *(const float4*)&Evd[v * 132 + tdg * 8 + 4];
            ull bb[4] = {pk2(b0.x, b0.y), pk2(b0.z, b0.w), pk2(b1.x, b1.y), pk2(b1.z, b1.w)};
            float av[8] = {a0.x, a0.y, a0.z, a0.w, a1.x, a1.y, a1.z, a1.w};
            #pragma unroll
            for (int i = 0; i < 8; i++) {
                ull ai = pk2(av[i], av[i]);
                fma2(acc[i][0], ai, bb[0]); fma2(acc[i][1], ai, bb[1]);
                fma2(acc[i][2], ai, bb[2]); fma2(acc[i][3], ai, bb[3]);
            }
        }
        __syncthreads();
        // load Evd half1 + write Ps half1 (threads tv8>=8 own v = 64 + (tv8-8)*8 + j)
        {
            int v = t >> 2, dq = (t & 3) * 32;
            const float* src = E + (size_t)(vg + 64 + v) * 128 + dq;
            float* dst = Evd + v * 132 + dq;
            #pragma unroll
            for (int q = 0; q < 8; q++) *(float4*)(dst + q * 4) = *(const float4*)(src + q * 4);
        }
        if (tv8 >= 8) {
            #pragma unroll
            for (int i = 0; i < 8; i++) {
                int m = tm1 * 8 + i;
                float e[8];
                upk(L[i][0], e[0], e[1]); upk(L[i][1], e[2], e[3]);
                upk(L[i][2], e[4], e[5]); upk(L[i][3], e[6], e[7]);
                #pragma unroll
                for (int j = 0; j < 8; j++) Ps[((tv8 - 8) * 8 + j) * 132 + m] = e[j];
            }
        }
        __syncthreads();
        // GEMM2 half1
        #pragma unroll 4
        for (int v = 0; v < 64; v++) {
            float4 a0 = *(const float4*)&Ps[v * 132 + tmg * 8];
            float4 a1 = *(const float4*)&Ps[v * 132 + tmg * 8 + 4];
            float4 b0 = *(const float4*)&Evd[v * 132 + tdg * 8];
            float4 b1 = *(const float4*)&Evd[v * 132 + tdg * 8 + 4];
            ull bb[4] = {pk2(b0.x, b0.y), pk2(b0.z, b0.w), pk2(b1.x, b1.y), pk2(b1.z, b1.w)};
            float av[8] = {a0.x, a0.y, a0.z, a0.w, a1.x, a1.y, a1.z, a1.w};
            #pragma unroll
            for (int i = 0; i < 8; i++) {
                ull ai = pk2(av[i], av[i]);
                fma2(acc[i][0], ai, bb[0]); fma2(acc[i][1], ai, bb[1]);
                fma2(acc[i][2], ai, bb[2]); fma2(acc[i][3], ai, bb[3]);
            }
        }
    }
    // write per-block partials
    #pragma unroll
    for (int i = 0; i < 8; i++) {
        float f[8];
        upk(acc[i][0], f[0], f[1]); upk(acc[i][1], f[2], f[3]);
        upk(acc[i][2], f[4], f[5]); upk(acc[i][3], f[6], f[7]);
        size_t base = ((size_t)b * 128 + tmg * 8 + i) * 128 + tdg * 8;
        *(float4*)&g_SEpart[base]     = make_float4(f[0], f[1], f[2], f[3]);
        *(float4*)&g_SEpart[base + 4] = make_float4(f[4], f[5], f[6], f[7]);
    }
    // reduce psum across the 16 tv8 groups (reuse Etd: [128 m][17])
    __syncthreads();
    float* red = Etd;
    #pragma unroll
    for (int i = 0; i < 8; i++) red[(tm1 * 8 + i) * 17 + tv8] = psum[i];
    __syncthreads();
    if (t < 128) {
        float s = 0.f;
        #pragma unroll
        for (int q = 0; q < 16; q++) s += red[t * 17 + q];
        g_SEsum[b * 128 + t] = s;
    }
}

// ==================== final out = qz @ E^T ====================
__global__ void __launch_bounds__(256) k_msg(const float* __restrict__ E, float* __restrict__ out) {
    __shared__ float As[8][128], Bs[8][128];
    int t = threadIdx.x;
    int m0 = blockIdx.y * 128, n0 = blockIdx.x * 128;
    int row = t >> 1, kq = (t & 1) * 4;
    int tm = t >> 4, tn = t & 15;
    ull acc[8][4];
    #pragma unroll
    for (int i = 0; i < 8; i++)
        #pragma unroll
        for (int q = 0; q < 4; q++) acc[i][q] = pk2(0.f, 0.f);
    for (int s = 0; s < 16; s++) {
        int k0 = s * 8;
        float4 av = *(const float4*)&g_qz[(m0 + row) * 128 + k0 + kq];
        float4 bv = *(const float4*)&E[(size_t)(n0 + row) * 128 + k0 + kq];
        __syncthreads();
        As[kq][row] = av.x; As[kq + 1][row] = av.y; As[kq + 2][row] = av.z; As[kq + 3][row] = av.w;
        Bs[kq][row] = bv.x; Bs[kq + 1][row] = bv.y; Bs[kq + 2][row] = bv.z; Bs[kq + 3][row] = bv.w;
        __syncthreads();
        #pragma unroll
        for (int p = 0; p < 8; p++) {
            float4 a0 = *(const float4*)&As[p][tm * 8], a1 = *(const float4*)&As[p][tm * 8 + 4];
            float4 b0 = *(const float4*)&Bs[p][tn * 8], b1 = *(const float4*)&Bs[p][tn * 8 + 4];
            ull bb[4] = {pk2(b0.x, b0.y), pk2(b0.z, b0.w), pk2(b1.x, b1.y), pk2(b1.z, b1.w)};
            float avv[8] = {a0.x, a0.y, a0.z, a0.w, a1.x, a1.y, a1.z, a1.w};
            #pragma unroll
            for (int i = 0; i < 8; i++) {
                ull ai = pk2(avv[i], avv[i]);
                fma2(acc[i][0], ai, bb[0]); fma2(acc[i][1], ai, bb[1]);
                fma2(acc[i][2], ai, bb[2]); fma2(acc[i][3], ai, bb[3]);
            }
        }
    }
    #pragma unroll
    for (int i = 0; i < 8; i++) {
        float f[8];
        upk(acc[i][0], f[0], f[1]); upk(acc[i][1], f[2], f[3]);
        upk(acc[i][2], f[4], f[5]); upk(acc[i][3], f[6], f[7]);
        size_t base = (size_t)(m0 + tm * 8 + i) * 32000 + n0 + tn * 8;
        *(float4*)&out[base] = make_float4(f[0], f[1], f[2], f[3]);
        *(float4*)&out[base + 4] = make_float4(f[4], f[5], f[6], f[7]);
    }
}

// ==================== launch ====================
extern "C" void kernel_launch(void* const* d_in, const int* in_sizes, int n_in,
                              void* d_out, int out_size) {
    const float* x    = (const float*)d_in[0];
    const int*   mask = (const int*)d_in[1];
    const float* E    = (const float*)d_in[2];
    const int*   mm   = (const int*)d_in[3];
    const float* T    = (const float*)d_in[4];
    float* out = (float*)d_out;

    static cudaStream_t s2 = nullptr;
    static cudaEvent_t eF = nullptr, eJ = nullptr;
    if (!s2) {
        cudaStreamCreate(&s2);
        cudaEventCreateWithFlags(&eF, cudaEventDisableTiming);
        cudaEventCreateWithFlags(&eJ, cudaEventDisableTiming);
        cudaFuncSetAttribute(k_sef, cudaFuncAttributeMaxDynamicSharedMemorySize, SEF_SMEM);
    }
    cudaStream_t s0 = 0;

    cudaEventRecord(eF, s0);
    cudaStreamWaitEvent(s2, eF, 0);
    k_transE<<<dim3(250, 4), 256, 0, s2>>>(E);

    k_emean_part<<<64, 256, 0, s0>>>(E);
    k_emean_red<<<1, 128, 0, s0>>>();
    k_bmat<<<2048, 256, 0, s0>>>(T);
    k_midx<<<1, 512, 0, s0>>>(mask, mm);
    k_init_qz<<<512, 128, 0, s0>>>(x, mask, mm);

    for (int it = 0; it < 4; it++) {
        k_nn64<<<dim3(16, 8, 2), 256, 0, s0>>>(T, 0);
        k_F<<<512, 256, 0, s0>>>(mask);
        k_S<<<512, 256, 0, s0>>>();
        k_nn64<<<dim3(2, 8, 8), 256, 0, s0>>>(T, 1);
        if (it > 0) cudaStreamWaitEvent(s0, eJ, 0);
        k_zupd<<<512, 128, 0, s0>>>(x, mask, mm, it > 0);
        if (it < 3) {
            cudaEventRecord(eF, s0);
            cudaStreamWaitEvent(s2, eF, 0);
            k_sef<<<148, 256, SEF_SMEM, s2>>>(E);
            k_sered<<<512, 128, 0, s2>>>();
            cudaEventRecord(eJ, s2);
        } else {
            k_msg<<<dim3(250, 4), 256, 0, s0>>>(E, out);
        }
    }
}

// round 12
// speedup vs baseline: 1.1076x; 1.0146x over previous
#include <cuda_runtime.h>
#include <math.h>
#include <stdint.h>

#define NEGC 1.0e9f
typedef unsigned long long ull;

// ==================== static scratch ====================
__device__ float g_epart[64 * 128];
__device__ float g_emean[128];
__device__ float g_Bmat[4096 * 128];
__device__ float g_qz[512 * 128];
__device__ float g_U[2 * 512 * 1024];
__device__ float g_qhn[4 * 8 * 128 * 128];
__device__ float g_qhnT[4 * 8 * 128 * 128];
__device__ float g_S[512 * 4096];
__device__ float g_Gpart[8 * 512 * 128];
__device__ float g_ET[128 * 32000];          // E transposed (fp32)
__device__ float g_SEpart[148 * 128 * 128];  // per-block partials (compact rows)
__device__ float g_SEsum[148 * 128];
__device__ float g_SE[512 * 128];            // dense reduced SE (compact rows)
__device__ int   g_midx[512];
__device__ int   g_mpos[512];
__device__ int   g_mcount;

// ---- f32x2 helpers ----
__device__ __forceinline__ ull pk2(float lo, float hi) {
    ull r; asm("mov.b64 %0, {%1, %2};" : "=l"(r) : "f"(lo), "f"(hi)); return r;
}
__device__ __forceinline__ void fma2(ull &d, ull a, ull b) {
    asm("fma.rn.f32x2 %0, %1, %2, %3;" : "=l"(d) : "l"(a), "l"(b), "l"(d));
}
__device__ __forceinline__ void upk(ull v, float &lo, float &hi) {
    asm("mov.b64 {%0, %1}, %2;" : "=f"(lo), "=f"(hi) : "l"(v));
}

// ---- FMA-pipe exp (no MUFU). Valid for |x| < ~80. ----
__device__ __forceinline__ float fexp(float x) {
    float z = x * 1.4426950408889634f;
    float m = z + 12582912.0f;
    int ni = __float_as_int(m) - 0x4B400000;
    float f = z - (m - 12582912.0f);
    float p = 0.0013333558f;
    p = fmaf(p, f, 0.0096181291f);
    p = fmaf(p, f, 0.0555041087f);
    p = fmaf(p, f, 0.2402265070f);
    p = fmaf(p, f, 0.6931471806f);
    p = fmaf(p, f, 1.0f);
    return p * __int_as_float((ni + 127) << 23);
}
__device__ __forceinline__ float fexp_s(float x) { return fexp(fmaxf(x, -80.f)); }

// ==================== setup ====================
__global__ void k_emean_part(const float* __restrict__ E) {
    int b = blockIdx.x, t = threadIdx.x;
    int d = t & 127, h = t >> 7;
    float s = 0.f;
    for (int v = b * 500 + h; v < b * 500 + 500; v += 2) s += E[v * 128 + d];
    __shared__ float sh[256];
    sh[t] = s; __syncthreads();
    if (t < 128) g_epart[b * 128 + t] = sh[t] + sh[t + 128];
}
__global__ void k_emean_red() {
    int t = threadIdx.x;
    float s = 0.f;
    for (int b = 0; b < 64; b++) s += g_epart[b * 128 + t];
    g_emean[t] = s * (1.0f / 32000.0f);
}

__global__ void k_bmat(const float* __restrict__ T) {
    int idx = blockIdx.x * 256 + threadIdx.x;
    if (idx >= 4096 * 128) return;
    int r = idx >> 7, col = idx & 127;
    float val;
    if (r < 2048) {
        int k = r >> 10, c = (r >> 7) & 7, b = r & 127;
        val = T[((k * 128 + col) * 128 + b) * 8 + c];
    } else {
        int r2 = r - 2048;
        int k = r2 >> 10, c = (r2 >> 7) & 7, a = r2 & 127;
        val = T[((k * 128 + a) * 128 + col) * 8 + c];
    }
    g_Bmat[idx] = val;
}

__global__ void k_transE(const float* __restrict__ E) {
    __shared__ float tile[128][33];
    int v0 = blockIdx.x * 128, d0 = blockIdx.y * 32, t = threadIdx.x;
    for (int idx = t; idx < 4096; idx += 256) {
        int r = idx >> 5, c = idx & 31;
        tile[r][c] = E[(size_t)(v0 + r) * 128 + d0 + c];
    }
    __syncthreads();
    for (int idx = t; idx < 4096; idx += 256) {
        int d = idx >> 7, vv = idx & 127;
        g_ET[(size_t)(d0 + d) * 32000 + v0 + vv] = tile[vv][d];
    }
}

__global__ void k_midx(const int* __restrict__ mask, const int* __restrict__ mmask) {
    __shared__ int pref[512];
    int t = threadIdx.x;
    int f = (mmask[t] != 0 && mask[t] != 0) ? 1 : 0;
    pref[t] = f;
    __syncthreads();
    for (int o = 1; o < 512; o <<= 1) {
        int v = (t >= o) ? pref[t - o] : 0;
        __syncthreads();
        pref[t] += v;
        __syncthreads();
    }
    if (f) { int pos = pref[t] - 1; g_midx[pos] = t; g_mpos[t] = pos; }
    else g_mpos[t] = -1;
    if (t == 511) g_mcount = pref[511];
}

__device__ __forceinline__ float softmax128(float raw, float* r1, float* r2) {
    int lane = threadIdx.x & 31, w = threadIdx.x >> 5;
    float m = raw;
    #pragma unroll
    for (int o = 16; o; o >>= 1) m = fmaxf(m, __shfl_xor_sync(~0u, m, o));
    if (lane == 0) r1[w] = m;
    __syncthreads();
    m = fmaxf(fmaxf(r1[0], r1[1]), fmaxf(r1[2], r1[3]));
    float e = fexp_s(raw - m), s = e;
    #pragma unroll
    for (int o = 16; o; o >>= 1) s += __shfl_xor_sync(~0u, s, o);
    if (lane == 0) r2[w] = s;
    __syncthreads();
    return e / (r2[0] + r2[1] + r2[2] + r2[3]);
}

__global__ void k_init_qz(const float* __restrict__ x, const int* __restrict__ mask,
                          const int* __restrict__ mmask) {
    int zi = blockIdx.x, a = threadIdx.x;
    __shared__ float r1[4], r2[4];
    float keep = mask[zi] ? 1.f : 0.f;
    float mm = (float)mmask[zi];
    float raw = (x[zi * 128 + a] * (1.f - mm) + g_emean[a] * mm) * keep;
    float p = softmax128(raw, r1, r2);
    g_qz[zi * 128 + a] = p * keep;
}

// ==================== small FFMA GEMMs ====================
__global__ void __launch_bounds__(256) k_nn64(const float* __restrict__ T, int which) {
    const float *A, *B; float *C;
    int lda, ldb, ldc, ksteps, kb;
    if (which == 0) {
        int kk = blockIdx.z;
        A = g_qz; lda = 128; B = T + kk * 131072; ldb = 1024;
        C = g_U + (size_t)kk * 524288; ldc = 1024; ksteps = 8; kb = 0;
    } else {
        int ks = blockIdx.z;
        A = g_S; lda = 4096; B = g_Bmat; ldb = 128;
        C = g_Gpart + (size_t)ks * 65536; ldc = 128; ksteps = 32; kb = ks * 512;
    }
    int m0 = blockIdx.y * 64, n0 = blockIdx.x * 64;
    __shared__ float As[16][68], Bs[16][64];
    int t = threadIdx.x, tm = t >> 4, tn = t & 15;
    ull acc[4][2];
    #pragma unroll
    for (int i = 0; i < 4; i++) { acc[i][0] = pk2(0.f, 0.f); acc[i][1] = pk2(0.f, 0.f); }
    for (int s = 0; s < ksteps; s++) {
        int k0 = kb + s * 16;
        { int r = t >> 2, c4 = (t & 3) * 4;
          float4 av = *(const float4*)&A[(size_t)(m0 + r) * lda + k0 + c4];
          As[c4][r] = av.x; As[c4 + 1][r] = av.y; As[c4 + 2][r] = av.z; As[c4 + 3][r] = av.w; }
        { int r = t >> 4, c4 = (t & 15) * 4;
          *(float4*)&Bs[r][c4] = *(const float4*)&B[(size_t)(k0 + r) * ldb + n0 + c4]; }
        __syncthreads();
        #pragma unroll
        for (int p = 0; p < 16; p++) {
            float4 a = *(const float4*)&As[p][tm * 4];
            float4 b = *(const float4*)&Bs[p][tn * 4];
            ull b01 = pk2(b.x, b.y), b23 = pk2(b.z, b.w);
            ull a0 = pk2(a.x, a.x), a1 = pk2(a.y, a.y), a2 = pk2(a.z, a.z), a3 = pk2(a.w, a.w);
            fma2(acc[0][0], a0, b01); fma2(acc[0][1], a0, b23);
            fma2(acc[1][0], a1, b01); fma2(acc[1][1], a1, b23);
            fma2(acc[2][0], a2, b01); fma2(acc[2][1], a2, b23);
            fma2(acc[3][0], a3, b01); fma2(acc[3][1], a3, b23);
        }
        __syncthreads();
    }
    #pragma unroll
    for (int i = 0; i < 4; i++) {
        float c0, c1, c2, c3;
        upk(acc[i][0], c0, c1); upk(acc[i][1], c2, c3);
        *(float4*)&C[(size_t)(m0 + tm * 4 + i) * ldc + n0 + tn * 4] = make_float4(c0, c1, c2, c3);
    }
}

__global__ void __launch_bounds__(256) k_F(const int* __restrict__ mask) {
    int zi = blockIdx.x, z = zi >> 7, i = zi & 127;
    int t = threadIdx.x;
    __shared__ float U_sh[2][1024];
    __shared__ float qz_sh[32][129];
    __shared__ float qh_sh[8][128];
    __shared__ float smax[8], ssum[8];
    for (int idx = t; idx < 2048; idx += 256) {
        int k = idx >> 10, bc = idx & 1023;
        U_sh[k][bc] = g_U[((size_t)k * 512 + zi) * 1024 + bc];
    }
    int j = t & 127, ch = t >> 7;
    int ksel = (j > i) ? 0 : 1;
    float a0 = 0.f, a1 = 0.f, a2 = 0.f, a3 = 0.f;
    const float* qzb = g_qz + z * 128 * 128;
    for (int b0 = 0; b0 < 128; b0 += 32) {
        __syncthreads();
        #pragma unroll
        for (int e = 0; e < 16; e++) {
            int lin = t + e * 256;
            int jj = lin >> 5, col = lin & 31;
            qz_sh[col][jj] = qzb[jj * 128 + b0 + col];
        }
        __syncthreads();
        #pragma unroll 8
        for (int bb = 0; bb < 32; bb++) {
            float qv = qz_sh[bb][j];
            float4 u4 = *(const float4*)&U_sh[ksel][(b0 + bb) * 8 + ch * 4];
            a0 += qv * u4.x; a1 += qv * u4.y; a2 += qv * u4.z; a3 += qv * u4.w;
        }
    }
    bool vi = mask[z * 128 + i] != 0, vj = mask[z * 128 + j] != 0;
    if (i == j || !vi || !vj) { a0 = a1 = a2 = a3 = -NEGC; }
    qh_sh[ch * 4 + 0][j] = a0; qh_sh[ch * 4 + 1][j] = a1;
    qh_sh[ch * 4 + 2][j] = a2; qh_sh[ch * 4 + 3][j] = a3;
    __syncthreads();
    int w = t >> 5, lane = t & 31;
    float v0 = qh_sh[w][lane], v1 = qh_sh[w][lane + 32];
    float v2 = qh_sh[w][lane + 64], v3 = qh_sh[w][lane + 96];
    float mx = fmaxf(fmaxf(v0, v1), fmaxf(v2, v3));
    #pragma unroll
    for (int o = 16; o; o >>= 1) mx = fmaxf(mx, __shfl_xor_sync(~0u, mx, o));
    float sum = fexp_s(v0 - mx) + fexp_s(v1 - mx) + fexp_s(v2 - mx) + fexp_s(v3 - mx);
    #pragma unroll
    for (int o = 16; o; o >>= 1) sum += __shfl_xor_sync(~0u, sum, o);
    if (lane == 0) { smax[w] = mx; ssum[w] = sum; }
    __syncthreads();
    float vals[4] = {a0, a1, a2, a3};
    #pragma unroll
    for (int hh = 0; hh < 4; hh++) {
        int h = ch * 4 + hh;
        float p = fexp_s(vals[hh] - smax[h]) / ssum[h];
        g_qhn[(((z * 8 + h) * 128 + i) << 7) + j] = p;   // coalesced only
    }
}

// tiled transpose qhn -> qhnT (both directions coalesced)
__global__ void __launch_bounds__(256) k_trq() {
    __shared__ float tile[32][33];
    int zh = blockIdx.x;                       // 0..31  (z*8+h)
    int ti = blockIdx.y >> 2, tj = blockIdx.y & 3;  // 4x4 tiles of 32
    int t = threadIdx.x;
    int r = t >> 5, c = t & 31;                // 8 rows x 32 cols
    const float* src = g_qhn + ((size_t)zh << 14);
    float* dst = g_qhnT + ((size_t)zh << 14);
    #pragma unroll
    for (int q = 0; q < 4; q++)
        tile[r + q * 8][c] = src[(ti * 32 + r + q * 8) * 128 + tj * 32 + c];
    __syncthreads();
    #pragma unroll
    for (int q = 0; q < 4; q++)
        dst[(tj * 32 + r + q * 8) * 128 + ti * 32 + c] = tile[c][r + q * 8];
}

__global__ void __launch_bounds__(256) k_S() {
    int zi = blockIdx.x, z = zi >> 7, i = zi & 127;
    int t = threadIdx.x;
    __shared__ float wT[128][36];
    __shared__ float qzc[32][128];
    // coalesced load: consecutive threads read consecutive j
    for (int idx = t; idx < 4096; idx += 256) {
        int r = idx >> 7, j = idx & 127;
        float v; bool m;
        if (r < 16) {
            int k = r >> 3, c = r & 7;
            v = g_qhn[(((z * 8 + c) * 128 + i) << 7) + j];
            m = (k == 0) ? (j > i) : (j < i);
        } else {
            int r2 = r - 16, k = r2 >> 3, c = r2 & 7;
            v = g_qhnT[(((z * 8 + c) * 128 + i) << 7) + j];
            m = (k == 0) ? (j < i) : (j > i);
        }
        wT[j][r] = m ? v : 0.f;
    }
    int tm = t >> 5, tn = t & 31;
    ull acc[4][2];
    #pragma unroll
    for (int q = 0; q < 4; q++) { acc[q][0] = pk2(0.f, 0.f); acc[q][1] = pk2(0.f, 0.f); }
    for (int j0 = 0; j0 < 128; j0 += 32) {
        __syncthreads();
        for (int idx = t; idx < 4096; idx += 256) {
            int jl = idx >> 7, b = idx & 127;
            qzc[jl][b] = g_qz[((z * 128) + j0 + jl) * 128 + b];
        }
        __syncthreads();
        #pragma unroll 8
        for (int jl = 0; jl < 32; jl++) {
            float4 wv = *(const float4*)&wT[j0 + jl][tm * 4];
            float4 qv = *(const float4*)&qzc[jl][tn * 4];
            ull q01 = pk2(qv.x, qv.y), q23 = pk2(qv.z, qv.w);
            ull w0 = pk2(wv.x, wv.x), w1 = pk2(wv.y, wv.y), w2 = pk2(wv.z, wv.z), w3 = pk2(wv.w, wv.w);
            fma2(acc[0][0], w0, q01); fma2(acc[0][1], w0, q23);
            fma2(acc[1][0], w1, q01); fma2(acc[1][1], w1, q23);
            fma2(acc[2][0], w2, q01); fma2(acc[2][1], w2, q23);
            fma2(acc[3][0], w3, q01); fma2(acc[3][1], w3, q23);
        }
    }
    #pragma unroll
    for (int q = 0; q < 4; q++) {
        int r = tm * 4 + q;
        int base = (r < 16) ? r * 128 : 2048 + (r - 16) * 128;
        float c0, c1, c2, c3;
        upk(acc[q][0], c0, c1); upk(acc[q][1], c2, c3);
        *(float4*)&g_S[(size_t)zi * 4096 + base + tn * 4] = make_float4(c0, c1, c2, c3);
    }
}

// ---- reduce per-block SE partials into dense g_SE (runs on side stream) ----
__global__ void k_sered() {
    int count = g_mcount;
    int pos = blockIdx.x;
    if (pos >= count) return;
    int ntiles = (count + 127) >> 7;
    int mt = pos >> 7, row = pos & 127;
    int gb0 = (mt * 148 + ntiles - 1) / ntiles;
    int gb1 = ((mt + 1) * 148 + ntiles - 1) / ntiles;
    int d = threadIdx.x;
    float num = 0.f, den = 0.f;
    for (int bb = gb0; bb < gb1; bb++) {
        num += g_SEpart[((size_t)bb * 128 + row) * 128 + d];
        den += g_SEsum[bb * 128 + row];
    }
    g_SE[pos * 128 + d] = num / den;
}

// ---- Z update: dense SE read, unary mix, softmax ----
__global__ void k_zupd(const float* __restrict__ x, const int* __restrict__ mask,
                       const int* __restrict__ mmask, int useSE) {
    int zi = blockIdx.x, d = threadIdx.x;
    __shared__ float r1[4], r2[4];
    float g = 0.f;
    #pragma unroll
    for (int p = 0; p < 8; p++) g += g_Gpart[((size_t)p * 512 + zi) * 128 + d];
    float mm = (float)mmask[zi];
    float se = 0.f;
    if (mm != 0.f) {
        if (useSE) {
            int pos = g_mpos[zi];
            if (pos >= 0) se = g_SE[pos * 128 + d];
        } else se = g_emean[d];
    }
    float raw = x[zi * 128 + d] * (1.f - mm) + se * mm + g;
    float keep = mask[zi] ? 1.f : 0.f;
    float p_ = softmax128(raw, r1, r2);
    g_qz[zi * 128 + d] = p_ * keep;
}

// ==================== fused SE: v-tile 128, 8m x 8v GEMM1, Ps in [v][m] ====
#define QZT_OFF 0                         // [128 d][132 m]
#define ETD_OFF (128 * 132)               // [128 d][132 v]  (v-tile = 128)
#define EVD_OFF (ETD_OFF + 128 * 132)     // [64 v][132 d]   (per half)
#define PS_OFF  (EVD_OFF + 64 * 132)      // [64 v][132 m]   (per half)
#define SEF_SMEM ((PS_OFF + 64 * 132) * 4)

__global__ void __launch_bounds__(256) k_sef(const float* __restrict__ E) {
    int count = g_mcount;
    if (count == 0) return;
    int ntiles = (count + 127) >> 7;
    int b = blockIdx.x;
    int mt = (b * ntiles) / 148;
    int gb0 = (mt * 148 + ntiles - 1) / ntiles;
    int gb1 = ((mt + 1) * 148 + ntiles - 1) / ntiles;
    int gsz = gb1 - gb0, li = b - gb0;
    int ustart = (li * 250) / gsz;
    int ucount = ((li + 1) * 250) / gsz - ustart;
    int m0 = mt * 128;

    extern __shared__ float sm[];
    float* qzT = sm + QZT_OFF;
    float* Etd = sm + ETD_OFF;
    float* Evd = sm + EVD_OFF;
    float* Ps  = sm + PS_OFF;
    int t = threadIdx.x;

    {
        int m = t >> 1, d0 = (t & 1) * 64;
        int pos = m0 + m;
        int zi = (pos < count) ? g_midx[pos] : 0;
        const float* src = g_qz + (size_t)zi * 128 + d0;
        #pragma unroll
        for (int q = 0; q < 16; q++) {
            float4 v = *(const float4*)(src + q * 4);
            qzT[(d0 + q * 4 + 0) * 132 + m] = v.x;
            qzT[(d0 + q * 4 + 1) * 132 + m] = v.y;
            qzT[(d0 + q * 4 + 2) * 132 + m] = v.z;
            qzT[(d0 + q * 4 + 3) * 132 + m] = v.w;
        }
    }

    int tm1 = t >> 4, tv8 = t & 15;
    int tmg = t >> 4, tdg = t & 15;
    ull acc[8][4];
    #pragma unroll
    for (int i = 0; i < 8; i++)
        #pragma unroll
        for (int q = 0; q < 4; q++) acc[i][q] = pk2(0.f, 0.f);
    float psum[8];
    #pragma unroll
    for (int i = 0; i < 8; i++) psum[i] = 0.f;

    for (int tile = 0; tile < ucount; tile++) {
        int vg = (ustart + tile) * 128;
        __syncthreads();
        {
            int d = t >> 1, vq = (t & 1) * 64;
            const float* src = g_ET + (size_t)d * 32000 + vg + vq;
            float* dst = Etd + d * 132 + vq;
            #pragma unroll
            for (int q = 0; q < 16; q++) *(float4*)(dst + q * 4) = *(const float4*)(src + q * 4);
        }
        {
            int v = t >> 2, dq = (t & 3) * 32;
            const float* src = E + (size_t)(vg + v) * 128 + dq;
            float* dst = Evd + v * 132 + dq;
            #pragma unroll
            for (int q = 0; q < 8; q++) *(float4*)(dst + q * 4) = *(const float4*)(src + q * 4);
        }
        __syncthreads();
        ull L[8][4];
        #pragma unroll
        for (int i = 0; i < 8; i++)
            #pragma unroll
            for (int q = 0; q < 4; q++) L[i][q] = pk2(0.f, 0.f);
        #pragma unroll 2
        for (int d = 0; d < 128; d++) {
            float4 a0 = *(const float4*)&qzT[d * 132 + tm1 * 8];
            float4 a1 = *(const float4*)&qzT[d * 132 + tm1 * 8 + 4];
            float4 b0 = *(const float4*)&Etd[d * 132 + tv8 * 8];
            float4 b1 = *(const float4*)&Etd[d * 132 + tv8 * 8 + 4];
            ull bb[4] = {pk2(b0.x, b0.y), pk2(b0.z, b0.w), pk2(b1.x, b1.y), pk2(b1.z, b1.w)};
            float av[8] = {a0.x, a0.y, a0.z, a0.w, a1.x, a1.y, a1.z, a1.w};
            #pragma unroll
            for (int i = 0; i < 8; i++) {
                ull ai = pk2(av[i], av[i]);
                fma2(L[i][0], ai, bb[0]); fma2(L[i][1], ai, bb[1]);
                fma2(L[i][2], ai, bb[2]); fma2(L[i][3], ai, bb[3]);
            }
        }
        #pragma unroll
        for (int i = 0; i < 8; i++)
            #pragma unroll
            for (int q = 0; q < 4; q++) {
                float e0, e1;
                upk(L[i][q], e0, e1);
                e0 = fexp(e0); e1 = fexp(e1);
                psum[i] += e0 + e1;
                L[i][q] = pk2(e0, e1);
            }
        if (tv8 < 8) {
            #pragma unroll
            for (int i = 0; i < 8; i++) {
                int m = tm1 * 8 + i;
                float e[8];
                upk(L[i][0], e[0], e[1]); upk(L[i][1], e[2], e[3]);
                upk(L[i][2], e[4], e[5]); upk(L[i][3], e[6], e[7]);
                #pragma unroll
                for (int j = 0; j < 8; j++) Ps[(tv8 * 8 + j) * 132 + m] = e[j];
            }
        }
        __syncthreads();
        #pragma unroll 4
        for (int v = 0; v < 64; v++) {
            float4 a0 = *(const float4*)&Ps[v * 132 + tmg * 8];
            float4 a1 = *(const float4*)&Ps[v * 132 + tmg * 8 + 4];
            float4 b0 = *(const float4*)&Evd[v * 132 + tdg * 8];
            float4 b1 = *(const float4*)&Evd[v * 132 + tdg * 8 + 4];
            ull bb[4] = {pk2(b0.x, b0.y), pk2(b0.z, b0.w), pk2(b1.x, b1.y), pk2(b1.z, b1.w)};
            float av[8] = {a0.x, a0.y, a0.z, a0.w, a1.x, a1.y, a1.z, a1.w};
            #pragma unroll
            for (int i = 0; i < 8; i++) {
                ull ai = pk2(av[i], av[i]);
                fma2(acc[i][0], ai, bb[0]); fma2(acc[i][1], ai, bb[1]);
                fma2(acc[i][2], ai, bb[2]); fma2(acc[i][3], ai, bb[3]);
            }
        }
        __syncthreads();
        {
            int v = t >> 2, dq = (t & 3) * 32;
            const float* src = E + (size_t)(vg + 64 + v) * 128 + dq;
            float* dst = Evd + v * 132 + dq;
            #pragma unroll
            for (int q = 0; q < 8; q++) *(float4*)(dst + q * 4) = *(const float4*)(src + q * 4);
        }
        if (tv8 >= 8) {
            #pragma unroll
            for (int i = 0; i < 8; i++) {
                int m = tm1 * 8 + i;
                float e[8];
                upk(L[i][0], e[0], e[1]); upk(L[i][1], e[2], e[3]);
                upk(L[i][2], e[4], e[5]); upk(L[i][3], e[6], e[7]);
                #pragma unroll
                for (int j = 0; j < 8; j++) Ps[((tv8 - 8) * 8 + j) * 132 + m] = e[j];
            }
        }
        __syncthreads();
        #pragma unroll 4
        for (int v = 0; v < 64; v++) {
            float4 a0 = *(const float4*)&Ps[v * 132 + tmg * 8];
            float4 a1 = *(const float4*)&Ps[v * 132 + tmg * 8 + 4];
            float4 b0 = *(const float4*)&Evd[v * 132 + tdg * 8];
            float4 b1 = *(const float4*)&Evd[v * 132 + tdg * 8 + 4];
            ull bb[4] = {pk2(b0.x, b0.y), pk2(b0.z, b0.w), pk2(b1.x, b1.y), pk2(b1.z, b1.w)};
            float av[8] = {a0.x, a0.y, a0.z, a0.w, a1.x, a1.y, a1.z, a1.w};
            #pragma unroll
            for (int i = 0; i < 8; i++) {
                ull ai = pk2(av[i], av[i]);
                fma2(acc[i][0], ai, bb[0]); fma2(acc[i][1], ai, bb[1]);
                fma2(acc[i][2], ai, bb[2]); fma2(acc[i][3], ai, bb[3]);
            }
        }
    }
    #pragma unroll
    for (int i = 0; i < 8; i++) {
        float f[8];
        upk(acc[i][0], f[0], f[1]); upk(acc[i][1], f[2], f[3]);
        upk(acc[i][2], f[4], f[5]); upk(acc[i][3], f[6], f[7]);
        size_t base = ((size_t)b * 128 + tmg * 8 + i) * 128 + tdg * 8;
        *(float4*)&g_SEpart[base]     = make_float4(f[0], f[1], f[2], f[3]);
        *(float4*)&g_SEpart[base + 4] = make_float4(f[4], f[5], f[6], f[7]);
    }
    __syncthreads();
    float* red = Etd;
    #pragma unroll
    for (int i = 0; i < 8; i++) red[(tm1 * 8 + i) * 17 + tv8] = psum[i];
    __syncthreads();
    if (t < 128) {
        float s = 0.f;
        #pragma unroll
        for (int q = 0; q < 16; q++) s += red[t * 17 + q];
        g_SEsum[b * 128 + t] = s;
    }
}

// ==================== final out = qz @ E^T ====================
__global__ void __launch_bounds__(256) k_msg(const float* __restrict__ E, float* __restrict__ out) {
    __shared__ float As[8][128], Bs[8][128];
    int t = threadIdx.x;
    int m0 = blockIdx.y * 128, n0 = blockIdx.x * 128;
    int row = t >> 1, kq = (t & 1) * 4;
    int tm = t >> 4, tn = t & 15;
    ull acc[8][4];
    #pragma unroll
    for (int i = 0; i < 8; i++)
        #pragma unroll
        for (int q = 0; q < 4; q++) acc[i][q] = pk2(0.f, 0.f);
    for (int s = 0; s < 16; s++) {
        int k0 = s * 8;
        float4 av = *(const float4*)&g_qz[(m0 + row) * 128 + k0 + kq];
        float4 bv = *(const float4*)&E[(size_t)(n0 + row) * 128 + k0 + kq];
        __syncthreads();
        As[kq][row] = av.x; As[kq + 1][row] = av.y; As[kq + 2][row] = av.z; As[kq + 3][row] = av.w;
        Bs[kq][row] = bv.x; Bs[kq + 1][row] = bv.y; Bs[kq + 2][row] = bv.z; Bs[kq + 3][row] = bv.w;
        __syncthreads();
        #pragma unroll
        for (int p = 0; p < 8; p++) {
            float4 a0 = *(const float4*)&As[p][tm * 8], a1 = *(const float4*)&As[p][tm * 8 + 4];
            float4 b0 = *(const float4*)&Bs[p][tn * 8], b1 = *(const float4*)&Bs[p][tn * 8 + 4];
            ull bb[4] = {pk2(b0.x, b0.y), pk2(b0.z, b0.w), pk2(b1.x, b1.y), pk2(b1.z, b1.w)};
            float avv[8] = {a0.x, a0.y, a0.z, a0.w, a1.x, a1.y, a1.z, a1.w};
            #pragma unroll
            for (int i = 0; i < 8; i++) {
                ull ai = pk2(avv[i], avv[i]);
                fma2(acc[i][0], ai, bb[0]); fma2(acc[i][1], ai, bb[1]);
                fma2(acc[i][2], ai, bb[2]); fma2(acc[i][3], ai, bb[3]);
            }
        }
    }
    #pragma unroll
    for (int i = 0; i < 8; i++) {
        float f[8];
        upk(acc[i][0], f[0], f[1]); upk(acc[i][1], f[2], f[3]);
        upk(acc[i][2], f[4], f[5]); upk(acc[i][3], f[6], f[7]);
        size_t base = (size_t)(m0 + tm * 8 + i) * 32000 + n0 + tn * 8;
        *(float4*)&out[base] = make_float4(f[0], f[1], f[2], f[3]);
        *(float4*)&out[base + 4] = make_float4(f[4], f[5], f[6], f[7]);
    }
}

// ==================== launch ====================
extern "C" void kernel_launch(void* const* d_in, const int* in_sizes, int n_in,
                              void* d_out, int out_size) {
    const float* x    = (const float*)d_in[0];
    const int*   mask = (const int*)d_in[1];
    const float* E    = (const float*)d_in[2];
    const int*   mm   = (const int*)d_in[3];
    const float* T    = (const float*)d_in[4];
    float* out = (float*)d_out;

    static cudaStream_t s2 = nullptr;
    static cudaEvent_t eF = nullptr, eJ = nullptr;
    if (!s2) {
        cudaStreamCreate(&s2);
        cudaEventCreateWithFlags(&eF, cudaEventDisableTiming);
        cudaEventCreateWithFlags(&eJ, cudaEventDisableTiming);
        cudaFuncSetAttribute(k_sef, cudaFuncAttributeMaxDynamicSharedMemorySize, SEF_SMEM);
    }
    cudaStream_t s0 = 0;

    cudaEventRecord(eF, s0);
    cudaStreamWaitEvent(s2, eF, 0);
    k_transE<<<dim3(250, 4), 256, 0, s2>>>(E);

    k_emean_part<<<64, 256, 0, s0>>>(E);
    k_emean_red<<<1, 128, 0, s0>>>();
    k_bmat<<<2048, 256, 0, s0>>>(T);
    k_midx<<<1, 512, 0, s0>>>(mask, mm);
    k_init_qz<<<512, 128, 0, s0>>>(x, mask, mm);

    for (int it = 0; it < 4; it++) {
        k_nn64<<<dim3(16, 8, 2), 256, 0, s0>>>(T, 0);
        k_F<<<512, 256, 0, s0>>>(mask);
        k_trq<<<dim3(32, 16), 256, 0, s0>>>();
        k_S<<<512, 256, 0, s0>>>();
        k_nn64<<<dim3(2, 8, 8), 256, 0, s0>>>(T, 1);
        if (it > 0) cudaStreamWaitEvent(s0, eJ, 0);
        k_zupd<<<512, 128, 0, s0>>>(x, mask, mm, it > 0);
        if (it < 3) {
            cudaEventRecord(eF, s0);
            cudaStreamWaitEvent(s2, eF, 0);
            k_sef<<<148, 256, SEF_SMEM, s2>>>(E);
            k_sered<<<512, 128, 0, s2>>>();
            cudaEventRecord(eJ, s2);
        } else {
            k_msg<<<dim3(250, 4), 256, 0, s0>>>(E, out);
        }
    }
}

// round 13
// speedup vs baseline: 1.1185x; 1.0098x over previous
#include <cuda_runtime.h>
#include <cuda_bf16.h>
#include <math.h>
#include <stdint.h>

#define NEGC 1.0e9f
typedef unsigned long long ull;

// ==================== static scratch ====================
__device__ float g_epart[64 * 128];
__device__ float g_emean[128];
__device__ float g_Bmat[4096 * 128];
__device__ float g_qz[512 * 128];
__device__ float g_U[2 * 512 * 1024];
__device__ float g_qhn[4 * 8 * 128 * 128];
__device__ float g_qhnT[4 * 8 * 128 * 128];
__device__ float g_S[512 * 4096];
__device__ float g_Gpart[8 * 512 * 128];
__device__ float g_ET[128 * 32000];          // E transposed (fp32)
__device__ __nv_bfloat16 g_Ehi[32000 * 128];
__device__ __nv_bfloat16 g_Elo[32000 * 128];
__device__ float g_SEpart[148 * 128 * 128];
__device__ float g_SEsum[148 * 128];
__device__ float g_SE[512 * 128];
__device__ int   g_midx[512];
__device__ int   g_mpos[512];
__device__ int   g_mcount;

// ---- f32x2 helpers ----
__device__ __forceinline__ ull pk2(float lo, float hi) {
    ull r; asm("mov.b64 %0, {%1, %2};" : "=l"(r) : "f"(lo), "f"(hi)); return r;
}
__device__ __forceinline__ void fma2(ull &d, ull a, ull b) {
    asm("fma.rn.f32x2 %0, %1, %2, %3;" : "=l"(d) : "l"(a), "l"(b), "l"(d));
}
__device__ __forceinline__ void upk(ull v, float &lo, float &hi) {
    asm("mov.b64 {%0, %1}, %2;" : "=f"(lo), "=f"(hi) : "l"(v));
}

// ---- bf16 mma.sync (base PTX, fallback HMMA on sm_103) ----
__device__ __forceinline__ void mma16816(float c[4], const uint32_t a[4], const uint32_t b[2]) {
    asm volatile("mma.sync.aligned.m16n8k16.row.col.f32.bf16.bf16.f32 "
        "{%0,%1,%2,%3}, {%4,%5,%6,%7}, {%8,%9}, {%0,%1,%2,%3};"
        : "+f"(c[0]), "+f"(c[1]), "+f"(c[2]), "+f"(c[3])
        : "r"(a[0]), "r"(a[1]), "r"(a[2]), "r"(a[3]), "r"(b[0]), "r"(b[1]));
}

// ---- FMA-pipe exp ----
__device__ __forceinline__ float fexp(float x) {
    float z = x * 1.4426950408889634f;
    float m = z + 12582912.0f;
    int ni = __float_as_int(m) - 0x4B400000;
    float f = z - (m - 12582912.0f);
    float p = 0.0013333558f;
    p = fmaf(p, f, 0.0096181291f);
    p = fmaf(p, f, 0.0555041087f);
    p = fmaf(p, f, 0.2402265070f);
    p = fmaf(p, f, 0.6931471806f);
    p = fmaf(p, f, 1.0f);
    return p * __int_as_float((ni + 127) << 23);
}
__device__ __forceinline__ float fexp_s(float x) { return fexp(fmaxf(x, -80.f)); }

// ==================== setup ====================
__global__ void k_emean_part(const float* __restrict__ E) {
    int b = blockIdx.x, t = threadIdx.x;
    int d = t & 127, h = t >> 7;
    float s = 0.f;
    for (int v = b * 500 + h; v < b * 500 + 500; v += 2) s += E[v * 128 + d];
    __shared__ float sh[256];
    sh[t] = s; __syncthreads();
    if (t < 128) g_epart[b * 128 + t] = sh[t] + sh[t + 128];
}
__global__ void k_emean_red() {
    int t = threadIdx.x;
    float s = 0.f;
    for (int b = 0; b < 64; b++) s += g_epart[b * 128 + t];
    g_emean[t] = s * (1.0f / 32000.0f);
}

__global__ void k_bmat(const float* __restrict__ T) {
    int idx = blockIdx.x * 256 + threadIdx.x;
    if (idx >= 4096 * 128) return;
    int r = idx >> 7, col = idx & 127;
    float val;
    if (r < 2048) {
        int k = r >> 10, c = (r >> 7) & 7, b = r & 127;
        val = T[((k * 128 + col) * 128 + b) * 8 + c];
    } else {
        int r2 = r - 2048;
        int k = r2 >> 10, c = (r2 >> 7) & 7, a = r2 & 127;
        val = T[((k * 128 + a) * 128 + col) * 8 + c];
    }
    g_Bmat[idx] = val;
}

__global__ void k_transE(const float* __restrict__ E) {
    __shared__ float tile[128][33];
    int v0 = blockIdx.x * 128, d0 = blockIdx.y * 32, t = threadIdx.x;
    for (int idx = t; idx < 4096; idx += 256) {
        int r = idx >> 5, c = idx & 31;
        tile[r][c] = E[(size_t)(v0 + r) * 128 + d0 + c];
    }
    __syncthreads();
    for (int idx = t; idx < 4096; idx += 256) {
        int d = idx >> 7, vv = idx & 127;
        g_ET[(size_t)(d0 + d) * 32000 + v0 + vv] = tile[vv][d];
    }
}

// split E rows into bf16 hi/lo. grid 250, 256 thr.
__global__ void k_splitE(const float* __restrict__ E) {
    int v0 = blockIdx.x * 128, t = threadIdx.x;
    int row = t >> 1, half = t & 1;
    const float* src = E + (size_t)(v0 + row) * 128 + half * 64;
    size_t dstoff = (size_t)(v0 + row) * 128 + half * 64;
    #pragma unroll
    for (int q = 0; q < 16; q++) {
        float4 v = *(const float4*)(src + q * 4);
        __nv_bfloat162 h01 = __floats2bfloat162_rn(v.x, v.y);
        __nv_bfloat162 h23 = __floats2bfloat162_rn(v.z, v.w);
        __nv_bfloat162 l01 = __floats2bfloat162_rn(v.x - __bfloat162float(h01.x), v.y - __bfloat162float(h01.y));
        __nv_bfloat162 l23 = __floats2bfloat162_rn(v.z - __bfloat162float(h23.x), v.w - __bfloat162float(h23.y));
        *(__nv_bfloat162*)&g_Ehi[dstoff + q * 4]     = h01;
        *(__nv_bfloat162*)&g_Ehi[dstoff + q * 4 + 2] = h23;
        *(__nv_bfloat162*)&g_Elo[dstoff + q * 4]     = l01;
        *(__nv_bfloat162*)&g_Elo[dstoff + q * 4 + 2] = l23;
    }
}

__global__ void k_midx(const int* __restrict__ mask, const int* __restrict__ mmask) {
    __shared__ int pref[512];
    int t = threadIdx.x;
    int f = (mmask[t] != 0 && mask[t] != 0) ? 1 : 0;
    pref[t] = f;
    __syncthreads();
    for (int o = 1; o < 512; o <<= 1) {
        int v = (t >= o) ? pref[t - o] : 0;
        __syncthreads();
        pref[t] += v;
        __syncthreads();
    }
    if (f) { int pos = pref[t] - 1; g_midx[pos] = t; g_mpos[t] = pos; }
    else g_mpos[t] = -1;
    if (t == 511) g_mcount = pref[511];
}

__device__ __forceinline__ float softmax128(float raw, float* r1, float* r2) {
    int lane = threadIdx.x & 31, w = threadIdx.x >> 5;
    float m = raw;
    #pragma unroll
    for (int o = 16; o; o >>= 1) m = fmaxf(m, __shfl_xor_sync(~0u, m, o));
    if (lane == 0) r1[w] = m;
    __syncthreads();
    m = fmaxf(fmaxf(r1[0], r1[1]), fmaxf(r1[2], r1[3]));
    float e = fexp_s(raw - m), s = e;
    #pragma unroll
    for (int o = 16; o; o >>= 1) s += __shfl_xor_sync(~0u, s, o);
    if (lane == 0) r2[w] = s;
    __syncthreads();
    return e / (r2[0] + r2[1] + r2[2] + r2[3]);
}

__global__ void k_init_qz(const float* __restrict__ x, const int* __restrict__ mask,
                          const int* __restrict__ mmask) {
    int zi = blockIdx.x, a = threadIdx.x;
    __shared__ float r1[4], r2[4];
    float keep = mask[zi] ? 1.f : 0.f;
    float mm = (float)mmask[zi];
    float raw = (x[zi * 128 + a] * (1.f - mm) + g_emean[a] * mm) * keep;
    float p = softmax128(raw, r1, r2);
    g_qz[zi * 128 + a] = p * keep;
}

// ==================== small FFMA GEMMs ====================
__global__ void __launch_bounds__(256) k_nn64(const float* __restrict__ T, int which) {
    const float *A, *B; float *C;
    int lda, ldb, ldc, ksteps, kb;
    if (which == 0) {
        int kk = blockIdx.z;
        A = g_qz; lda = 128; B = T + kk * 131072; ldb = 1024;
        C = g_U + (size_t)kk * 524288; ldc = 1024; ksteps = 8; kb = 0;
    } else {
        int ks = blockIdx.z;
        A = g_S; lda = 4096; B = g_Bmat; ldb = 128;
        C = g_Gpart + (size_t)ks * 65536; ldc = 128; ksteps = 32; kb = ks * 512;
    }
    int m0 = blockIdx.y * 64, n0 = blockIdx.x * 64;
    __shared__ float As[16][68], Bs[16][64];
    int t = threadIdx.x, tm = t >> 4, tn = t & 15;
    ull acc[4][2];
    #pragma unroll
    for (int i = 0; i < 4; i++) { acc[i][0] = pk2(0.f, 0.f); acc[i][1] = pk2(0.f, 0.f); }
    for (int s = 0; s < ksteps; s++) {
        int k0 = kb + s * 16;
        { int r = t >> 2, c4 = (t & 3) * 4;
          float4 av = *(const float4*)&A[(size_t)(m0 + r) * lda + k0 + c4];
          As[c4][r] = av.x; As[c4 + 1][r] = av.y; As[c4 + 2][r] = av.z; As[c4 + 3][r] = av.w; }
        { int r = t >> 4, c4 = (t & 15) * 4;
          *(float4*)&Bs[r][c4] = *(const float4*)&B[(size_t)(k0 + r) * ldb + n0 + c4]; }
        __syncthreads();
        #pragma unroll
        for (int p = 0; p < 16; p++) {
            float4 a = *(const float4*)&As[p][tm * 4];
            float4 b = *(const float4*)&Bs[p][tn * 4];
            ull b01 = pk2(b.x, b.y), b23 = pk2(b.z, b.w);
            ull a0 = pk2(a.x, a.x), a1 = pk2(a.y, a.y), a2 = pk2(a.z, a.z), a3 = pk2(a.w, a.w);
            fma2(acc[0][0], a0, b01); fma2(acc[0][1], a0, b23);
            fma2(acc[1][0], a1, b01); fma2(acc[1][1], a1, b23);
            fma2(acc[2][0], a2, b01); fma2(acc[2][1], a2, b23);
            fma2(acc[3][0], a3, b01); fma2(acc[3][1], a3, b23);
        }
        __syncthreads();
    }
    #pragma unroll
    for (int i = 0; i < 4; i++) {
        float c0, c1, c2, c3;
        upk(acc[i][0], c0, c1); upk(acc[i][1], c2, c3);
        *(float4*)&C[(size_t)(m0 + tm * 4 + i) * ldc + n0 + tn * 4] = make_float4(c0, c1, c2, c3);
    }
}

__global__ void __launch_bounds__(256) k_F(const int* __restrict__ mask) {
    int zi = blockIdx.x, z = zi >> 7, i = zi & 127;
    int t = threadIdx.x;
    __shared__ float U_sh[2][1024];
    __shared__ float qz_sh[32][129];
    __shared__ float qh_sh[8][128];
    __shared__ float smax[8], ssum[8];
    for (int idx = t; idx < 2048; idx += 256) {
        int k = idx >> 10, bc = idx & 1023;
        U_sh[k][bc] = g_U[((size_t)k * 512 + zi) * 1024 + bc];
    }
    int j = t & 127, ch = t >> 7;
    int ksel = (j > i) ? 0 : 1;
    float a0 = 0.f, a1 = 0.f, a2 = 0.f, a3 = 0.f;
    const float* qzb = g_qz + z * 128 * 128;
    for (int b0 = 0; b0 < 128; b0 += 32) {
        __syncthreads();
        #pragma unroll
        for (int e = 0; e < 16; e++) {
            int lin = t + e * 256;
            int jj = lin >> 5, col = lin & 31;
            qz_sh[col][jj] = qzb[jj * 128 + b0 + col];
        }
        __syncthreads();
        #pragma unroll 8
        for (int bb = 0; bb < 32; bb++) {
            float qv = qz_sh[bb][j];
            float4 u4 = *(const float4*)&U_sh[ksel][(b0 + bb) * 8 + ch * 4];
            a0 += qv * u4.x; a1 += qv * u4.y; a2 += qv * u4.z; a3 += qv * u4.w;
        }
    }
    bool vi = mask[z * 128 + i] != 0, vj = mask[z * 128 + j] != 0;
    if (i == j || !vi || !vj) { a0 = a1 = a2 = a3 = -NEGC; }
    qh_sh[ch * 4 + 0][j] = a0; qh_sh[ch * 4 + 1][j] = a1;
    qh_sh[ch * 4 + 2][j] = a2; qh_sh[ch * 4 + 3][j] = a3;
    __syncthreads();
    int w = t >> 5, lane = t & 31;
    float v0 = qh_sh[w][lane], v1 = qh_sh[w][lane + 32];
    float v2 = qh_sh[w][lane + 64], v3 = qh_sh[w][lane + 96];
    float mx = fmaxf(fmaxf(v0, v1), fmaxf(v2, v3));
    #pragma unroll
    for (int o = 16; o; o >>= 1) mx = fmaxf(mx, __shfl_xor_sync(~0u, mx, o));
    float sum = fexp_s(v0 - mx) + fexp_s(v1 - mx) + fexp_s(v2 - mx) + fexp_s(v3 - mx);
    #pragma unroll
    for (int o = 16; o; o >>= 1) sum += __shfl_xor_sync(~0u, sum, o);
    if (lane == 0) { smax[w] = mx; ssum[w] = sum; }
    __syncthreads();
    float vals[4] = {a0, a1, a2, a3};
    #pragma unroll
    for (int hh = 0; hh < 4; hh++) {
        int h = ch * 4 + hh;
        float p = fexp_s(vals[hh] - smax[h]) / ssum[h];
        g_qhn[(((z * 8 + h) * 128 + i) << 7) + j] = p;
    }
}

__global__ void __launch_bounds__(256) k_trq() {
    __shared__ float tile[32][33];
    int zh = blockIdx.x;
    int ti = blockIdx.y >> 2, tj = blockIdx.y & 3;
    int t = threadIdx.x;
    int r = t >> 5, c = t & 31;
    const float* src = g_qhn + ((size_t)zh << 14);
    float* dst = g_qhnT + ((size_t)zh << 14);
    #pragma unroll
    for (int q = 0; q < 4; q++)
        tile[r + q * 8][c] = src[(ti * 32 + r + q * 8) * 128 + tj * 32 + c];
    __syncthreads();
    #pragma unroll
    for (int q = 0; q < 4; q++)
        dst[(tj * 32 + r + q * 8) * 128 + ti * 32 + c] = tile[c][r + q * 8];
}

__global__ void __launch_bounds__(256) k_S() {
    int zi = blockIdx.x, z = zi >> 7, i = zi & 127;
    int t = threadIdx.x;
    __shared__ float wT[128][36];
    __shared__ float qzc[32][128];
    for (int idx = t; idx < 4096; idx += 256) {
        int r = idx >> 7, j = idx & 127;
        float v; bool m;
        if (r < 16) {
            int k = r >> 3, c = r & 7;
            v = g_qhn[(((z * 8 + c) * 128 + i) << 7) + j];
            m = (k == 0) ? (j > i) : (j < i);
        } else {
            int r2 = r - 16, k = r2 >> 3, c = r2 & 7;
            v = g_qhnT[(((z * 8 + c) * 128 + i) << 7) + j];
            m = (k == 0) ? (j < i) : (j > i);
        }
        wT[j][r] = m ? v : 0.f;
    }
    int tm = t >> 5, tn = t & 31;
    ull acc[4][2];
    #pragma unroll
    for (int q = 0; q < 4; q++) { acc[q][0] = pk2(0.f, 0.f); acc[q][1] = pk2(0.f, 0.f); }
    for (int j0 = 0; j0 < 128; j0 += 32) {
        __syncthreads();
        for (int idx = t; idx < 4096; idx += 256) {
            int jl = idx >> 7, b = idx & 127;
            qzc[jl][b] = g_qz[((z * 128) + j0 + jl) * 128 + b];
        }
        __syncthreads();
        #pragma unroll 8
        for (int jl = 0; jl < 32; jl++) {
            float4 wv = *(const float4*)&wT[j0 + jl][tm * 4];
            float4 qv = *(const float4*)&qzc[jl][tn * 4];
            ull q01 = pk2(qv.x, qv.y), q23 = pk2(qv.z, qv.w);
            ull w0 = pk2(wv.x, wv.x), w1 = pk2(wv.y, wv.y), w2 = pk2(wv.z, wv.z), w3 = pk2(wv.w, wv.w);
            fma2(acc[0][0], w0, q01); fma2(acc[0][1], w0, q23);
            fma2(acc[1][0], w1, q01); fma2(acc[1][1], w1, q23);
            fma2(acc[2][0], w2, q01); fma2(acc[2][1], w2, q23);
            fma2(acc[3][0], w3, q01); fma2(acc[3][1], w3, q23);
        }
    }
    #pragma unroll
    for (int q = 0; q < 4; q++) {
        int r = tm * 4 + q;
        int base = (r < 16) ? r * 128 : 2048 + (r - 16) * 128;
        float c0, c1, c2, c3;
        upk(acc[q][0], c0, c1); upk(acc[q][1], c2, c3);
        *(float4*)&g_S[(size_t)zi * 4096 + base + tn * 4] = make_float4(c0, c1, c2, c3);
    }
}

__global__ void k_sered() {
    int count = g_mcount;
    int pos = blockIdx.x;
    if (pos >= count) return;
    int ntiles = (count + 127) >> 7;
    int mt = pos >> 7, row = pos & 127;
    int gb0 = (mt * 148 + ntiles - 1) / ntiles;
    int gb1 = ((mt + 1) * 148 + ntiles - 1) / ntiles;
    int d = threadIdx.x;
    float num = 0.f, den = 0.f;
    for (int bb = gb0; bb < gb1; bb++) {
        num += g_SEpart[((size_t)bb * 128 + row) * 128 + d];
        den += g_SEsum[bb * 128 + row];
    }
    g_SE[pos * 128 + d] = num / den;
}

__global__ void k_zupd(const float* __restrict__ x, const int* __restrict__ mask,
                       const int* __restrict__ mmask, int useSE) {
    int zi = blockIdx.x, d = threadIdx.x;
    __shared__ float r1[4], r2[4];
    float g = 0.f;
    #pragma unroll
    for (int p = 0; p < 8; p++) g += g_Gpart[((size_t)p * 512 + zi) * 128 + d];
    float mm = (float)mmask[zi];
    float se = 0.f;
    if (mm != 0.f) {
        if (useSE) {
            int pos = g_mpos[zi];
            if (pos >= 0) se = g_SE[pos * 128 + d];
        } else se = g_emean[d];
    }
    float raw = x[zi * 128 + d] * (1.f - mm) + se * mm + g;
    float keep = mask[zi] ? 1.f : 0.f;
    float p_ = softmax128(raw, r1, r2);
    g_qz[zi * 128 + d] = p_ * keep;
}

// ==================== fused SE (unchanged from R12) ====================
#define QZT_OFF 0
#define ETD_OFF (128 * 132)
#define EVD_OFF (ETD_OFF + 128 * 132)
#define PS_OFF  (EVD_OFF + 64 * 132)
#define SEF_SMEM ((PS_OFF + 64 * 132) * 4)

__global__ void __launch_bounds__(256) k_sef(const float* __restrict__ E) {
    int count = g_mcount;
    if (count == 0) return;
    int ntiles = (count + 127) >> 7;
    int b = blockIdx.x;
    int mt = (b * ntiles) / 148;
    int gb0 = (mt * 148 + ntiles - 1) / ntiles;
    int gb1 = ((mt + 1) * 148 + ntiles - 1) / ntiles;
    int gsz = gb1 - gb0, li = b - gb0;
    int ustart = (li * 250) / gsz;
    int ucount = ((li + 1) * 250) / gsz - ustart;
    int m0 = mt * 128;

    extern __shared__ float sm[];
    float* qzT = sm + QZT_OFF;
    float* Etd = sm + ETD_OFF;
    float* Evd = sm + EVD_OFF;
    float* Ps  = sm + PS_OFF;
    int t = threadIdx.x;

    {
        int m = t >> 1, d0 = (t & 1) * 64;
        int pos = m0 + m;
        int zi = (pos < count) ? g_midx[pos] : 0;
        const float* src = g_qz + (size_t)zi * 128 + d0;
        #pragma unroll
        for (int q = 0; q < 16; q++) {
            float4 v = *(const float4*)(src + q * 4);
            qzT[(d0 + q * 4 + 0) * 132 + m] = v.x;
            qzT[(d0 + q * 4 + 1) * 132 + m] = v.y;
            qzT[(d0 + q * 4 + 2) * 132 + m] = v.z;
            qzT[(d0 + q * 4 + 3) * 132 + m] = v.w;
        }
    }

    int tm1 = t >> 4, tv8 = t & 15;
    int tmg = t >> 4, tdg = t & 15;
    ull acc[8][4];
    #pragma unroll
    for (int i = 0; i < 8; i++)
        #pragma unroll
        for (int q = 0; q < 4; q++) acc[i][q] = pk2(0.f, 0.f);
    float psum[8];
    #pragma unroll
    for (int i = 0; i < 8; i++) psum[i] = 0.f;

    for (int tile = 0; tile < ucount; tile++) {
        int vg = (ustart + tile) * 128;
        __syncthreads();
        {
            int d = t >> 1, vq = (t & 1) * 64;
            const float* src = g_ET + (size_t)d * 32000 + vg + vq;
            float* dst = Etd + d * 132 + vq;
            #pragma unroll
            for (int q = 0; q < 16; q++) *(float4*)(dst + q * 4) = *(const float4*)(src + q * 4);
        }
        {
            int v = t >> 2, dq = (t & 3) * 32;
            const float* src = E + (size_t)(vg + v) * 128 + dq;
            float* dst = Evd + v * 132 + dq;
            #pragma unroll
            for (int q = 0; q < 8; q++) *(float4*)(dst + q * 4) = *(const float4*)(src + q * 4);
        }
        __syncthreads();
        ull L[8][4];
        #pragma unroll
        for (int i = 0; i < 8; i++)
            #pragma unroll
            for (int q = 0; q < 4; q++) L[i][q] = pk2(0.f, 0.f);
        #pragma unroll 2
        for (int d = 0; d < 128; d++) {
            float4 a0 = *(const float4*)&qzT[d * 132 + tm1 * 8];
            float4 a1 = *(const float4*)&qzT[d * 132 + tm1 * 8 + 4];
            float4 b0 = *(const float4*)&Etd[d * 132 + tv8 * 8];
            float4 b1 = *(const float4*)&Etd[d * 132 + tv8 * 8 + 4];
            ull bb[4] = {pk2(b0.x, b0.y), pk2(b0.z, b0.w), pk2(b1.x, b1.y), pk2(b1.z, b1.w)};
            float av[8] = {a0.x, a0.y, a0.z, a0.w, a1.x, a1.y, a1.z, a1.w};
            #pragma unroll
            for (int i = 0; i < 8; i++) {
                ull ai = pk2(av[i], av[i]);
                fma2(L[i][0], ai, bb[0]); fma2(L[i][1], ai, bb[1]);
                fma2(L[i][2], ai, bb[2]); fma2(L[i][3], ai, bb[3]);
            }
        }
        #pragma unroll
        for (int i = 0; i < 8; i++)
            #pragma unroll
            for (int q = 0; q < 4; q++) {
                float e0, e1;
                upk(L[i][q], e0, e1);
                e0 = fexp(e0); e1 = fexp(e1);
                psum[i] += e0 + e1;
                L[i][q] = pk2(e0, e1);
            }
        if (tv8 < 8) {
            #pragma unroll
            for (int i = 0; i < 8; i++) {
                int m = tm1 * 8 + i;
                float e[8];
                upk(L[i][0], e[0], e[1]); upk(L[i][1], e[2], e[3]);
                upk(L[i][2], e[4], e[5]); upk(L[i][3], e[6], e[7]);
                #pragma unroll
                for (int j = 0; j < 8; j++) Ps[(tv8 * 8 + j) * 132 + m] = e[j];
            }
        }
        __syncthreads();
        #pragma unroll 4
        for (int v = 0; v < 64; v++) {
            float4 a0 = *(const float4*)&Ps[v * 132 + tmg * 8];
            float4 a1 = *(const float4*)&Ps[v * 132 + tmg * 8 + 4];
            float4 b0 = *(const float4*)&Evd[v * 132 + tdg * 8];
            float4 b1 = *(const float4*)&Evd[v * 132 + tdg * 8 + 4];
            ull bb[4] = {pk2(b0.x, b0.y), pk2(b0.z, b0.w), pk2(b1.x, b1.y), pk2(b1.z, b1.w)};
            float av[8] = {a0.x, a0.y, a0.z, a0.w, a1.x, a1.y, a1.z, a1.w};
            #pragma unroll
            for (int i = 0; i < 8; i++) {
                ull ai = pk2(av[i], av[i]);
                fma2(acc[i][0], ai, bb[0]); fma2(acc[i][1], ai, bb[1]);
                fma2(acc[i][2], ai, bb[2]); fma2(acc[i][3], ai, bb[3]);
            }
        }
        __syncthreads();
        {
            int v = t >> 2, dq = (t & 3) * 32;
            const float* src = E + (size_t)(vg + 64 + v) * 128 + dq;
            float* dst = Evd + v * 132 + dq;
            #pragma unroll
            for (int q = 0; q < 8; q++) *(float4*)(dst + q * 4) = *(const float4*)(src + q * 4);
        }
        if (tv8 >= 8) {
            #pragma unroll
            for (int i = 0; i < 8; i++) {
                int m = tm1 * 8 + i;
                float e[8];
                upk(L[i][0], e[0], e[1]); upk(L[i][1], e[2], e[3]);
                upk(L[i][2], e[4], e[5]); upk(L[i][3], e[6], e[7]);
                #pragma unroll
                for (int j = 0; j < 8; j++) Ps[((tv8 - 8) * 8 + j) * 132 + m] = e[j];
            }
        }
        __syncthreads();
        #pragma unroll 4
        for (int v = 0; v < 64; v++) {
            float4 a0 = *(const float4*)&Ps[v * 132 + tmg * 8];
            float4 a1 = *(const float4*)&Ps[v * 132 + tmg * 8 + 4];
            float4 b0 = *(const float4*)&Evd[v * 132 + tdg * 8];
            float4 b1 = *(const float4*)&Evd[v * 132 + tdg * 8 + 4];
            ull bb[4] = {pk2(b0.x, b0.y), pk2(b0.z, b0.w), pk2(b1.x, b1.y), pk2(b1.z, b1.w)};
            float av[8] = {a0.x, a0.y, a0.z, a0.w, a1.x, a1.y, a1.z, a1.w};
            #pragma unroll
            for (int i = 0; i < 8; i++) {
                ull ai = pk2(av[i], av[i]);
                fma2(acc[i][0], ai, bb[0]); fma2(acc[i][1], ai, bb[1]);
                fma2(acc[i][2], ai, bb[2]); fma2(acc[i][3], ai, bb[3]);
            }
        }
    }
    #pragma unroll
    for (int i = 0; i < 8; i++) {
        float f[8];
        upk(acc[i][0], f[0], f[1]); upk(acc[i][1], f[2], f[3]);
        upk(acc[i][2], f[4], f[5]); upk(acc[i][3], f[6], f[7]);
        size_t base = ((size_t)b * 128 + tmg * 8 + i) * 128 + tdg * 8;
        *(float4*)&g_SEpart[base]     = make_float4(f[0], f[1], f[2], f[3]);
        *(float4*)&g_SEpart[base + 4] = make_float4(f[4], f[5], f[6], f[7]);
    }
    __syncthreads();
    float* red = Etd;
    #pragma unroll
    for (int i = 0; i < 8; i++) red[(tm1 * 8 + i) * 17 + tv8] = psum[i];
    __syncthreads();
    if (t < 128) {
        float s = 0.f;
        #pragma unroll
        for (int q = 0; q < 16; q++) s += red[t * 17 + q];
        g_SEsum[b * 128 + t] = s;
    }
}

// ==================== final out = qz @ E^T via mma.sync bf16 3-term ====================
#define MH_S 136                              // bf16 row stride (272B: 4-bank rotation)
#define MH_AH 0
#define MH_AL (128 * MH_S)
#define MH_BH (2 * 128 * MH_S)
#define MH_BL (3 * 128 * MH_S)
#define MH_SMEM (4 * 128 * MH_S * 2)

__global__ void __launch_bounds__(256) k_msg_h(float* __restrict__ out) {
    extern __shared__ __nv_bfloat16 smh[];
    __nv_bfloat16* Ah = smh + MH_AH;
    __nv_bfloat16* Al = smh + MH_AL;
    __nv_bfloat16* Bh = smh + MH_BH;
    __nv_bfloat16* Bl = smh + MH_BL;
    int t = threadIdx.x;
    int v0 = blockIdx.x * 128, m0 = blockIdx.y * 128;
    // load + split A (qz)
    {
        int row = t >> 1, half = t & 1;
        const float* src = g_qz + (size_t)(m0 + row) * 128 + half * 64;
        int dof = row * MH_S + half * 64;
        #pragma unroll
        for (int q = 0; q < 16; q++) {
            float4 v = *(const float4*)(src + q * 4);
            __nv_bfloat162 h01 = __floats2bfloat162_rn(v.x, v.y);
            __nv_bfloat162 h23 = __floats2bfloat162_rn(v.z, v.w);
            __nv_bfloat162 l01 = __floats2bfloat162_rn(v.x - __bfloat162float(h01.x), v.y - __bfloat162float(h01.y));
            __nv_bfloat162 l23 = __floats2bfloat162_rn(v.z - __bfloat162float(h23.x), v.w - __bfloat162float(h23.y));
            *(__nv_bfloat162*)&Ah[dof + q * 4]     = h01;
            *(__nv_bfloat162*)&Ah[dof + q * 4 + 2] = h23;
            *(__nv_bfloat162*)&Al[dof + q * 4]     = l01;
            *(__nv_bfloat162*)&Al[dof + q * 4 + 2] = l23;
        }
    }
    // load B (pre-split E)
    {
        int row = t >> 1, half = t & 1;
        size_t soff = (size_t)(v0 + row) * 128 + half * 64;
        int dof = row * MH_S + half * 64;
        #pragma unroll
        for (int q = 0; q < 8; q++) {
            *(uint4*)&Bh[dof + q * 8] = *(const uint4*)&g_Ehi[soff + q * 8];
            *(uint4*)&Bl[dof + q * 8] = *(const uint4*)&g_Elo[soff + q * 8];
        }
    }
    __syncthreads();

    int lane = t & 31, warp = t >> 5;
    int wy = warp >> 1, wx = warp & 1;            // 4m x 2v warp grid
    int g = lane >> 2, tig = lane & 3;
    float c[16][4];
    #pragma unroll
    for (int i = 0; i < 16; i++)
        #pragma unroll
        for (int q = 0; q < 4; q++) c[i][q] = 0.f;

    #pragma unroll
    for (int ks = 0; ks < 8; ks++) {
        int k0 = ks * 16;
        uint32_t aH[2][4], aL[2][4];
        #pragma unroll
        for (int mt = 0; mt < 2; mt++) {
            int base = (wy * 32 + mt * 16 + g) * MH_S + k0;
            aH[mt][0] = *(uint32_t*)&Ah[base + tig * 2];
            aH[mt][1] = *(uint32_t*)&Ah[base + 8 * MH_S + tig * 2];
            aH[mt][2] = *(uint32_t*)&Ah[base + tig * 2 + 8];
            aH[mt][3] = *(uint32_t*)&Ah[base + 8 * MH_S + tig * 2 + 8];
            aL[mt][0] = *(uint32_t*)&Al[base + tig * 2];
            aL[mt][1] = *(uint32_t*)&Al[base + 8 * MH_S + tig * 2];
            aL[mt][2] = *(uint32_t*)&Al[base + tig * 2 + 8];
            aL[mt][3] = *(uint32_t*)&Al[base + 8 * MH_S + tig * 2 + 8];
        }
        uint32_t bH[8][2], bL[8][2];
        #pragma unroll
        for (int vt = 0; vt < 8; vt++) {
            int base = (wx * 64 + vt * 8 + g) * MH_S + k0;
            bH[vt][0] = *(uint32_t*)&Bh[base + tig * 2];
            bH[vt][1] = *(uint32_t*)&Bh[base + tig * 2 + 8];
            bL[vt][0] = *(uint32_t*)&Bl[base + tig * 2];
            bL[vt][1] = *(uint32_t*)&Bl[base + tig * 2 + 8];
        }
        #pragma unroll
        for (int mt = 0; mt < 2; mt++)
            #pragma unroll
            for (int vt = 0; vt < 8; vt++) {
                int idx = mt * 8 + vt;
                mma16816(c[idx], aH[mt], bH[vt]);
                mma16816(c[idx], aH[mt], bL[vt]);
                mma16816(c[idx], aL[mt], bH[vt]);
            }
    }
    // epilogue
    #pragma unroll
    for (int mt = 0; mt < 2; mt++)
        #pragma unroll
        for (int vt = 0; vt < 8; vt++) {
            int idx = mt * 8 + vt;
            int r0 = m0 + wy * 32 + mt * 16 + g;
            int cc = v0 + wx * 64 + vt * 8 + tig * 2;
            *(float2*)&out[(size_t)r0 * 32000 + cc]       = make_float2(c[idx][0], c[idx][1]);
            *(float2*)&out[(size_t)(r0 + 8) * 32000 + cc] = make_float2(c[idx][2], c[idx][3]);
        }
}

// ==================== launch ====================
extern "C" void kernel_launch(void* const* d_in, const int* in_sizes, int n_in,
                              void* d_out, int out_size) {
    const float* x    = (const float*)d_in[0];
    const int*   mask = (const int*)d_in[1];
    const float* E    = (const float*)d_in[2];
    const int*   mm   = (const int*)d_in[3];
    const float* T    = (const float*)d_in[4];
    float* out = (float*)d_out;

    static cudaStream_t s2 = nullptr;
    static cudaEvent_t eF = nullptr, eJ = nullptr;
    if (!s2) {
        cudaStreamCreate(&s2);
        cudaEventCreateWithFlags(&eF, cudaEventDisableTiming);
        cudaEventCreateWithFlags(&eJ, cudaEventDisableTiming);
        cudaFuncSetAttribute(k_sef, cudaFuncAttributeMaxDynamicSharedMemorySize, SEF_SMEM);
        cudaFuncSetAttribute(k_msg_h, cudaFuncAttributeMaxDynamicSharedMemorySize, MH_SMEM);
    }
    cudaStream_t s0 = 0;

    cudaEventRecord(eF, s0);
    cudaStreamWaitEvent(s2, eF, 0);
    k_transE<<<dim3(250, 4), 256, 0, s2>>>(E);
    k_splitE<<<250, 256, 0, s2>>>(E);

    k_emean_part<<<64, 256, 0, s0>>>(E);
    k_emean_red<<<1, 128, 0, s0>>>();
    k_bmat<<<2048, 256, 0, s0>>>(T);
    k_midx<<<1, 512, 0, s0>>>(mask, mm);
    k_init_qz<<<512, 128, 0, s0>>>(x, mask, mm);

    for (int it = 0; it < 4; it++) {
        k_nn64<<<dim3(16, 8, 2), 256, 0, s0>>>(T, 0);
        k_F<<<512, 256, 0, s0>>>(mask);
        k_trq<<<dim3(32, 16), 256, 0, s0>>>();
        k_S<<<512, 256, 0, s0>>>();
        k_nn64<<<dim3(2, 8, 8), 256, 0, s0>>>(T, 1);
        if (it > 0) cudaStreamWaitEvent(s0, eJ, 0);
        k_zupd<<<512, 128, 0, s0>>>(x, mask, mm, it > 0);
        if (it < 3) {
            cudaEventRecord(eF, s0);
            cudaStreamWaitEvent(s2, eF, 0);
            k_sef<<<148, 256, SEF_SMEM, s2>>>(E);
            k_sered<<<512, 128, 0, s2>>>();
            cudaEventRecord(eJ, s2);
        } else {
            cudaEventRecord(eF, s0);          // k_msg_h needs g_Ehi/g_Elo from s2 setup
            cudaStreamWaitEvent(s0, eF, 0);
            k_msg_h<<<dim3(250, 4), 256, MH_SMEM, s0>>>(out);
        }
    }
}

// round 14
// speedup vs baseline: 1.4863x; 1.3288x over previous
#include <cuda_runtime.h>
#include <cuda_bf16.h>
#include <math.h>
#include <stdint.h>

#define NEGC 1.0e9f
typedef unsigned long long ull;

// ==================== static scratch ====================
__device__ float g_epart[64 * 128];
__device__ float g_emean[128];
__device__ float g_Bmat[4096 * 128];
__device__ float g_qz[512 * 128];
__device__ float g_U[2 * 512 * 1024];
__device__ float g_qhn[4 * 8 * 128 * 128];
__device__ float g_qhnT[4 * 8 * 128 * 128];
__device__ float g_S[512 * 4096];
__device__ float g_Gpart[8 * 512 * 128];
__device__ __nv_bfloat16 g_Ehi[32000 * 128];
__device__ __nv_bfloat16 g_Elo[32000 * 128];
__device__ __nv_bfloat16 g_EThi[128 * 32000];
__device__ __nv_bfloat16 g_ETlo[128 * 32000];
__device__ float g_SEpart[148 * 128 * 128];
__device__ float g_SEsum[148 * 128];
__device__ float g_SE[512 * 128];
__device__ int   g_midx[512];
__device__ int   g_mpos[512];
__device__ int   g_mcount;

// ---- f32x2 helpers ----
__device__ __forceinline__ ull pk2(float lo, float hi) {
    ull r; asm("mov.b64 %0, {%1, %2};" : "=l"(r) : "f"(lo), "f"(hi)); return r;
}
__device__ __forceinline__ void fma2(ull &d, ull a, ull b) {
    asm("fma.rn.f32x2 %0, %1, %2, %3;" : "=l"(d) : "l"(a), "l"(b), "l"(d));
}
__device__ __forceinline__ void upk(ull v, float &lo, float &hi) {
    asm("mov.b64 {%0, %1}, %2;" : "=f"(lo), "=f"(hi) : "l"(v));
}

// ---- bf16 mma.sync ----
__device__ __forceinline__ void mma16816(float c[4], const uint32_t a[4], const uint32_t b[2]) {
    asm volatile("mma.sync.aligned.m16n8k16.row.col.f32.bf16.bf16.f32 "
        "{%0,%1,%2,%3}, {%4,%5,%6,%7}, {%8,%9}, {%0,%1,%2,%3};"
        : "+f"(c[0]), "+f"(c[1]), "+f"(c[2]), "+f"(c[3])
        : "r"(a[0]), "r"(a[1]), "r"(a[2]), "r"(a[3]), "r"(b[0]), "r"(b[1]));
}

// ---- FMA-pipe exp ----
__device__ __forceinline__ float fexp(float x) {
    float z = x * 1.4426950408889634f;
    float m = z + 12582912.0f;
    int ni = __float_as_int(m) - 0x4B400000;
    float f = z - (m - 12582912.0f);
    float p = 0.0013333558f;
    p = fmaf(p, f, 0.0096181291f);
    p = fmaf(p, f, 0.0555041087f);
    p = fmaf(p, f, 0.2402265070f);
    p = fmaf(p, f, 0.6931471806f);
    p = fmaf(p, f, 1.0f);
    return p * __int_as_float((ni + 127) << 23);
}
__device__ __forceinline__ float fexp_s(float x) { return fexp(fmaxf(x, -80.f)); }

// ==================== setup ====================
__global__ void k_emean_part(const float* __restrict__ E) {
    int b = blockIdx.x, t = threadIdx.x;
    int d = t & 127, h = t >> 7;
    float s = 0.f;
    for (int v = b * 500 + h; v < b * 500 + 500; v += 2) s += E[v * 128 + d];
    __shared__ float sh[256];
    sh[t] = s; __syncthreads();
    if (t < 128) g_epart[b * 128 + t] = sh[t] + sh[t + 128];
}
__global__ void k_emean_red() {
    int t = threadIdx.x;
    float s = 0.f;
    for (int b = 0; b < 64; b++) s += g_epart[b * 128 + t];
    g_emean[t] = s * (1.0f / 32000.0f);
}

__global__ void k_bmat(const float* __restrict__ T) {
    int idx = blockIdx.x * 256 + threadIdx.x;
    if (idx >= 4096 * 128) return;
    int r = idx >> 7, col = idx & 127;
    float val;
    if (r < 2048) {
        int k = r >> 10, c = (r >> 7) & 7, b = r & 127;
        val = T[((k * 128 + col) * 128 + b) * 8 + c];
    } else {
        int r2 = r - 2048;
        int k = r2 >> 10, c = (r2 >> 7) & 7, a = r2 & 127;
        val = T[((k * 128 + a) * 128 + col) * 8 + c];
    }
    g_Bmat[idx] = val;
}

// transpose E -> ET bf16 hi/lo
__global__ void k_transE(const float* __restrict__ E) {
    __shared__ float tile[128][33];
    int v0 = blockIdx.x * 128, d0 = blockIdx.y * 32, t = threadIdx.x;
    for (int idx = t; idx < 4096; idx += 256) {
        int r = idx >> 5, c = idx & 31;
        tile[r][c] = E[(size_t)(v0 + r) * 128 + d0 + c];
    }
    __syncthreads();
    for (int idx = t; idx < 4096; idx += 256) {
        int d = idx >> 7, vv = idx & 127;
        float x = tile[vv][d];
        __nv_bfloat16 h = __float2bfloat16(x);
        g_EThi[(size_t)(d0 + d) * 32000 + v0 + vv] = h;
        g_ETlo[(size_t)(d0 + d) * 32000 + v0 + vv] = __float2bfloat16(x - __bfloat162float(h));
    }
}

// split E rows into bf16 hi/lo
__global__ void k_splitE(const float* __restrict__ E) {
    int v0 = blockIdx.x * 128, t = threadIdx.x;
    int row = t >> 1, half = t & 1;
    const float* src = E + (size_t)(v0 + row) * 128 + half * 64;
    size_t dstoff = (size_t)(v0 + row) * 128 + half * 64;
    #pragma unroll
    for (int q = 0; q < 16; q++) {
        float4 v = *(const float4*)(src + q * 4);
        __nv_bfloat162 h01 = __floats2bfloat162_rn(v.x, v.y);
        __nv_bfloat162 h23 = __floats2bfloat162_rn(v.z, v.w);
        __nv_bfloat162 l01 = __floats2bfloat162_rn(v.x - __bfloat162float(h01.x), v.y - __bfloat162float(h01.y));
        __nv_bfloat162 l23 = __floats2bfloat162_rn(v.z - __bfloat162float(h23.x), v.w - __bfloat162float(h23.y));
        *(__nv_bfloat162*)&g_Ehi[dstoff + q * 4]     = h01;
        *(__nv_bfloat162*)&g_Ehi[dstoff + q * 4 + 2] = h23;
        *(__nv_bfloat162*)&g_Elo[dstoff + q * 4]     = l01;
        *(__nv_bfloat162*)&g_Elo[dstoff + q * 4 + 2] = l23;
    }
}

__global__ void k_midx(const int* __restrict__ mask, const int* __restrict__ mmask) {
    __shared__ int pref[512];
    int t = threadIdx.x;
    int f = (mmask[t] != 0 && mask[t] != 0) ? 1 : 0;
    pref[t] = f;
    __syncthreads();
    for (int o = 1; o < 512; o <<= 1) {
        int v = (t >= o) ? pref[t - o] : 0;
        __syncthreads();
        pref[t] += v;
        __syncthreads();
    }
    if (f) { int pos = pref[t] - 1; g_midx[pos] = t; g_mpos[t] = pos; }
    else g_mpos[t] = -1;
    if (t == 511) g_mcount = pref[511];
}

__device__ __forceinline__ float softmax128(float raw, float* r1, float* r2) {
    int lane = threadIdx.x & 31, w = threadIdx.x >> 5;
    float m = raw;
    #pragma unroll
    for (int o = 16; o; o >>= 1) m = fmaxf(m, __shfl_xor_sync(~0u, m, o));
    if (lane == 0) r1[w] = m;
    __syncthreads();
    m = fmaxf(fmaxf(r1[0], r1[1]), fmaxf(r1[2], r1[3]));
    float e = fexp_s(raw - m), s = e;
    #pragma unroll
    for (int o = 16; o; o >>= 1) s += __shfl_xor_sync(~0u, s, o);
    if (lane == 0) r2[w] = s;
    __syncthreads();
    return e / (r2[0] + r2[1] + r2[2] + r2[3]);
}

__global__ void k_init_qz(const float* __restrict__ x, const int* __restrict__ mask,
                          const int* __restrict__ mmask) {
    int zi = blockIdx.x, a = threadIdx.x;
    __shared__ float r1[4], r2[4];
    float keep = mask[zi] ? 1.f : 0.f;
    float mm = (float)mmask[zi];
    float raw = (x[zi * 128 + a] * (1.f - mm) + g_emean[a] * mm) * keep;
    float p = softmax128(raw, r1, r2);
    g_qz[zi * 128 + a] = p * keep;
}

// ==================== small FFMA GEMMs (unchanged) ====================
__global__ void __launch_bounds__(256) k_nn64(const float* __restrict__ T, int which) {
    const float *A, *B; float *C;
    int lda, ldb, ldc, ksteps, kb;
    if (which == 0) {
        int kk = blockIdx.z;
        A = g_qz; lda = 128; B = T + kk * 131072; ldb = 1024;
        C = g_U + (size_t)kk * 524288; ldc = 1024; ksteps = 8; kb = 0;
    } else {
        int ks = blockIdx.z;
        A = g_S; lda = 4096; B = g_Bmat; ldb = 128;
        C = g_Gpart + (size_t)ks * 65536; ldc = 128; ksteps = 32; kb = ks * 512;
    }
    int m0 = blockIdx.y * 64, n0 = blockIdx.x * 64;
    __shared__ float As[16][68], Bs[16][64];
    int t = threadIdx.x, tm = t >> 4, tn = t & 15;
    ull acc[4][2];
    #pragma unroll
    for (int i = 0; i < 4; i++) { acc[i][0] = pk2(0.f, 0.f); acc[i][1] = pk2(0.f, 0.f); }
    for (int s = 0; s < ksteps; s++) {
        int k0 = kb + s * 16;
        { int r = t >> 2, c4 = (t & 3) * 4;
          float4 av = *(const float4*)&A[(size_t)(m0 + r) * lda + k0 + c4];
          As[c4][r] = av.x; As[c4 + 1][r] = av.y; As[c4 + 2][r] = av.z; As[c4 + 3][r] = av.w; }
        { int r = t >> 4, c4 = (t & 15) * 4;
          *(float4*)&Bs[r][c4] = *(const float4*)&B[(size_t)(k0 + r) * ldb + n0 + c4]; }
        __syncthreads();
        #pragma unroll
        for (int p = 0; p < 16; p++) {
            float4 a = *(const float4*)&As[p][tm * 4];
            float4 b = *(const float4*)&Bs[p][tn * 4];
            ull b01 = pk2(b.x, b.y), b23 = pk2(b.z, b.w);
            ull a0 = pk2(a.x, a.x), a1 = pk2(a.y, a.y), a2 = pk2(a.z, a.z), a3 = pk2(a.w, a.w);
            fma2(acc[0][0], a0, b01); fma2(acc[0][1], a0, b23);
            fma2(acc[1][0], a1, b01); fma2(acc[1][1], a1, b23);
            fma2(acc[2][0], a2, b01); fma2(acc[2][1], a2, b23);
            fma2(acc[3][0], a3, b01); fma2(acc[3][1], a3, b23);
        }
        __syncthreads();
    }
    #pragma unroll
    for (int i = 0; i < 4; i++) {
        float c0, c1, c2, c3;
        upk(acc[i][0], c0, c1); upk(acc[i][1], c2, c3);
        *(float4*)&C[(size_t)(m0 + tm * 4 + i) * ldc + n0 + tn * 4] = make_float4(c0, c1, c2, c3);
    }
}

__global__ void __launch_bounds__(256) k_F(const int* __restrict__ mask) {
    int zi = blockIdx.x, z = zi >> 7, i = zi & 127;
    int t = threadIdx.x;
    __shared__ float U_sh[2][1024];
    __shared__ float qz_sh[32][129];
    __shared__ float qh_sh[8][128];
    __shared__ float smax[8], ssum[8];
    for (int idx = t; idx < 2048; idx += 256) {
        int k = idx >> 10, bc = idx & 1023;
        U_sh[k][bc] = g_U[((size_t)k * 512 + zi) * 1024 + bc];
    }
    int j = t & 127, ch = t >> 7;
    int ksel = (j > i) ? 0 : 1;
    float a0 = 0.f, a1 = 0.f, a2 = 0.f, a3 = 0.f;
    const float* qzb = g_qz + z * 128 * 128;
    for (int b0 = 0; b0 < 128; b0 += 32) {
        __syncthreads();
        #pragma unroll
        for (int e = 0; e < 16; e++) {
            int lin = t + e * 256;
            int jj = lin >> 5, col = lin & 31;
            qz_sh[col][jj] = qzb[jj * 128 + b0 + col];
        }
        __syncthreads();
        #pragma unroll 8
        for (int bb = 0; bb < 32; bb++) {
            float qv = qz_sh[bb][j];
            float4 u4 = *(const float4*)&U_sh[ksel][(b0 + bb) * 8 + ch * 4];
            a0 += qv * u4.x; a1 += qv * u4.y; a2 += qv * u4.z; a3 += qv * u4.w;
        }
    }
    bool vi = mask[z * 128 + i] != 0, vj = mask[z * 128 + j] != 0;
    if (i == j || !vi || !vj) { a0 = a1 = a2 = a3 = -NEGC; }
    qh_sh[ch * 4 + 0][j] = a0; qh_sh[ch * 4 + 1][j] = a1;
    qh_sh[ch * 4 + 2][j] = a2; qh_sh[ch * 4 + 3][j] = a3;
    __syncthreads();
    int w = t >> 5, lane = t & 31;
    float v0 = qh_sh[w][lane], v1 = qh_sh[w][lane + 32];
    float v2 = qh_sh[w][lane + 64], v3 = qh_sh[w][lane + 96];
    float mx = fmaxf(fmaxf(v0, v1), fmaxf(v2, v3));
    #pragma unroll
    for (int o = 16; o; o >>= 1) mx = fmaxf(mx, __shfl_xor_sync(~0u, mx, o));
    float sum = fexp_s(v0 - mx) + fexp_s(v1 - mx) + fexp_s(v2 - mx) + fexp_s(v3 - mx);
    #pragma unroll
    for (int o = 16; o; o >>= 1) sum += __shfl_xor_sync(~0u, sum, o);
    if (lane == 0) { smax[w] = mx; ssum[w] = sum; }
    __syncthreads();
    float vals[4] = {a0, a1, a2, a3};
    #pragma unroll
    for (int hh = 0; hh < 4; hh++) {
        int h = ch * 4 + hh;
        float p = fexp_s(vals[hh] - smax[h]) / ssum[h];
        g_qhn[(((z * 8 + h) * 128 + i) << 7) + j] = p;
    }
}

__global__ void __launch_bounds__(256) k_trq() {
    __shared__ float tile[32][33];
    int zh = blockIdx.x;
    int ti = blockIdx.y >> 2, tj = blockIdx.y & 3;
    int t = threadIdx.x;
    int r = t >> 5, c = t & 31;
    const float* src = g_qhn + ((size_t)zh << 14);
    float* dst = g_qhnT + ((size_t)zh << 14);
    #pragma unroll
    for (int q = 0; q < 4; q++)
        tile[r + q * 8][c] = src[(ti * 32 + r + q * 8) * 128 + tj * 32 + c];
    __syncthreads();
    #pragma unroll
    for (int q = 0; q < 4; q++)
        dst[(tj * 32 + r + q * 8) * 128 + ti * 32 + c] = tile[c][r + q * 8];
}

__global__ void __launch_bounds__(256) k_S() {
    int zi = blockIdx.x, z = zi >> 7, i = zi & 127;
    int t = threadIdx.x;
    __shared__ float wT[128][36];
    __shared__ float qzc[32][128];
    for (int idx = t; idx < 4096; idx += 256) {
        int r = idx >> 7, j = idx & 127;
        float v; bool m;
        if (r < 16) {
            int k = r >> 3, c = r & 7;
            v = g_qhn[(((z * 8 + c) * 128 + i) << 7) + j];
            m = (k == 0) ? (j > i) : (j < i);
        } else {
            int r2 = r - 16, k = r2 >> 3, c = r2 & 7;
            v = g_qhnT[(((z * 8 + c) * 128 + i) << 7) + j];
            m = (k == 0) ? (j < i) : (j > i);
        }
        wT[j][r] = m ? v : 0.f;
    }
    int tm = t >> 5, tn = t & 31;
    ull acc[4][2];
    #pragma unroll
    for (int q = 0; q < 4; q++) { acc[q][0] = pk2(0.f, 0.f); acc[q][1] = pk2(0.f, 0.f); }
    for (int j0 = 0; j0 < 128; j0 += 32) {
        __syncthreads();
        for (int idx = t; idx < 4096; idx += 256) {
            int jl = idx >> 7, b = idx & 127;
            qzc[jl][b] = g_qz[((z * 128) + j0 + jl) * 128 + b];
        }
        __syncthreads();
        #pragma unroll 8
        for (int jl = 0; jl < 32; jl++) {
            float4 wv = *(const float4*)&wT[j0 + jl][tm * 4];
            float4 qv = *(const float4*)&qzc[jl][tn * 4];
            ull q01 = pk2(qv.x, qv.y), q23 = pk2(qv.z, qv.w);
            ull w0 = pk2(wv.x, wv.x), w1 = pk2(wv.y, wv.y), w2 = pk2(wv.z, wv.z), w3 = pk2(wv.w, wv.w);
            fma2(acc[0][0], w0, q01); fma2(acc[0][1], w0, q23);
            fma2(acc[1][0], w1, q01); fma2(acc[1][1], w1, q23);
            fma2(acc[2][0], w2, q01); fma2(acc[2][1], w2, q23);
            fma2(acc[3][0], w3, q01); fma2(acc[3][1], w3, q23);
        }
    }
    #pragma unroll
    for (int q = 0; q < 4; q++) {
        int r = tm * 4 + q;
        int base = (r < 16) ? r * 128 : 2048 + (r - 16) * 128;
        float c0, c1, c2, c3;
        upk(acc[q][0], c0, c1); upk(acc[q][1], c2, c3);
        *(float4*)&g_S[(size_t)zi * 4096 + base + tn * 4] = make_float4(c0, c1, c2, c3);
    }
}

__global__ void k_sered() {
    int count = g_mcount;
    int pos = blockIdx.x;
    if (pos >= count) return;
    int ntiles = (count + 127) >> 7;
    int mt = pos >> 7, row = pos & 127;
    int gb0 = (mt * 148 + ntiles - 1) / ntiles;
    int gb1 = ((mt + 1) * 148 + ntiles - 1) / ntiles;
    int d = threadIdx.x;
    float num = 0.f, den = 0.f;
    for (int bb = gb0; bb < gb1; bb++) {
        num += g_SEpart[((size_t)bb * 128 + row) * 128 + d];
        den += g_SEsum[bb * 128 + row];
    }
    g_SE[pos * 128 + d] = num / den;
}

__global__ void k_zupd(const float* __restrict__ x, const int* __restrict__ mask,
                       const int* __restrict__ mmask, int useSE) {
    int zi = blockIdx.x, d = threadIdx.x;
    __shared__ float r1[4], r2[4];
    float g = 0.f;
    #pragma unroll
    for (int p = 0; p < 8; p++) g += g_Gpart[((size_t)p * 512 + zi) * 128 + d];
    float mm = (float)mmask[zi];
    float se = 0.f;
    if (mm != 0.f) {
        if (useSE) {
            int pos = g_mpos[zi];
            if (pos >= 0) se = g_SE[pos * 128 + d];
        } else se = g_emean[d];
    }
    float raw = x[zi * 128 + d] * (1.f - mm) + se * mm + g;
    float keep = mask[zi] ? 1.f : 0.f;
    float p_ = softmax128(raw, r1, r2);
    g_qz[zi * 128 + d] = p_ * keep;
}

// ==================== fused SE via mma.sync bf16 3-term ====================
// smem: Ah Al (qz) | Bh Bl (shared E-tile then ET-tile) | Ph Pl | psum[2][128]
#define SH_T 17408                         // 128*136 bf16 per plane
#define SEFH_SMEM (6 * SH_T * 2 + 1024)

__global__ void __launch_bounds__(256) k_sef_h() {
    int count = g_mcount;
    if (count == 0) return;
    int ntiles = (count + 127) >> 7;
    int b = blockIdx.x;
    int mt_ = (b * ntiles) / 148;
    int gb0 = (mt_ * 148 + ntiles - 1) / ntiles;
    int gb1 = ((mt_ + 1) * 148 + ntiles - 1) / ntiles;
    int gsz = gb1 - gb0, li = b - gb0;
    int ustart = (li * 250) / gsz;
    int ucount = ((li + 1) * 250) / gsz - ustart;
    int m0 = mt_ * 128;

    extern __shared__ __nv_bfloat16 shb[];
    __nv_bfloat16* Ah = shb;
    __nv_bfloat16* Al = shb + SH_T;
    __nv_bfloat16* Bh = shb + 2 * SH_T;
    __nv_bfloat16* Bl = shb + 3 * SH_T;
    __nv_bfloat16* Ph = shb + 4 * SH_T;
    __nv_bfloat16* Pl = shb + 5 * SH_T;
    float* psum_s = (float*)(shb + 6 * SH_T);   // [2][128]

    int t = threadIdx.x;
    // load + split qz compact rows
    {
        int row = t >> 1, half = t & 1;
        int pos = m0 + row;
        int zi = (pos < count) ? g_midx[pos] : 0;
        const float* src = g_qz + (size_t)zi * 128 + half * 64;
        int dof = row * 136 + half * 64;
        #pragma unroll
        for (int q = 0; q < 16; q++) {
            float4 v = *(const float4*)(src + q * 4);
            __nv_bfloat162 h01 = __floats2bfloat162_rn(v.x, v.y);
            __nv_bfloat162 h23 = __floats2bfloat162_rn(v.z, v.w);
            __nv_bfloat162 l01 = __floats2bfloat162_rn(v.x - __bfloat162float(h01.x), v.y - __bfloat162float(h01.y));
            __nv_bfloat162 l23 = __floats2bfloat162_rn(v.z - __bfloat162float(h23.x), v.w - __bfloat162float(h23.y));
            *(__nv_bfloat162*)&Ah[dof + q * 4]     = h01;
            *(__nv_bfloat162*)&Ah[dof + q * 4 + 2] = h23;
            *(__nv_bfloat162*)&Al[dof + q * 4]     = l01;
            *(__nv_bfloat162*)&Al[dof + q * 4 + 2] = l23;
        }
    }

    int lane = t & 31, warp = t >> 5;
    int wy = warp >> 1, wx = warp & 1;
    int g = lane >> 2, tig = lane & 3;
    float c2[2][8][4];
    #pragma unroll
    for (int i = 0; i < 2; i++)
        #pragma unroll
        for (int j = 0; j < 8; j++)
            #pragma unroll
            for (int q = 0; q < 4; q++) c2[i][j][q] = 0.f;
    float psr[2][2] = {{0.f, 0.f}, {0.f, 0.f}};

    for (int tile = 0; tile < ucount; tile++) {
        int vg = (ustart + tile) * 128;
        __syncthreads();
        // B <- E rows (GEMM1 operand)
        {
            int row = t >> 1, half = t & 1;
            size_t soff = (size_t)(vg + row) * 128 + half * 64;
            int dof = row * 136 + half * 64;
            #pragma unroll
            for (int q = 0; q < 8; q++) {
                *(uint4*)&Bh[dof + q * 8] = *(const uint4*)&g_Ehi[soff + q * 8];
                *(uint4*)&Bl[dof + q * 8] = *(const uint4*)&g_Elo[soff + q * 8];
            }
        }
        __syncthreads();
        // GEMM1: L[m32][v64] per warp
        float c1[2][8][4];
        #pragma unroll
        for (int i = 0; i < 2; i++)
            #pragma unroll
            for (int j = 0; j < 8; j++)
                #pragma unroll
                for (int q = 0; q < 4; q++) c1[i][j][q] = 0.f;
        #pragma unroll
        for (int ks = 0; ks < 8; ks++) {
            int k0 = ks * 16;
            uint32_t aH[2][4], aL[2][4];
            #pragma unroll
            for (int mt = 0; mt < 2; mt++) {
                int base = (wy * 32 + mt * 16 + g) * 136 + k0;
                aH[mt][0] = *(uint32_t*)&Ah[base + tig * 2];
                aH[mt][1] = *(uint32_t*)&Ah[base + 8 * 136 + tig * 2];
                aH[mt][2] = *(uint32_t*)&Ah[base + tig * 2 + 8];
                aH[mt][3] = *(uint32_t*)&Ah[base + 8 * 136 + tig * 2 + 8];
                aL[mt][0] = *(uint32_t*)&Al[base + tig * 2];
                aL[mt][1] = *(uint32_t*)&Al[base + 8 * 136 + tig * 2];
                aL[mt][2] = *(uint32_t*)&Al[base + tig * 2 + 8];
                aL[mt][3] = *(uint32_t*)&Al[base + 8 * 136 + tig * 2 + 8];
            }
            #pragma unroll
            for (int vt = 0; vt < 8; vt++) {
                int basev = (wx * 64 + vt * 8 + g) * 136 + k0;
                uint32_t bH[2] = {*(uint32_t*)&Bh[basev + tig * 2], *(uint32_t*)&Bh[basev + tig * 2 + 8]};
                uint32_t bL[2] = {*(uint32_t*)&Bl[basev + tig * 2], *(uint32_t*)&Bl[basev + tig * 2 + 8]};
                #pragma unroll
                for (int mt = 0; mt < 2; mt++) {
                    mma16816(c1[mt][vt], aH[mt], bH);
                    mma16816(c1[mt][vt], aH[mt], bL);
                    mma16816(c1[mt][vt], aL[mt], bH);
                }
            }
        }
        // exp + psum + store P (hi/lo bf16)
        #pragma unroll
        for (int mt = 0; mt < 2; mt++)
            #pragma unroll
            for (int vt = 0; vt < 8; vt++) {
                float e0 = fexp(c1[mt][vt][0]), e1 = fexp(c1[mt][vt][1]);
                float e2 = fexp(c1[mt][vt][2]), e3 = fexp(c1[mt][vt][3]);
                psr[mt][0] += e0 + e1;
                psr[mt][1] += e2 + e3;
                int r0 = wy * 32 + mt * 16 + g;
                int col = wx * 64 + vt * 8 + tig * 2;
                __nv_bfloat162 h01 = __floats2bfloat162_rn(e0, e1);
                __nv_bfloat162 l01 = __floats2bfloat162_rn(e0 - __bfloat162float(h01.x), e1 - __bfloat162float(h01.y));
                __nv_bfloat162 h23 = __floats2bfloat162_rn(e2, e3);
                __nv_bfloat162 l23 = __floats2bfloat162_rn(e2 - __bfloat162float(h23.x), e3 - __bfloat162float(h23.y));
                *(__nv_bfloat162*)&Ph[r0 * 136 + col] = h01;
                *(__nv_bfloat162*)&Pl[r0 * 136 + col] = l01;
                *(__nv_bfloat162*)&Ph[(r0 + 8) * 136 + col] = h23;
                *(__nv_bfloat162*)&Pl[(r0 + 8) * 136 + col] = l23;
            }
        __syncthreads();
        // B <- ET rows (GEMM2 operand)
        {
            int row = t >> 1, half = t & 1;
            size_t soff = (size_t)row * 32000 + vg + half * 64;
            int dof = row * 136 + half * 64;
            #pragma unroll
            for (int q = 0; q < 8; q++) {
                *(uint4*)&Bh[dof + q * 8] = *(const uint4*)&g_EThi[soff + q * 8];
                *(uint4*)&Bl[dof + q * 8] = *(const uint4*)&g_ETlo[soff + q * 8];
            }
        }
        __syncthreads();
        // GEMM2: SE[m32][d64] accumulate into c2, K = 128 (v)
        #pragma unroll
        for (int ks = 0; ks < 8; ks++) {
            int k0 = ks * 16;
            uint32_t aH[2][4], aL[2][4];
            #pragma unroll
            for (int mt = 0; mt < 2; mt++) {
                int base = (wy * 32 + mt * 16 + g) * 136 + k0;
                aH[mt][0] = *(uint32_t*)&Ph[base + tig * 2];
                aH[mt][1] = *(uint32_t*)&Ph[base + 8 * 136 + tig * 2];
                aH[mt][2] = *(uint32_t*)&Ph[base + tig * 2 + 8];
                aH[mt][3] = *(uint32_t*)&Ph[base + 8 * 136 + tig * 2 + 8];
                aL[mt][0] = *(uint32_t*)&Pl[base + tig * 2];
                aL[mt][1] = *(uint32_t*)&Pl[base + 8 * 136 + tig * 2];
                aL[mt][2] = *(uint32_t*)&Pl[base + tig * 2 + 8];
                aL[mt][3] = *(uint32_t*)&Pl[base + 8 * 136 + tig * 2 + 8];
            }
            #pragma unroll
            for (int dt = 0; dt < 8; dt++) {
                int basev = (wx * 64 + dt * 8 + g) * 136 + k0;
                uint32_t bH[2] = {*(uint32_t*)&Bh[basev + tig * 2], *(uint32_t*)&Bh[basev + tig * 2 + 8]};
                uint32_t bL[2] = {*(uint32_t*)&Bl[basev + tig * 2], *(uint32_t*)&Bl[basev + tig * 2 + 8]};
                #pragma unroll
                for (int mt = 0; mt < 2; mt++) {
                    mma16816(c2[mt][dt], aH[mt], bH);
                    mma16816(c2[mt][dt], aH[mt], bL);
                    mma16816(c2[mt][dt], aL[mt], bH);
                }
            }
        }
    }
    // epilogue: SEpart
    #pragma unroll
    for (int mt = 0; mt < 2; mt++)
        #pragma unroll
        for (int dt = 0; dt < 8; dt++) {
            int r0 = wy * 32 + mt * 16 + g;
            int col = wx * 64 + dt * 8 + tig * 2;
            *(float2*)&g_SEpart[((size_t)b * 128 + r0) * 128 + col] =
                make_float2(c2[mt][dt][0], c2[mt][dt][1]);
            *(float2*)&g_SEpart[((size_t)b * 128 + r0 + 8) * 128 + col] =
                make_float2(c2[mt][dt][2], c2[mt][dt][3]);
        }
    // psum: quad reduce then write
    #pragma unroll
    for (int mt = 0; mt < 2; mt++)
        #pragma unroll
        for (int h = 0; h < 2; h++) {
            float v = psr[mt][h];
            v += __shfl_xor_sync(~0u, v, 1);
            v += __shfl_xor_sync(~0u, v, 2);
            psr[mt][h] = v;
        }
    if (tig == 0) {
        #pragma unroll
        for (int mt = 0; mt < 2; mt++)
            #pragma unroll
            for (int h = 0; h < 2; h++)
                psum_s[wx * 128 + wy * 32 + mt * 16 + g + h * 8] = psr[mt][h];
    }
    __syncthreads();
    if (t < 128) g_SEsum[b * 128 + t] = psum_s[t] + psum_s[128 + t];
}

// ==================== final out = qz @ E^T via mma ====================
#define MH_S 136
#define MH_SMEM (4 * 128 * MH_S * 2)

__global__ void __launch_bounds__(256) k_msg_h(float* __restrict__ out) {
    extern __shared__ __nv_bfloat16 smh[];
    __nv_bfloat16* Ah = smh;
    __nv_bfloat16* Al = smh + 128 * MH_S;
    __nv_bfloat16* Bh = smh + 2 * 128 * MH_S;
    __nv_bfloat16* Bl = smh + 3 * 128 * MH_S;
    int t = threadIdx.x;
    int v0 = blockIdx.x * 128, m0 = blockIdx.y * 128;
    {
        int row = t >> 1, half = t & 1;
        const float* src = g_qz + (size_t)(m0 + row) * 128 + half * 64;
        int dof = row * MH_S + half * 64;
        #pragma unroll
        for (int q = 0; q < 16; q++) {
            float4 v = *(const float4*)(src + q * 4);
            __nv_bfloat162 h01 = __floats2bfloat162_rn(v.x, v.y);
            __nv_bfloat162 h23 = __floats2bfloat162_rn(v.z, v.w);
            __nv_bfloat162 l01 = __floats2bfloat162_rn(v.x - __bfloat162float(h01.x), v.y - __bfloat162float(h01.y));
            __nv_bfloat162 l23 = __floats2bfloat162_rn(v.z - __bfloat162float(h23.x), v.w - __bfloat162float(h23.y));
            *(__nv_bfloat162*)&Ah[dof + q * 4]     = h01;
            *(__nv_bfloat162*)&Ah[dof + q * 4 + 2] = h23;
            *(__nv_bfloat162*)&Al[dof + q * 4]     = l01;
            *(__nv_bfloat162*)&Al[dof + q * 4 + 2] = l23;
        }
    }
    {
        int row = t >> 1, half = t & 1;
        size_t soff = (size_t)(v0 + row) * 128 + half * 64;
        int dof = row * MH_S + half * 64;
        #pragma unroll
        for (int q = 0; q < 8; q++) {
            *(uint4*)&Bh[dof + q * 8] = *(const uint4*)&g_Ehi[soff + q * 8];
            *(uint4*)&Bl[dof + q * 8] = *(const uint4*)&g_Elo[soff + q * 8];
        }
    }
    __syncthreads();

    int lane = t & 31, warp = t >> 5;
    int wy = warp >> 1, wx = warp & 1;
    int g = lane >> 2, tig = lane & 3;
    float c[16][4];
    #pragma unroll
    for (int i = 0; i < 16; i++)
        #pragma unroll
        for (int q = 0; q < 4; q++) c[i][q] = 0.f;

    #pragma unroll
    for (int ks = 0; ks < 8; ks++) {
        int k0 = ks * 16;
        uint32_t aH[2][4], aL[2][4];
        #pragma unroll
        for (int mt = 0; mt < 2; mt++) {
            int base = (wy * 32 + mt * 16 + g) * MH_S + k0;
            aH[mt][0] = *(uint32_t*)&Ah[base + tig * 2];
            aH[mt][1] = *(uint32_t*)&Ah[base + 8 * MH_S + tig * 2];
            aH[mt][2] = *(uint32_t*)&Ah[base + tig * 2 + 8];
            aH[mt][3] = *(uint32_t*)&Ah[base + 8 * MH_S + tig * 2 + 8];
            aL[mt][0] = *(uint32_t*)&Al[base + tig * 2];
            aL[mt][1] = *(uint32_t*)&Al[base + 8 * MH_S + tig * 2];
            aL[mt][2] = *(uint32_t*)&Al[base + tig * 2 + 8];
            aL[mt][3] = *(uint32_t*)&Al[base + 8 * MH_S + tig * 2 + 8];
        }
        #pragma unroll
        for (int vt = 0; vt < 8; vt++) {
            int basev = (wx * 64 + vt * 8 + g) * MH_S + k0;
            uint32_t bH[2] = {*(uint32_t*)&Bh[basev + tig * 2], *(uint32_t*)&Bh[basev + tig * 2 + 8]};
            uint32_t bL[2] = {*(uint32_t*)&Bl[basev + tig * 2], *(uint32_t*)&Bl[basev + tig * 2 + 8]};
            #pragma unroll
            for (int mt = 0; mt < 2; mt++) {
                int idx = mt * 8 + vt;
                mma16816(c[idx], aH[mt], bH);
                mma16816(c[idx], aH[mt], bL);
                mma16816(c[idx], aL[mt], bH);
            }
        }
    }
    #pragma unroll
    for (int mt = 0; mt < 2; mt++)
        #pragma unroll
        for (int vt = 0; vt < 8; vt++) {
            int idx = mt * 8 + vt;
            int r0 = m0 + wy * 32 + mt * 16 + g;
            int cc = v0 + wx * 64 + vt * 8 + tig * 2;
            *(float2*)&out[(size_t)r0 * 32000 + cc]       = make_float2(c[idx][0], c[idx][1]);
            *(float2*)&out[(size_t)(r0 + 8) * 32000 + cc] = make_float2(c[idx][2], c[idx][3]);
        }
}

// ==================== launch ====================
extern "C" void kernel_launch(void* const* d_in, const int* in_sizes, int n_in,
                              void* d_out, int out_size) {
    const float* x    = (const float*)d_in[0];
    const int*   mask = (const int*)d_in[1];
    const float* E    = (const float*)d_in[2];
    const int*   mm   = (const int*)d_in[3];
    const float* T    = (const float*)d_in[4];
    float* out = (float*)d_out;

    static cudaStream_t s2 = nullptr;
    static cudaEvent_t eF = nullptr, eJ = nullptr;
    if (!s2) {
        cudaStreamCreate(&s2);
        cudaEventCreateWithFlags(&eF, cudaEventDisableTiming);
        cudaEventCreateWithFlags(&eJ, cudaEventDisableTiming);
        cudaFuncSetAttribute(k_sef_h, cudaFuncAttributeMaxDynamicSharedMemorySize, SEFH_SMEM);
        cudaFuncSetAttribute(k_msg_h, cudaFuncAttributeMaxDynamicSharedMemorySize, MH_SMEM);
    }
    cudaStream_t s0 = 0;

    cudaEventRecord(eF, s0);
    cudaStreamWaitEvent(s2, eF, 0);
    k_transE<<<dim3(250, 4), 256, 0, s2>>>(E);
    k_splitE<<<250, 256, 0, s2>>>(E);

    k_emean_part<<<64, 256, 0, s0>>>(E);
    k_emean_red<<<1, 128, 0, s0>>>();
    k_bmat<<<2048, 256, 0, s0>>>(T);
    k_midx<<<1, 512, 0, s0>>>(mask, mm);
    k_init_qz<<<512, 128, 0, s0>>>(x, mask, mm);

    for (int it = 0; it < 4; it++) {
        k_nn64<<<dim3(16, 8, 2), 256, 0, s0>>>(T, 0);
        k_F<<<512, 256, 0, s0>>>(mask);
        k_trq<<<dim3(32, 16), 256, 0, s0>>>();
        k_S<<<512, 256, 0, s0>>>();
        k_nn64<<<dim3(2, 8, 8), 256, 0, s0>>>(T, 1);
        if (it > 0) cudaStreamWaitEvent(s0, eJ, 0);
        k_zupd<<<512, 128, 0, s0>>>(x, mask, mm, it > 0);
        if (it < 3) {
            cudaEventRecord(eF, s0);
            cudaStreamWaitEvent(s2, eF, 0);
            k_sef_h<<<148, 256, SEFH_SMEM, s2>>>();
            k_sered<<<512, 128, 0, s2>>>();
            cudaEventRecord(eJ, s2);
        } else {
            cudaEventRecord(eF, s0);
            cudaStreamWaitEvent(s0, eF, 0);
            k_msg_h<<<dim3(250, 4), 256, MH_SMEM, s0>>>(out);
        }
    }
}

// round 15
// speedup vs baseline: 1.5467x; 1.0406x over previous
#include <cuda_runtime.h>
#include <cuda_bf16.h>
#include <math.h>
#include <stdint.h>

#define NEGC 1.0e9f
typedef unsigned long long ull;

// ==================== static scratch ====================
__device__ float g_epart[64 * 128];
__device__ float g_emean[128];
__device__ float g_Bmat[4096 * 128];
__device__ float g_qz[512 * 128];
__device__ float g_U[2 * 512 * 1024];
__device__ float g_qhn[4 * 8 * 128 * 128];
__device__ float g_qhnT[4 * 8 * 128 * 128];
__device__ float g_S[512 * 4096];
__device__ float g_Gpart[32 * 512 * 128];
__device__ __nv_bfloat16 g_Ehi[32000 * 128];
__device__ __nv_bfloat16 g_Elo[32000 * 128];
__device__ __nv_bfloat16 g_EThi[128 * 32000];
__device__ __nv_bfloat16 g_ETlo[128 * 32000];
__device__ __nv_bfloat16 g_TThi[2 * 1024 * 128];
__device__ __nv_bfloat16 g_TTlo[2 * 1024 * 128];
__device__ __nv_bfloat16 g_BThi[128 * 4096];
__device__ __nv_bfloat16 g_BTlo[128 * 4096];
__device__ __nv_bfloat16 g_qzThi[4 * 128 * 128];
__device__ __nv_bfloat16 g_qzTlo[4 * 128 * 128];
__device__ float g_SEpart[148 * 128 * 128];
__device__ float g_SEsum[148 * 128];
__device__ float g_SE[512 * 128];
__device__ int   g_midx[512];
__device__ int   g_mpos[512];
__device__ int   g_mcount;

// ---- helpers ----
__device__ __forceinline__ void mma16816(float c[4], const uint32_t a[4], const uint32_t b[2]) {
    asm volatile("mma.sync.aligned.m16n8k16.row.col.f32.bf16.bf16.f32 "
        "{%0,%1,%2,%3}, {%4,%5,%6,%7}, {%8,%9}, {%0,%1,%2,%3};"
        : "+f"(c[0]), "+f"(c[1]), "+f"(c[2]), "+f"(c[3])
        : "r"(a[0]), "r"(a[1]), "r"(a[2]), "r"(a[3]), "r"(b[0]), "r"(b[1]));
}
__device__ __forceinline__ float fexp(float x) {
    float z = x * 1.4426950408889634f;
    float m = z + 12582912.0f;
    int ni = __float_as_int(m) - 0x4B400000;
    float f = z - (m - 12582912.0f);
    float p = 0.0013333558f;
    p = fmaf(p, f, 0.0096181291f);
    p = fmaf(p, f, 0.0555041087f);
    p = fmaf(p, f, 0.2402265070f);
    p = fmaf(p, f, 0.6931471806f);
    p = fmaf(p, f, 1.0f);
    return p * __int_as_float((ni + 127) << 23);
}
__device__ __forceinline__ float fexp_s(float x) { return fexp(fmaxf(x, -80.f)); }
__device__ __forceinline__ void split2(float a, float b, __nv_bfloat162 &h, __nv_bfloat162 &l) {
    h = __floats2bfloat162_rn(a, b);
    l = __floats2bfloat162_rn(a - __bfloat162float(h.x), b - __bfloat162float(h.y));
}

// ==================== setup ====================
__global__ void k_emean_part(const float* __restrict__ E) {
    int b = blockIdx.x, t = threadIdx.x;
    int d = t & 127, h = t >> 7;
    float s = 0.f;
    for (int v = b * 500 + h; v < b * 500 + 500; v += 2) s += E[v * 128 + d];
    __shared__ float sh[256];
    sh[t] = s; __syncthreads();
    if (t < 128) g_epart[b * 128 + t] = sh[t] + sh[t + 128];
}
__global__ void k_emean_red() {
    int t = threadIdx.x;
    float s = 0.f;
    for (int b = 0; b < 64; b++) s += g_epart[b * 128 + t];
    g_emean[t] = s * (1.0f / 32000.0f);
}

__global__ void k_bmat(const float* __restrict__ T) {
    int idx = blockIdx.x * 256 + threadIdx.x;
    if (idx >= 4096 * 128) return;
    int r = idx >> 7, col = idx & 127;
    float val;
    if (r < 2048) {
        int k = r >> 10, c = (r >> 7) & 7, b = r & 127;
        val = T[((k * 128 + col) * 128 + b) * 8 + c];
    } else {
        int r2 = r - 2048;
        int k = r2 >> 10, c = (r2 >> 7) & 7, a = r2 & 127;
        val = T[((k * 128 + a) * 128 + col) * 8 + c];
    }
    g_Bmat[idx] = val;
}

// BmatT[d][r] bf16 hi/lo. grid (128 rtile, 4 dtile), 256 thr, 32x32 tiles
__global__ void k_trB() {
    __shared__ float tile[32][33];
    int x = blockIdx.x, y = blockIdx.y, t = threadIdx.x;
    int r = t >> 5, c = t & 31;
    #pragma unroll
    for (int q = 0; q < 4; q++)
        tile[r + q * 8][c] = g_Bmat[(x * 32 + r + q * 8) * 128 + y * 32 + c];
    __syncthreads();
    #pragma unroll
    for (int q = 0; q < 4; q++) {
        float v = tile[c][r + q * 8];
        __nv_bfloat16 h = __float2bfloat16(v);
        size_t off = (size_t)(y * 32 + r + q * 8) * 4096 + x * 32 + c;
        g_BThi[off] = h;
        g_BTlo[off] = __float2bfloat16(v - __bfloat162float(h));
    }
}

// TT[k][bc][a] bf16 hi/lo from T. grid (32 ntile, 4 atile, 2 k), 256 thr
__global__ void k_trT(const float* __restrict__ T) {
    __shared__ float tile[32][33];
    int x = blockIdx.x, y = blockIdx.y, k = blockIdx.z, t = threadIdx.x;
    int r = t >> 5, c = t & 31;
    const float* src = T + k * 131072;
    #pragma unroll
    for (int q = 0; q < 4; q++)
        tile[r + q * 8][c] = src[(y * 32 + r + q * 8) * 1024 + x * 32 + c];
    __syncthreads();
    #pragma unroll
    for (int q = 0; q < 4; q++) {
        float v = tile[c][r + q * 8];
        __nv_bfloat16 h = __float2bfloat16(v);
        size_t off = (size_t)k * 131072 + (size_t)(x * 32 + r + q * 8) * 128 + y * 32 + c;
        g_TThi[off] = h;
        g_TTlo[off] = __float2bfloat16(v - __bfloat162float(h));
    }
}

__global__ void k_transE(const float* __restrict__ E) {
    __shared__ float tile[128][33];
    int v0 = blockIdx.x * 128, d0 = blockIdx.y * 32, t = threadIdx.x;
    for (int idx = t; idx < 4096; idx += 256) {
        int r = idx >> 5, c = idx & 31;
        tile[r][c] = E[(size_t)(v0 + r) * 128 + d0 + c];
    }
    __syncthreads();
    for (int idx = t; idx < 4096; idx += 256) {
        int d = idx >> 7, vv = idx & 127;
        float x = tile[vv][d];
        __nv_bfloat16 h = __float2bfloat16(x);
        g_EThi[(size_t)(d0 + d) * 32000 + v0 + vv] = h;
        g_ETlo[(size_t)(d0 + d) * 32000 + v0 + vv] = __float2bfloat16(x - __bfloat162float(h));
    }
}

__global__ void k_splitE(const float* __restrict__ E) {
    int v0 = blockIdx.x * 128, t = threadIdx.x;
    int row = t >> 1, half = t & 1;
    const float* src = E + (size_t)(v0 + row) * 128 + half * 64;
    size_t dstoff = (size_t)(v0 + row) * 128 + half * 64;
    #pragma unroll
    for (int q = 0; q < 16; q++) {
        float4 v = *(const float4*)(src + q * 4);
        __nv_bfloat162 h01, l01, h23, l23;
        split2(v.x, v.y, h01, l01);
        split2(v.z, v.w, h23, l23);
        *(__nv_bfloat162*)&g_Ehi[dstoff + q * 4]     = h01;
        *(__nv_bfloat162*)&g_Ehi[dstoff + q * 4 + 2] = h23;
        *(__nv_bfloat162*)&g_Elo[dstoff + q * 4]     = l01;
        *(__nv_bfloat162*)&g_Elo[dstoff + q * 4 + 2] = l23;
    }
}

__global__ void k_midx(const int* __restrict__ mask, const int* __restrict__ mmask) {
    __shared__ int pref[512];
    int t = threadIdx.x;
    int f = (mmask[t] != 0 && mask[t] != 0) ? 1 : 0;
    pref[t] = f;
    __syncthreads();
    for (int o = 1; o < 512; o <<= 1) {
        int v = (t >= o) ? pref[t - o] : 0;
        __syncthreads();
        pref[t] += v;
        __syncthreads();
    }
    if (f) { int pos = pref[t] - 1; g_midx[pos] = t; g_mpos[t] = pos; }
    else g_mpos[t] = -1;
    if (t == 511) g_mcount = pref[511];
}

__device__ __forceinline__ float softmax128(float raw, float* r1, float* r2) {
    int lane = threadIdx.x & 31, w = threadIdx.x >> 5;
    float m = raw;
    #pragma unroll
    for (int o = 16; o; o >>= 1) m = fmaxf(m, __shfl_xor_sync(~0u, m, o));
    if (lane == 0) r1[w] = m;
    __syncthreads();
    m = fmaxf(fmaxf(r1[0], r1[1]), fmaxf(r1[2], r1[3]));
    float e = fexp_s(raw - m), s = e;
    #pragma unroll
    for (int o = 16; o; o >>= 1) s += __shfl_xor_sync(~0u, s, o);
    if (lane == 0) r2[w] = s;
    __syncthreads();
    return e / (r2[0] + r2[1] + r2[2] + r2[3]);
}

__global__ void k_init_qz(const float* __restrict__ x, const int* __restrict__ mask,
                          const int* __restrict__ mmask) {
    int zi = blockIdx.x, a = threadIdx.x;
    __shared__ float r1[4], r2[4];
    float keep = mask[zi] ? 1.f : 0.f;
    float mm = (float)mmask[zi];
    float raw = (x[zi * 128 + a] * (1.f - mm) + g_emean[a] * mm) * keep;
    float p = softmax128(raw, r1, r2);
    g_qz[zi * 128 + a] = p * keep;
}

// per-iter: qzT[z][b][j] bf16 hi/lo. grid (4 z, 16), 256 thr
__global__ void k_trqz() {
    __shared__ float tile[32][33];
    int z = blockIdx.x;
    int ti = blockIdx.y >> 2, tj = blockIdx.y & 3;
    int t = threadIdx.x;
    int r = t >> 5, c = t & 31;
    const float* src = g_qz + z * 16384;
    #pragma unroll
    for (int q = 0; q < 4; q++)
        tile[r + q * 8][c] = src[(ti * 32 + r + q * 8) * 128 + tj * 32 + c];
    __syncthreads();
    #pragma unroll
    for (int q = 0; q < 4; q++) {
        float v = tile[c][r + q * 8];
        __nv_bfloat16 h = __float2bfloat16(v);
        int off = z * 16384 + (tj * 32 + r + q * 8) * 128 + ti * 32 + c;
        g_qzThi[off] = h;
        g_qzTlo[off] = __float2bfloat16(v - __bfloat162float(h));
    }
}

// ==================== generic mma helpers (validated fragment maps) ====================
// A-load+split: fp32 src rows -> smem hi/lo stride 136
__device__ __forceinline__ void load_splitA(__nv_bfloat16* Ah, __nv_bfloat16* Al,
                                            const float* src0, size_t srcStride, int t) {
    int row = t >> 1, half = t & 1;
    const float* src = src0 + (size_t)row * srcStride + half * 64;
    int dof = row * 136 + half * 64;
    #pragma unroll
    for (int q = 0; q < 16; q++) {
        float4 v = *(const float4*)(src + q * 4);
        __nv_bfloat162 h01, l01, h23, l23;
        split2(v.x, v.y, h01, l01);
        split2(v.z, v.w, h23, l23);
        *(__nv_bfloat162*)&Ah[dof + q * 4]     = h01;
        *(__nv_bfloat162*)&Ah[dof + q * 4 + 2] = h23;
        *(__nv_bfloat162*)&Al[dof + q * 4]     = l01;
        *(__nv_bfloat162*)&Al[dof + q * 4 + 2] = l23;
    }
}
// B copy: pre-split bf16 src rows (128 cols) -> smem stride 136
__device__ __forceinline__ void load_preB(__nv_bfloat16* Bh, __nv_bfloat16* Bl,
                                          const __nv_bfloat16* srcH, const __nv_bfloat16* srcL,
                                          size_t srcStride, int t) {
    int row = t >> 1, half = t & 1;
    size_t soff = (size_t)row * srcStride + half * 64;
    int dof = row * 136 + half * 64;
    #pragma unroll
    for (int q = 0; q < 8; q++) {
        *(uint4*)&Bh[dof + q * 8] = *(const uint4*)&srcH[soff + q * 8];
        *(uint4*)&Bl[dof + q * 8] = *(const uint4*)&srcL[soff + q * 8];
    }
}
// 128x128x128 3-term mma core: c[2][8][4] per warp (4m x 2n warp grid)
__device__ __forceinline__ void mma_core(float c[2][8][4],
        const __nv_bfloat16* Ah, const __nv_bfloat16* Al,
        const __nv_bfloat16* Bh, const __nv_bfloat16* Bl, int lane, int warp) {
    int wy = warp >> 1, wx = warp & 1;
    int g = lane >> 2, tig = lane & 3;
    #pragma unroll
    for (int ks = 0; ks < 8; ks++) {
        int k0 = ks * 16;
        uint32_t aH[2][4], aL[2][4];
        #pragma unroll
        for (int mt = 0; mt < 2; mt++) {
            int base = (wy * 32 + mt * 16 + g) * 136 + k0;
            aH[mt][0] = *(uint32_t*)&Ah[base + tig * 2];
            aH[mt][1] = *(uint32_t*)&Ah[base + 8 * 136 + tig * 2];
            aH[mt][2] = *(uint32_t*)&Ah[base + tig * 2 + 8];
            aH[mt][3] = *(uint32_t*)&Ah[base + 8 * 136 + tig * 2 + 8];
            aL[mt][0] = *(uint32_t*)&Al[base + tig * 2];
            aL[mt][1] = *(uint32_t*)&Al[base + 8 * 136 + tig * 2];
            aL[mt][2] = *(uint32_t*)&Al[base + tig * 2 + 8];
            aL[mt][3] = *(uint32_t*)&Al[base + 8 * 136 + tig * 2 + 8];
        }
        #pragma unroll
        for (int vt = 0; vt < 8; vt++) {
            int basev = (wx * 64 + vt * 8 + g) * 136 + k0;
            uint32_t bH[2] = {*(uint32_t*)&Bh[basev + tig * 2], *(uint32_t*)&Bh[basev + tig * 2 + 8]};
            uint32_t bL[2] = {*(uint32_t*)&Bl[basev + tig * 2], *(uint32_t*)&Bl[basev + tig * 2 + 8]};
            #pragma unroll
            for (int mt = 0; mt < 2; mt++) {
                mma16816(c[mt][vt], aH[mt], bH);
                mma16816(c[mt][vt], aH[mt], bL);
                mma16816(c[mt][vt], aL[mt], bH);
            }
        }
    }
}

#define STD_SMEM (4 * 128 * 136 * 2)

// ---- U = qz @ T[k] : grid (8 n, 4 m, 2 k) ----
__global__ void __launch_bounds__(256) k_U_h() {
    extern __shared__ __nv_bfloat16 sb[];
    __nv_bfloat16 *Ah = sb, *Al = sb + 128 * 136, *Bh = sb + 2 * 128 * 136, *Bl = sb + 3 * 128 * 136;
    int t = threadIdx.x;
    int n0 = blockIdx.x * 128, m0 = blockIdx.y * 128, kk = blockIdx.z;
    load_splitA(Ah, Al, g_qz + (size_t)m0 * 128, 128, t);
    load_preB(Bh, Bl, g_TThi + (size_t)kk * 131072 + (size_t)n0 * 128,
                      g_TTlo + (size_t)kk * 131072 + (size_t)n0 * 128, 128, t);
    __syncthreads();
    int lane = t & 31, warp = t >> 5;
    float c[2][8][4];
    #pragma unroll
    for (int i = 0; i < 2; i++)
        #pragma unroll
        for (int j = 0; j < 8; j++)
            #pragma unroll
            for (int q = 0; q < 4; q++) c[i][j][q] = 0.f;
    mma_core(c, Ah, Al, Bh, Bl, lane, warp);
    int wy = warp >> 1, wx = warp & 1, g = lane >> 2, tig = lane & 3;
    float* C = g_U + (size_t)kk * 524288;
    #pragma unroll
    for (int mt = 0; mt < 2; mt++)
        #pragma unroll
        for (int vt = 0; vt < 8; vt++) {
            int r0 = m0 + wy * 32 + mt * 16 + g;
            int cc = n0 + wx * 64 + vt * 8 + tig * 2;
            *(float2*)&C[(size_t)r0 * 1024 + cc]       = make_float2(c[mt][vt][0], c[mt][vt][1]);
            *(float2*)&C[(size_t)(r0 + 8) * 1024 + cc] = make_float2(c[mt][vt][2], c[mt][vt][3]);
        }
}

// ---- Gpart[ks] = S[:, ks*128:+128] @ BmatT : grid (4 m, 32 ks) ----
__global__ void __launch_bounds__(256) k_g_h() {
    extern __shared__ __nv_bfloat16 sb[];
    __nv_bfloat16 *Ah = sb, *Al = sb + 128 * 136, *Bh = sb + 2 * 128 * 136, *Bl = sb + 3 * 128 * 136;
    int t = threadIdx.x;
    int m0 = blockIdx.x * 128, kb = blockIdx.y * 128;
    load_splitA(Ah, Al, g_S + (size_t)m0 * 4096 + kb, 4096, t);
    load_preB(Bh, Bl, g_BThi + kb, g_BTlo + kb, 4096, t);
    __syncthreads();
    int lane = t & 31, warp = t >> 5;
    float c[2][8][4];
    #pragma unroll
    for (int i = 0; i < 2; i++)
        #pragma unroll
        for (int j = 0; j < 8; j++)
            #pragma unroll
            for (int q = 0; q < 4; q++) c[i][j][q] = 0.f;
    mma_core(c, Ah, Al, Bh, Bl, lane, warp);
    int wy = warp >> 1, wx = warp & 1, g = lane >> 2, tig = lane & 3;
    #pragma unroll
    for (int mt = 0; mt < 2; mt++)
        #pragma unroll
        for (int vt = 0; vt < 8; vt++) {
            int r0 = m0 + wy * 32 + mt * 16 + g;
            int cc = wx * 64 + vt * 8 + tig * 2;
            *(float2*)&g_Gpart[((size_t)blockIdx.y * 512 + r0) * 128 + cc] =
                make_float2(c[mt][vt][0], c[mt][vt][1]);
            *(float2*)&g_Gpart[((size_t)blockIdx.y * 512 + r0 + 8) * 128 + cc] =
                make_float2(c[mt][vt][2], c[mt][vt][3]);
        }
}

// ---- S = W(32x128) @ qz(128x128) per zi block : grid 512 ----
#define SH2_SMEM ((32 * 136 * 2 + 2 * 128 * 136) * 2)
__global__ void __launch_bounds__(256) k_S_h() {
    extern __shared__ __nv_bfloat16 sb[];
    __nv_bfloat16 *Wh = sb, *Wl = sb + 32 * 136;
    __nv_bfloat16 *Bh = sb + 64 * 136, *Bl = sb + 64 * 136 + 128 * 136;
    int zi = blockIdx.x, z = zi >> 7, i = zi & 127;
    int t = threadIdx.x;
    // masked W load (coalesced over j) + split
    for (int idx = t; idx < 4096; idx += 256) {
        int r = idx >> 7, j = idx & 127;
        float v; bool m;
        if (r < 16) {
            int k = r >> 3, c = r & 7;
            v = g_qhn[(((z * 8 + c) * 128 + i) << 7) + j];
            m = (k == 0) ? (j > i) : (j < i);
        } else {
            int r2 = r - 16, k = r2 >> 3, c = r2 & 7;
            v = g_qhnT[(((z * 8 + c) * 128 + i) << 7) + j];
            m = (k == 0) ? (j < i) : (j > i);
        }
        v = m ? v : 0.f;
        __nv_bfloat16 h = __float2bfloat16(v);
        Wh[r * 136 + j] = h;
        Wl[r * 136 + j] = __float2bfloat16(v - __bfloat162float(h));
    }
    load_preB(Bh, Bl, g_qzThi + z * 16384, g_qzTlo + z * 16384, 128, t);
    __syncthreads();
    int lane = t & 31, warp = t >> 5;
    int wy = warp >> 2, wx = warp & 3;     // 2m16 x 4n32
    int g = lane >> 2, tig = lane & 3;
    float c[4][4];
    #pragma unroll
    for (int j = 0; j < 4; j++)
        #pragma unroll
        for (int q = 0; q < 4; q++) c[j][q] = 0.f;
    #pragma unroll
    for (int ks = 0; ks < 8; ks++) {
        int k0 = ks * 16;
        uint32_t aH[4], aL[4];
        int base = (wy * 16 + g) * 136 + k0;
        aH[0] = *(uint32_t*)&Wh[base + tig * 2];
        aH[1] = *(uint32_t*)&Wh[base + 8 * 136 + tig * 2];
        aH[2] = *(uint32_t*)&Wh[base + tig * 2 + 8];
        aH[3] = *(uint32_t*)&Wh[base + 8 * 136 + tig * 2 + 8];
        aL[0] = *(uint32_t*)&Wl[base + tig * 2];
        aL[1] = *(uint32_t*)&Wl[base + 8 * 136 + tig * 2];
        aL[2] = *(uint32_t*)&Wl[base + tig * 2 + 8];
        aL[3] = *(uint32_t*)&Wl[base + 8 * 136 + tig * 2 + 8];
        #pragma unroll
        for (int vt = 0; vt < 4; vt++) {
            int basev = (wx * 32 + vt * 8 + g) * 136 + k0;
            uint32_t bH[2] = {*(uint32_t*)&Bh[basev + tig * 2], *(uint32_t*)&Bh[basev + tig * 2 + 8]};
            uint32_t bL[2] = {*(uint32_t*)&Bl[basev + tig * 2], *(uint32_t*)&Bl[basev + tig * 2 + 8]};
            mma16816(c[vt], aH, bH);
            mma16816(c[vt], aH, bL);
            mma16816(c[vt], aL, bH);
        }
    }
    #pragma unroll
    for (int vt = 0; vt < 4; vt++) {
        int r0 = wy * 16 + g;
        int cc = wx * 32 + vt * 8 + tig * 2;
        int base0 = (r0 < 16) ? r0 * 128 : 2048 + (r0 - 16) * 128;
        int r1 = r0 + 8;
        int base1 = (r1 < 16) ? r1 * 128 : 2048 + (r1 - 16) * 128;
        *(float2*)&g_S[(size_t)zi * 4096 + base0 + cc] = make_float2(c[vt][0], c[vt][1]);
        *(float2*)&g_S[(size_t)zi * 4096 + base1 + cc] = make_float2(c[vt][2], c[vt][3]);
    }
}

// ==================== k_F (fp32, unchanged) ====================
__global__ void __launch_bounds__(256) k_F(const int* __restrict__ mask) {
    int zi = blockIdx.x, z = zi >> 7, i = zi & 127;
    int t = threadIdx.x;
    __shared__ float U_sh[2][1024];
    __shared__ float qz_sh[32][129];
    __shared__ float qh_sh[8][128];
    __shared__ float smax[8], ssum[8];
    for (int idx = t; idx < 2048; idx += 256) {
        int k = idx >> 10, bc = idx & 1023;
        U_sh[k][bc] = g_U[((size_t)k * 512 + zi) * 1024 + bc];
    }
    int j = t & 127, ch = t >> 7;
    int ksel = (j > i) ? 0 : 1;
    float a0 = 0.f, a1 = 0.f, a2 = 0.f, a3 = 0.f;
    const float* qzb = g_qz + z * 128 * 128;
    for (int b0 = 0; b0 < 128; b0 += 32) {
        __syncthreads();
        #pragma unroll
        for (int e = 0; e < 16; e++) {
            int lin = t + e * 256;
            int jj = lin >> 5, col = lin & 31;
            qz_sh[col][jj] = qzb[jj * 128 + b0 + col];
        }
        __syncthreads();
        #pragma unroll 8
        for (int bb = 0; bb < 32; bb++) {
            float qv = qz_sh[bb][j];
            float4 u4 = *(const float4*)&U_sh[ksel][(b0 + bb) * 8 + ch * 4];
            a0 += qv * u4.x; a1 += qv * u4.y; a2 += qv * u4.z; a3 += qv * u4.w;
        }
    }
    bool vi = mask[z * 128 + i] != 0, vj = mask[z * 128 + j] != 0;
    if (i == j || !vi || !vj) { a0 = a1 = a2 = a3 = -NEGC; }
    qh_sh[ch * 4 + 0][j] = a0; qh_sh[ch * 4 + 1][j] = a1;
    qh_sh[ch * 4 + 2][j] = a2; qh_sh[ch * 4 + 3][j] = a3;
    __syncthreads();
    int w = t >> 5, lane = t & 31;
    float v0 = qh_sh[w][lane], v1 = qh_sh[w][lane + 32];
    float v2 = qh_sh[w][lane + 64], v3 = qh_sh[w][lane + 96];
    float mx = fmaxf(fmaxf(v0, v1), fmaxf(v2, v3));
    #pragma unroll
    for (int o = 16; o; o >>= 1) mx = fmaxf(mx, __shfl_xor_sync(~0u, mx, o));
    float sum = fexp_s(v0 - mx) + fexp_s(v1 - mx) + fexp_s(v2 - mx) + fexp_s(v3 - mx);
    #pragma unroll
    for (int o = 16; o; o >>= 1) sum += __shfl_xor_sync(~0u, sum, o);
    if (lane == 0) { smax[w] = mx; ssum[w] = sum; }
    __syncthreads();
    float vals[4] = {a0, a1, a2, a3};
    #pragma unroll
    for (int hh = 0; hh < 4; hh++) {
        int h = ch * 4 + hh;
        float p = fexp_s(vals[hh] - smax[h]) / ssum[h];
        g_qhn[(((z * 8 + h) * 128 + i) << 7) + j] = p;
    }
}

__global__ void __launch_bounds__(256) k_trq() {
    __shared__ float tile[32][33];
    int zh = blockIdx.x;
    int ti = blockIdx.y >> 2, tj = blockIdx.y & 3;
    int t = threadIdx.x;
    int r = t >> 5, c = t & 31;
    const float* src = g_qhn + ((size_t)zh << 14);
    float* dst = g_qhnT + ((size_t)zh << 14);
    #pragma unroll
    for (int q = 0; q < 4; q++)
        tile[r + q * 8][c] = src[(ti * 32 + r + q * 8) * 128 + tj * 32 + c];
    __syncthreads();
    #pragma unroll
    for (int q = 0; q < 4; q++)
        dst[(tj * 32 + r + q * 8) * 128 + ti * 32 + c] = tile[c][r + q * 8];
}

__global__ void k_sered() {
    int count = g_mcount;
    int pos = blockIdx.x;
    if (pos >= count) return;
    int ntiles = (count + 127) >> 7;
    int mt = pos >> 7, row = pos & 127;
    int gb0 = (mt * 148 + ntiles - 1) / ntiles;
    int gb1 = ((mt + 1) * 148 + ntiles - 1) / ntiles;
    int d = threadIdx.x;
    float num = 0.f, den = 0.f;
    for (int bb = gb0; bb < gb1; bb++) {
        num += g_SEpart[((size_t)bb * 128 + row) * 128 + d];
        den += g_SEsum[bb * 128 + row];
    }
    g_SE[pos * 128 + d] = num / den;
}

__global__ void k_zupd(const float* __restrict__ x, const int* __restrict__ mask,
                       const int* __restrict__ mmask, int useSE) {
    int zi = blockIdx.x, d = threadIdx.x;
    __shared__ float r1[4], r2[4];
    float g = 0.f;
    #pragma unroll 8
    for (int p = 0; p < 32; p++) g += g_Gpart[((size_t)p * 512 + zi) * 128 + d];
    float mm = (float)mmask[zi];
    float se = 0.f;
    if (mm != 0.f) {
        if (useSE) {
            int pos = g_mpos[zi];
            if (pos >= 0) se = g_SE[pos * 128 + d];
        } else se = g_emean[d];
    }
    float raw = x[zi * 128 + d] * (1.f - mm) + se * mm + g;
    float keep = mask[zi] ? 1.f : 0.f;
    float p_ = softmax128(raw, r1, r2);
    g_qz[zi * 128 + d] = p_ * keep;
}

// ==================== fused SE via mma (unchanged from R14) ====================
#define SH_T 17408
#define SEFH_SMEM (6 * SH_T * 2 + 1024)

__global__ void __launch_bounds__(256) k_sef_h() {
    int count = g_mcount;
    if (count == 0) return;
    int ntiles = (count + 127) >> 7;
    int b = blockIdx.x;
    int mt_ = (b * ntiles) / 148;
    int gb0 = (mt_ * 148 + ntiles - 1) / ntiles;
    int gb1 = ((mt_ + 1) * 148 + ntiles - 1) / ntiles;
    int gsz = gb1 - gb0, li = b - gb0;
    int ustart = (li * 250) / gsz;
    int ucount = ((li + 1) * 250) / gsz - ustart;
    int m0 = mt_ * 128;

    extern __shared__ __nv_bfloat16 shb[];
    __nv_bfloat16* Ah = shb;
    __nv_bfloat16* Al = shb + SH_T;
    __nv_bfloat16* Bh = shb + 2 * SH_T;
    __nv_bfloat16* Bl = shb + 3 * SH_T;
    __nv_bfloat16* Ph = shb + 4 * SH_T;
    __nv_bfloat16* Pl = shb + 5 * SH_T;
    float* psum_s = (float*)(shb + 6 * SH_T);

    int t = threadIdx.x;
    {
        int row = t >> 1, half = t & 1;
        int pos = m0 + row;
        int zi = (pos < count) ? g_midx[pos] : 0;
        const float* src = g_qz + (size_t)zi * 128 + half * 64;
        int dof = row * 136 + half * 64;
        #pragma unroll
        for (int q = 0; q < 16; q++) {
            float4 v = *(const float4*)(src + q * 4);
            __nv_bfloat162 h01, l01, h23, l23;
            split2(v.x, v.y, h01, l01);
            split2(v.z, v.w, h23, l23);
            *(__nv_bfloat162*)&Ah[dof + q * 4]     = h01;
            *(__nv_bfloat162*)&Ah[dof + q * 4 + 2] = h23;
            *(__nv_bfloat162*)&Al[dof + q * 4]     = l01;
            *(__nv_bfloat162*)&Al[dof + q * 4 + 2] = l23;
        }
    }

    int lane = t & 31, warp = t >> 5;
    int wy = warp >> 1, wx = warp & 1;
    int g = lane >> 2, tig = lane & 3;
    float c2[2][8][4];
    #pragma unroll
    for (int i = 0; i < 2; i++)
        #pragma unroll
        for (int j = 0; j < 8; j++)
            #pragma unroll
            for (int q = 0; q < 4; q++) c2[i][j][q] = 0.f;
    float psr[2][2] = {{0.f, 0.f}, {0.f, 0.f}};

    for (int tile = 0; tile < ucount; tile++) {
        int vg = (ustart + tile) * 128;
        __syncthreads();
        load_preB(Bh, Bl, g_Ehi + (size_t)vg * 128, g_Elo + (size_t)vg * 128, 128, t);
        __syncthreads();
        float c1[2][8][4];
        #pragma unroll
        for (int i = 0; i < 2; i++)
            #pragma unroll
            for (int j = 0; j < 8; j++)
                #pragma unroll
                for (int q = 0; q < 4; q++) c1[i][j][q] = 0.f;
        mma_core(c1, Ah, Al, Bh, Bl, lane, warp);
        #pragma unroll
        for (int mt = 0; mt < 2; mt++)
            #pragma unroll
            for (int vt = 0; vt < 8; vt++) {
                float e0 = fexp(c1[mt][vt][0]), e1 = fexp(c1[mt][vt][1]);
                float e2 = fexp(c1[mt][vt][2]), e3 = fexp(c1[mt][vt][3]);
                psr[mt][0] += e0 + e1;
                psr[mt][1] += e2 + e3;
                int r0 = wy * 32 + mt * 16 + g;
                int col = wx * 64 + vt * 8 + tig * 2;
                __nv_bfloat162 h01, l01, h23, l23;
                split2(e0, e1, h01, l01);
                split2(e2, e3, h23, l23);
                *(__nv_bfloat162*)&Ph[r0 * 136 + col] = h01;
                *(__nv_bfloat162*)&Pl[r0 * 136 + col] = l01;
                *(__nv_bfloat162*)&Ph[(r0 + 8) * 136 + col] = h23;
                *(__nv_bfloat162*)&Pl[(r0 + 8) * 136 + col] = l23;
            }
        __syncthreads();
        load_preB(Bh, Bl, g_EThi + vg, g_ETlo + vg, 32000, t);
        __syncthreads();
        mma_core(c2, Ph, Pl, Bh, Bl, lane, warp);
    }
    #pragma unroll
    for (int mt = 0; mt < 2; mt++)
        #pragma unroll
        for (int dt = 0; dt < 8; dt++) {
            int r0 = wy * 32 + mt * 16 + g;
            int col = wx * 64 + dt * 8 + tig * 2;
            *(float2*)&g_SEpart[((size_t)b * 128 + r0) * 128 + col] =
                make_float2(c2[mt][dt][0], c2[mt][dt][1]);
            *(float2*)&g_SEpart[((size_t)b * 128 + r0 + 8) * 128 + col] =
                make_float2(c2[mt][dt][2], c2[mt][dt][3]);
        }
    #pragma unroll
    for (int mt = 0; mt < 2; mt++)
        #pragma unroll
        for (int h = 0; h < 2; h++) {
            float v = psr[mt][h];
            v += __shfl_xor_sync(~0u, v, 1);
            v += __shfl_xor_sync(~0u, v, 2);
            psr[mt][h] = v;
        }
    if (tig == 0) {
        #pragma unroll
        for (int mt = 0; mt < 2; mt++)
            #pragma unroll
            for (int h = 0; h < 2; h++)
                psum_s[wx * 128 + wy * 32 + mt * 16 + g + h * 8] = psr[mt][h];
    }
    __syncthreads();
    if (t < 128) g_SEsum[b * 128 + t] = psum_s[t] + psum_s[128 + t];
}

// ==================== final out = qz @ E^T (unchanged) ====================
__global__ void __launch_bounds__(256) k_msg_h(float* __restrict__ out) {
    extern __shared__ __nv_bfloat16 smh[];
    __nv_bfloat16 *Ah = smh, *Al = smh + 128 * 136, *Bh = smh + 2 * 128 * 136, *Bl = smh + 3 * 128 * 136;
    int t = threadIdx.x;
    int v0 = blockIdx.x * 128, m0 = blockIdx.y * 128;
    load_splitA(Ah, Al, g_qz + (size_t)m0 * 128, 128, t);
    load_preB(Bh, Bl, g_Ehi + (size_t)v0 * 128, g_Elo + (size_t)v0 * 128, 128, t);
    __syncthreads();
    int lane = t & 31, warp = t >> 5;
    float c[2][8][4];
    #pragma unroll
    for (int i = 0; i < 2; i++)
        #pragma unroll
        for (int j = 0; j < 8; j++)
            #pragma unroll
            for (int q = 0; q < 4; q++) c[i][j][q] = 0.f;
    mma_core(c, Ah, Al, Bh, Bl, lane, warp);
    int wy = warp >> 1, wx = warp & 1, g = lane >> 2, tig = lane & 3;
    #pragma unroll
    for (int mt = 0; mt < 2; mt++)
        #pragma unroll
        for (int vt = 0; vt < 8; vt++) {
            int r0 = m0 + wy * 32 + mt * 16 + g;
            int cc = v0 + wx * 64 + vt * 8 + tig * 2;
            *(float2*)&out[(size_t)r0 * 32000 + cc]       = make_float2(c[mt][vt][0], c[mt][vt][1]);
            *(float2*)&out[(size_t)(r0 + 8) * 32000 + cc] = make_float2(c[mt][vt][2], c[mt][vt][3]);
        }
}

// ==================== launch ====================
extern "C" void kernel_launch(void* const* d_in, const int* in_sizes, int n_in,
                              void* d_out, int out_size) {
    const float* x    = (const float*)d_in[0];
    const int*   mask = (const int*)d_in[1];
    const float* E    = (const float*)d_in[2];
    const int*   mm   = (const int*)d_in[3];
    const float* T    = (const float*)d_in[4];
    float* out = (float*)d_out;

    static cudaStream_t s2 = nullptr;
    static cudaEvent_t eF = nullptr, eJ = nullptr;
    if (!s2) {
        cudaStreamCreate(&s2);
        cudaEventCreateWithFlags(&eF, cudaEventDisableTiming);
        cudaEventCreateWithFlags(&eJ, cudaEventDisableTiming);
        cudaFuncSetAttribute(k_sef_h, cudaFuncAttributeMaxDynamicSharedMemorySize, SEFH_SMEM);
        cudaFuncSetAttribute(k_msg_h, cudaFuncAttributeMaxDynamicSharedMemorySize, STD_SMEM);
        cudaFuncSetAttribute(k_U_h,   cudaFuncAttributeMaxDynamicSharedMemorySize, STD_SMEM);
        cudaFuncSetAttribute(k_g_h,   cudaFuncAttributeMaxDynamicSharedMemorySize, STD_SMEM);
        cudaFuncSetAttribute(k_S_h,   cudaFuncAttributeMaxDynamicSharedMemorySize, SH2_SMEM);
    }
    cudaStream_t s0 = 0;

    cudaEventRecord(eF, s0);
    cudaStreamWaitEvent(s2, eF, 0);
    k_transE<<<dim3(250, 4), 256, 0, s2>>>(E);
    k_splitE<<<250, 256, 0, s2>>>(E);

    k_emean_part<<<64, 256, 0, s0>>>(E);
    k_emean_red<<<1, 128, 0, s0>>>();
    k_bmat<<<2048, 256, 0, s0>>>(T);
    k_trB<<<dim3(128, 4), 256, 0, s0>>>();
    k_trT<<<dim3(32, 4, 2), 256, 0, s0>>>(T);
    k_midx<<<1, 512, 0, s0>>>(mask, mm);
    k_init_qz<<<512, 128, 0, s0>>>(x, mask, mm);

    for (int it = 0; it < 4; it++) {
        k_U_h<<<dim3(8, 4, 2), 256, STD_SMEM, s0>>>();
        k_F<<<512, 256, 0, s0>>>(mask);
        k_trq<<<dim3(32, 16), 256, 0, s0>>>();
        k_trqz<<<dim3(4, 16), 256, 0, s0>>>();
        k_S_h<<<512, 256, SH2_SMEM, s0>>>();
        k_g_h<<<dim3(4, 32), 256, STD_SMEM, s0>>>();
        if (it > 0) cudaStreamWaitEvent(s0, eJ, 0);
        k_zupd<<<512, 128, 0, s0>>>(x, mask, mm, it > 0);
        if (it < 3) {
            cudaEventRecord(eF, s0);
            cudaStreamWaitEvent(s2, eF, 0);
            k_sef_h<<<148, 256, SEFH_SMEM, s2>>>();
            k_sered<<<512, 128, 0, s2>>>();
            cudaEventRecord(eJ, s2);
        } else {
            k_msg_h<<<dim3(250, 4), 256, STD_SMEM, s0>>>(out);
        }
    }
}

// round 16
// speedup vs baseline: 1.5625x; 1.0102x over previous
#include <cuda_runtime.h>
#include <cuda_bf16.h>
#include <math.h>
#include <stdint.h>

#define NEGC 1.0e9f
typedef unsigned long long ull;

// ==================== static scratch ====================
__device__ float g_epart[64 * 128];
__device__ float g_emean[128];
__device__ float g_Bmat[4096 * 128];
__device__ float g_qz[512 * 128];
__device__ float g_U[2 * 512 * 1024];
__device__ __nv_bfloat16 g_Ufhi[2 * 4 * 1024 * 128];
__device__ __nv_bfloat16 g_Uflo[2 * 4 * 1024 * 128];
__device__ float g_F[2 * 4 * 1024 * 128];
__device__ float g_qhn[4 * 8 * 128 * 128];
__device__ float g_qhnT[4 * 8 * 128 * 128];
__device__ float g_S[512 * 4096];
__device__ float g_Gpart[32 * 512 * 128];
__device__ __nv_bfloat16 g_Ehi[32000 * 128];
__device__ __nv_bfloat16 g_Elo[32000 * 128];
__device__ __nv_bfloat16 g_EThi[128 * 32000];
__device__ __nv_bfloat16 g_ETlo[128 * 32000];
__device__ __nv_bfloat16 g_TThi[2 * 1024 * 128];
__device__ __nv_bfloat16 g_TTlo[2 * 1024 * 128];
__device__ __nv_bfloat16 g_BThi[128 * 4096];
__device__ __nv_bfloat16 g_BTlo[128 * 4096];
__device__ __nv_bfloat16 g_qzThi[4 * 128 * 128];
__device__ __nv_bfloat16 g_qzTlo[4 * 128 * 128];
__device__ float g_SEpart[148 * 128 * 128];
__device__ float g_SEsum[148 * 128];
__device__ float g_SE[512 * 128];
__device__ int   g_midx[512];
__device__ int   g_mpos[512];
__device__ int   g_mcount;

// ---- helpers ----
__device__ __forceinline__ void mma16816(float c[4], const uint32_t a[4], const uint32_t b[2]) {
    asm volatile("mma.sync.aligned.m16n8k16.row.col.f32.bf16.bf16.f32 "
        "{%0,%1,%2,%3}, {%4,%5,%6,%7}, {%8,%9}, {%0,%1,%2,%3};"
        : "+f"(c[0]), "+f"(c[1]), "+f"(c[2]), "+f"(c[3])
        : "r"(a[0]), "r"(a[1]), "r"(a[2]), "r"(a[3]), "r"(b[0]), "r"(b[1]));
}
__device__ __forceinline__ float fexp(float x) {
    float z = x * 1.4426950408889634f;
    float m = z + 12582912.0f;
    int ni = __float_as_int(m) - 0x4B400000;
    float f = z - (m - 12582912.0f);
    float p = 0.0013333558f;
    p = fmaf(p, f, 0.0096181291f);
    p = fmaf(p, f, 0.0555041087f);
    p = fmaf(p, f, 0.2402265070f);
    p = fmaf(p, f, 0.6931471806f);
    p = fmaf(p, f, 1.0f);
    return p * __int_as_float((ni + 127) << 23);
}
__device__ __forceinline__ float fexp_s(float x) { return fexp(fmaxf(x, -80.f)); }
__device__ __forceinline__ void split2(float a, float b, __nv_bfloat162 &h, __nv_bfloat162 &l) {
    h = __floats2bfloat162_rn(a, b);
    l = __floats2bfloat162_rn(a - __bfloat162float(h.x), b - __bfloat162float(h.y));
}

// ==================== setup ====================
__global__ void k_emean_part(const float* __restrict__ E) {
    int b = blockIdx.x, t = threadIdx.x;
    int d = t & 127, h = t >> 7;
    float s = 0.f;
    for (int v = b * 500 + h; v < b * 500 + 500; v += 2) s += E[v * 128 + d];
    __shared__ float sh[256];
    sh[t] = s; __syncthreads();
    if (t < 128) g_epart[b * 128 + t] = sh[t] + sh[t + 128];
}
__global__ void k_emean_red() {
    int t = threadIdx.x;
    float s = 0.f;
    for (int b = 0; b < 64; b++) s += g_epart[b * 128 + t];
    g_emean[t] = s * (1.0f / 32000.0f);
}

__global__ void k_bmat(const float* __restrict__ T) {
    int idx = blockIdx.x * 256 + threadIdx.x;
    if (idx >= 4096 * 128) return;
    int r = idx >> 7, col = idx & 127;
    float val;
    if (r < 2048) {
        int k = r >> 10, c = (r >> 7) & 7, b = r & 127;
        val = T[((k * 128 + col) * 128 + b) * 8 + c];
    } else {
        int r2 = r - 2048;
        int k = r2 >> 10, c = (r2 >> 7) & 7, a = r2 & 127;
        val = T[((k * 128 + a) * 128 + col) * 8 + c];
    }
    g_Bmat[idx] = val;
}

__global__ void k_trB() {
    __shared__ float tile[32][33];
    int x = blockIdx.x, y = blockIdx.y, t = threadIdx.x;
    int r = t >> 5, c = t & 31;
    #pragma unroll
    for (int q = 0; q < 4; q++)
        tile[r + q * 8][c] = g_Bmat[(x * 32 + r + q * 8) * 128 + y * 32 + c];
    __syncthreads();
    #pragma unroll
    for (int q = 0; q < 4; q++) {
        float v = tile[c][r + q * 8];
        __nv_bfloat16 h = __float2bfloat16(v);
        size_t off = (size_t)(y * 32 + r + q * 8) * 4096 + x * 32 + c;
        g_BThi[off] = h;
        g_BTlo[off] = __float2bfloat16(v - __bfloat162float(h));
    }
}

__global__ void k_trT(const float* __restrict__ T) {
    __shared__ float tile[32][33];
    int x = blockIdx.x, y = blockIdx.y, k = blockIdx.z, t = threadIdx.x;
    int r = t >> 5, c = t & 31;
    const float* src = T + k * 131072;
    #pragma unroll
    for (int q = 0; q < 4; q++)
        tile[r + q * 8][c] = src[(y * 32 + r + q * 8) * 1024 + x * 32 + c];
    __syncthreads();
    #pragma unroll
    for (int q = 0; q < 4; q++) {
        float v = tile[c][r + q * 8];
        __nv_bfloat16 h = __float2bfloat16(v);
        size_t off = (size_t)k * 131072 + (size_t)(x * 32 + r + q * 8) * 128 + y * 32 + c;
        g_TThi[off] = h;
        g_TTlo[off] = __float2bfloat16(v - __bfloat162float(h));
    }
}

__global__ void k_transE(const float* __restrict__ E) {
    __shared__ float tile[128][33];
    int v0 = blockIdx.x * 128, d0 = blockIdx.y * 32, t = threadIdx.x;
    for (int idx = t; idx < 4096; idx += 256) {
        int r = idx >> 5, c = idx & 31;
        tile[r][c] = E[(size_t)(v0 + r) * 128 + d0 + c];
    }
    __syncthreads();
    for (int idx = t; idx < 4096; idx += 256) {
        int d = idx >> 7, vv = idx & 127;
        float x = tile[vv][d];
        __nv_bfloat16 h = __float2bfloat16(x);
        g_EThi[(size_t)(d0 + d) * 32000 + v0 + vv] = h;
        g_ETlo[(size_t)(d0 + d) * 32000 + v0 + vv] = __float2bfloat16(x - __bfloat162float(h));
    }
}

__global__ void k_splitE(const float* __restrict__ E) {
    int v0 = blockIdx.x * 128, t = threadIdx.x;
    int row = t >> 1, half = t & 1;
    const float* src = E + (size_t)(v0 + row) * 128 + half * 64;
    size_t dstoff = (size_t)(v0 + row) * 128 + half * 64;
    #pragma unroll
    for (int q = 0; q < 16; q++) {
        float4 v = *(const float4*)(src + q * 4);
        __nv_bfloat162 h01, l01, h23, l23;
        split2(v.x, v.y, h01, l01);
        split2(v.z, v.w, h23, l23);
        *(__nv_bfloat162*)&g_Ehi[dstoff + q * 4]     = h01;
        *(__nv_bfloat162*)&g_Ehi[dstoff + q * 4 + 2] = h23;
        *(__nv_bfloat162*)&g_Elo[dstoff + q * 4]     = l01;
        *(__nv_bfloat162*)&g_Elo[dstoff + q * 4 + 2] = l23;
    }
}

__global__ void k_midx(const int* __restrict__ mask, const int* __restrict__ mmask) {
    __shared__ int pref[512];
    int t = threadIdx.x;
    int f = (mmask[t] != 0 && mask[t] != 0) ? 1 : 0;
    pref[t] = f;
    __syncthreads();
    for (int o = 1; o < 512; o <<= 1) {
        int v = (t >= o) ? pref[t - o] : 0;
        __syncthreads();
        pref[t] += v;
        __syncthreads();
    }
    if (f) { int pos = pref[t] - 1; g_midx[pos] = t; g_mpos[t] = pos; }
    else g_mpos[t] = -1;
    if (t == 511) g_mcount = pref[511];
}

__device__ __forceinline__ float softmax128(float raw, float* r1, float* r2) {
    int lane = threadIdx.x & 31, w = threadIdx.x >> 5;
    float m = raw;
    #pragma unroll
    for (int o = 16; o; o >>= 1) m = fmaxf(m, __shfl_xor_sync(~0u, m, o));
    if (lane == 0) r1[w] = m;
    __syncthreads();
    m = fmaxf(fmaxf(r1[0], r1[1]), fmaxf(r1[2], r1[3]));
    float e = fexp_s(raw - m), s = e;
    #pragma unroll
    for (int o = 16; o; o >>= 1) s += __shfl_xor_sync(~0u, s, o);
    if (lane == 0) r2[w] = s;
    __syncthreads();
    return e / (r2[0] + r2[1] + r2[2] + r2[3]);
}

__global__ void k_init_qz(const float* __restrict__ x, const int* __restrict__ mask,
                          const int* __restrict__ mmask) {
    int zi = blockIdx.x, a = threadIdx.x;
    __shared__ float r1[4], r2[4];
    float keep = mask[zi] ? 1.f : 0.f;
    float mm = (float)mmask[zi];
    float raw = (x[zi * 128 + a] * (1.f - mm) + g_emean[a] * mm) * keep;
    float p = softmax128(raw, r1, r2);
    g_qz[zi * 128 + a] = p * keep;
}

__global__ void k_trqz() {
    __shared__ float tile[32][33];
    int z = blockIdx.x;
    int ti = blockIdx.y >> 2, tj = blockIdx.y & 3;
    int t = threadIdx.x;
    int r = t >> 5, c = t & 31;
    const float* src = g_qz + z * 16384;
    #pragma unroll
    for (int q = 0; q < 4; q++)
        tile[r + q * 8][c] = src[(ti * 32 + r + q * 8) * 128 + tj * 32 + c];
    __syncthreads();
    #pragma unroll
    for (int q = 0; q < 4; q++) {
        float v = tile[c][r + q * 8];
        __nv_bfloat16 h = __float2bfloat16(v);
        int off = z * 16384 + (tj * 32 + r + q * 8) * 128 + ti * 32 + c;
        g_qzThi[off] = h;
        g_qzTlo[off] = __float2bfloat16(v - __bfloat162float(h));
    }
}

// ==================== generic mma helpers ====================
__device__ __forceinline__ void load_splitA(__nv_bfloat16* Ah, __nv_bfloat16* Al,
                                            const float* src0, size_t srcStride, int t) {
    int row = t >> 1, half = t & 1;
    const float* src = src0 + (size_t)row * srcStride + half * 64;
    int dof = row * 136 + half * 64;
    #pragma unroll
    for (int q = 0; q < 16; q++) {
        float4 v = *(const float4*)(src + q * 4);
        __nv_bfloat162 h01, l01, h23, l23;
        split2(v.x, v.y, h01, l01);
        split2(v.z, v.w, h23, l23);
        *(__nv_bfloat162*)&Ah[dof + q * 4]     = h01;
        *(__nv_bfloat162*)&Ah[dof + q * 4 + 2] = h23;
        *(__nv_bfloat162*)&Al[dof + q * 4]     = l01;
        *(__nv_bfloat162*)&Al[dof + q * 4 + 2] = l23;
    }
}
__device__ __forceinline__ void load_preB(__nv_bfloat16* Bh, __nv_bfloat16* Bl,
                                          const __nv_bfloat16* srcH, const __nv_bfloat16* srcL,
                                          size_t srcStride, int t) {
    int row = t >> 1, half = t & 1;
    size_t soff = (size_t)row * srcStride + half * 64;
    int dof = row * 136 + half * 64;
    #pragma unroll
    for (int q = 0; q < 8; q++) {
        *(uint4*)&Bh[dof + q * 8] = *(const uint4*)&srcH[soff + q * 8];
        *(uint4*)&Bl[dof + q * 8] = *(const uint4*)&srcL[soff + q * 8];
    }
}
__device__ __forceinline__ void mma_core(float c[2][8][4],
        const __nv_bfloat16* Ah, const __nv_bfloat16* Al,
        const __nv_bfloat16* Bh, const __nv_bfloat16* Bl, int lane, int warp) {
    int wy = warp >> 1, wx = warp & 1;
    int g = lane >> 2, tig = lane & 3;
    #pragma unroll
    for (int ks = 0; ks < 8; ks++) {
        int k0 = ks * 16;
        uint32_t aH[2][4], aL[2][4];
        #pragma unroll
        for (int mt = 0; mt < 2; mt++) {
            int base = (wy * 32 + mt * 16 + g) * 136 + k0;
            aH[mt][0] = *(uint32_t*)&Ah[base + tig * 2];
            aH[mt][1] = *(uint32_t*)&Ah[base + 8 * 136 + tig * 2];
            aH[mt][2] = *(uint32_t*)&Ah[base + tig * 2 + 8];
            aH[mt][3] = *(uint32_t*)&Ah[base + 8 * 136 + tig * 2 + 8];
            aL[mt][0] = *(uint32_t*)&Al[base + tig * 2];
            aL[mt][1] = *(uint32_t*)&Al[base + 8 * 136 + tig * 2];
            aL[mt][2] = *(uint32_t*)&Al[base + tig * 2 + 8];
            aL[mt][3] = *(uint32_t*)&Al[base + 8 * 136 + tig * 2 + 8];
        }
        #pragma unroll
        for (int vt = 0; vt < 8; vt++) {
            int basev = (wx * 64 + vt * 8 + g) * 136 + k0;
            uint32_t bH[2] = {*(uint32_t*)&Bh[basev + tig * 2], *(uint32_t*)&Bh[basev + tig * 2 + 8]};
            uint32_t bL[2] = {*(uint32_t*)&Bl[basev + tig * 2], *(uint32_t*)&Bl[basev + tig * 2 + 8]};
            #pragma unroll
            for (int mt = 0; mt < 2; mt++) {
                mma16816(c[mt][vt], aH[mt], bH);
                mma16816(c[mt][vt], aH[mt], bL);
                mma16816(c[mt][vt], aL[mt], bH);
            }
        }
    }
}

#define STD_SMEM (4 * 128 * 136 * 2)

// ---- U = qz @ T[k] ----
__global__ void __launch_bounds__(256) k_U_h() {
    extern __shared__ __nv_bfloat16 sb[];
    __nv_bfloat16 *Ah = sb, *Al = sb + 128 * 136, *Bh = sb + 2 * 128 * 136, *Bl = sb + 3 * 128 * 136;
    int t = threadIdx.x;
    int n0 = blockIdx.x * 128, m0 = blockIdx.y * 128, kk = blockIdx.z;
    load_splitA(Ah, Al, g_qz + (size_t)m0 * 128, 128, t);
    load_preB(Bh, Bl, g_TThi + (size_t)kk * 131072 + (size_t)n0 * 128,
                      g_TTlo + (size_t)kk * 131072 + (size_t)n0 * 128, 128, t);
    __syncthreads();
    int lane = t & 31, warp = t >> 5;
    float c[2][8][4];
    #pragma unroll
    for (int i = 0; i < 2; i++)
        #pragma unroll
        for (int j = 0; j < 8; j++)
            #pragma unroll
            for (int q = 0; q < 4; q++) c[i][j][q] = 0.f;
    mma_core(c, Ah, Al, Bh, Bl, lane, warp);
    int wy = warp >> 1, wx = warp & 1, g = lane >> 2, tig = lane & 3;
    float* C = g_U + (size_t)kk * 524288;
    #pragma unroll
    for (int mt = 0; mt < 2; mt++)
        #pragma unroll
        for (int vt = 0; vt < 8; vt++) {
            int r0 = m0 + wy * 32 + mt * 16 + g;
            int cc = n0 + wx * 64 + vt * 8 + tig * 2;
            *(float2*)&C[(size_t)r0 * 1024 + cc]       = make_float2(c[mt][vt][0], c[mt][vt][1]);
            *(float2*)&C[(size_t)(r0 + 8) * 1024 + cc] = make_float2(c[mt][vt][2], c[mt][vt][3]);
        }
}

// ---- re-layout U[k][zi][b*8+c] -> Uf[k][z][(i*8+c)][b] bf16 hi/lo. grid 1024, 128 thr ----
__global__ void __launch_bounds__(128) k_trU() {
    __shared__ float sh2[8 * 132];
    int blk = blockIdx.x;
    int k = blk >> 9, zi = blk & 511;
    int z = zi >> 7, i = zi & 127;
    int t = threadIdx.x;
    const float* src = g_U + (size_t)k * 524288 + (size_t)zi * 1024;
    #pragma unroll
    for (int q = 0; q < 8; q++) {
        int bc = t + q * 128;
        sh2[(bc & 7) * 132 + (bc >> 3)] = src[bc];
    }
    __syncthreads();
    size_t base = ((size_t)(k * 4 + z) * 1024 + i * 8) * 128;
    #pragma unroll
    for (int c = 0; c < 8; c++) {
        float v = sh2[c * 132 + t];
        __nv_bfloat16 h = __float2bfloat16(v);
        g_Ufhi[base + c * 128 + t] = h;
        g_Uflo[base + c * 128 + t] = __float2bfloat16(v - __bfloat162float(h));
    }
}

// ---- F = Uf @ qz^T : grid (8 mtile, 4 z, 2 k) ----
__global__ void __launch_bounds__(256) k_Fg() {
    extern __shared__ __nv_bfloat16 sb[];
    __nv_bfloat16 *Ah = sb, *Al = sb + 128 * 136, *Bh = sb + 2 * 128 * 136, *Bl = sb + 3 * 128 * 136;
    int t = threadIdx.x;
    int m0 = blockIdx.x * 128, z = blockIdx.y, k = blockIdx.z;
    size_t ubase = ((size_t)(k * 4 + z) * 1024 + m0) * 128;
    load_preB(Ah, Al, g_Ufhi + ubase, g_Uflo + ubase, 128, t);
    load_splitA(Bh, Bl, g_qz + (size_t)z * 16384, 128, t);
    __syncthreads();
    int lane = t & 31, warp = t >> 5;
    float c[2][8][4];
    #pragma unroll
    for (int i = 0; i < 2; i++)
        #pragma unroll
        for (int j = 0; j < 8; j++)
            #pragma unroll
            for (int q = 0; q < 4; q++) c[i][j][q] = 0.f;
    mma_core(c, Ah, Al, Bh, Bl, lane, warp);
    int wy = warp >> 1, wx = warp & 1, g = lane >> 2, tig = lane & 3;
    float* C = g_F + (size_t)(k * 4 + z) * 131072;
    #pragma unroll
    for (int mt = 0; mt < 2; mt++)
        #pragma unroll
        for (int vt = 0; vt < 8; vt++) {
            int r0 = m0 + wy * 32 + mt * 16 + g;
            int cc = wx * 64 + vt * 8 + tig * 2;
            *(float2*)&C[(size_t)r0 * 128 + cc]       = make_float2(c[mt][vt][0], c[mt][vt][1]);
            *(float2*)&C[(size_t)(r0 + 8) * 128 + cc] = make_float2(c[mt][vt][2], c[mt][vt][3]);
        }
}

// ---- select + mask + row softmax -> qhn. grid 512, 256 thr ----
__global__ void __launch_bounds__(256) k_Fsm(const int* __restrict__ mask) {
    int zi = blockIdx.x, z = zi >> 7, i = zi & 127;
    int t = threadIdx.x;
    __shared__ float qh_sh[8][128];
    __shared__ float smax[8], ssum[8];
    int j = t & 127, ch = t >> 7;
    bool vi = mask[z * 128 + i] != 0, vj = mask[z * 128 + j] != 0;
    int ksel = (j > i) ? 0 : 1;
    const float* Fb = g_F + (size_t)(ksel * 4 + z) * 131072 + (size_t)(i * 8) * 128;
    float vals[4];
    #pragma unroll
    for (int hh = 0; hh < 4; hh++) {
        int c = ch * 4 + hh;
        float v = Fb[c * 128 + j];
        if (i == j || !vi || !vj) v = -NEGC;
        vals[hh] = v;
        qh_sh[c][j] = v;
    }
    __syncthreads();
    int w = t >> 5, lane = t & 31;
    float v0 = qh_sh[w][lane], v1 = qh_sh[w][lane + 32];
    float v2 = qh_sh[w][lane + 64], v3 = qh_sh[w][lane + 96];
    float mx = fmaxf(fmaxf(v0, v1), fmaxf(v2, v3));
    #pragma unroll
    for (int o = 16; o; o >>= 1) mx = fmaxf(mx, __shfl_xor_sync(~0u, mx, o));
    float sum = fexp_s(v0 - mx) + fexp_s(v1 - mx) + fexp_s(v2 - mx) + fexp_s(v3 - mx);
    #pragma unroll
    for (int o = 16; o; o >>= 1) sum += __shfl_xor_sync(~0u, sum, o);
    if (lane == 0) { smax[w] = mx; ssum[w] = sum; }
    __syncthreads();
    #pragma unroll
    for (int hh = 0; hh < 4; hh++) {
        int h = ch * 4 + hh;
        float p = fexp_s(vals[hh] - smax[h]) / ssum[h];
        g_qhn[(((z * 8 + h) * 128 + i) << 7) + j] = p;
    }
}

// ---- Gpart = S @ BmatT (split-K 32) ----
__global__ void __launch_bounds__(256) k_g_h() {
    extern __shared__ __nv_bfloat16 sb[];
    __nv_bfloat16 *Ah = sb, *Al = sb + 128 * 136, *Bh = sb + 2 * 128 * 136, *Bl = sb + 3 * 128 * 136;
    int t = threadIdx.x;
    int m0 = blockIdx.x * 128, kb = blockIdx.y * 128;
    load_splitA(Ah, Al, g_S + (size_t)m0 * 4096 + kb, 4096, t);
    load_preB(Bh, Bl, g_BThi + kb, g_BTlo + kb, 4096, t);
    __syncthreads();
    int lane = t & 31, warp = t >> 5;
    float c[2][8][4];
    #pragma unroll
    for (int i = 0; i < 2; i++)
        #pragma unroll
        for (int j = 0; j < 8; j++)
            #pragma unroll
            for (int q = 0; q < 4; q++) c[i][j][q] = 0.f;
    mma_core(c, Ah, Al, Bh, Bl, lane, warp);
    int wy = warp >> 1, wx = warp & 1, g = lane >> 2, tig = lane & 3;
    #pragma unroll
    for (int mt = 0; mt < 2; mt++)
        #pragma unroll
        for (int vt = 0; vt < 8; vt++) {
            int r0 = m0 + wy * 32 + mt * 16 + g;
            int cc = wx * 64 + vt * 8 + tig * 2;
            *(float2*)&g_Gpart[((size_t)blockIdx.y * 512 + r0) * 128 + cc] =
                make_float2(c[mt][vt][0], c[mt][vt][1]);
            *(float2*)&g_Gpart[((size_t)blockIdx.y * 512 + r0 + 8) * 128 + cc] =
                make_float2(c[mt][vt][2], c[mt][vt][3]);
        }
}

// ---- S = W(32x128) @ qz(128x128) per zi ----
#define SH2_SMEM ((32 * 136 * 2 + 2 * 128 * 136) * 2)
__global__ void __launch_bounds__(256) k_S_h() {
    extern __shared__ __nv_bfloat16 sb[];
    __nv_bfloat16 *Wh = sb, *Wl = sb + 32 * 136;
    __nv_bfloat16 *Bh = sb + 64 * 136, *Bl = sb + 64 * 136 + 128 * 136;
    int zi = blockIdx.x, z = zi >> 7, i = zi & 127;
    int t = threadIdx.x;
    for (int idx = t; idx < 4096; idx += 256) {
        int r = idx >> 7, j = idx & 127;
        float v; bool m;
        if (r < 16) {
            int k = r >> 3, c = r & 7;
            v = g_qhn[(((z * 8 + c) * 128 + i) << 7) + j];
            m = (k == 0) ? (j > i) : (j < i);
        } else {
            int r2 = r - 16, k = r2 >> 3, c = r2 & 7;
            v = g_qhnT[(((z * 8 + c) * 128 + i) << 7) + j];
            m = (k == 0) ? (j < i) : (j > i);
        }
        v = m ? v : 0.f;
        __nv_bfloat16 h = __float2bfloat16(v);
        Wh[r * 136 + j] = h;
        Wl[r * 136 + j] = __float2bfloat16(v - __bfloat162float(h));
    }
    load_preB(Bh, Bl, g_qzThi + z * 16384, g_qzTlo + z * 16384, 128, t);
    __syncthreads();
    int lane = t & 31, warp = t >> 5;
    int wy = warp >> 2, wx = warp & 3;
    int g = lane >> 2, tig = lane & 3;
    float c[4][4];
    #pragma unroll
    for (int j = 0; j < 4; j++)
        #pragma unroll
        for (int q = 0; q < 4; q++) c[j][q] = 0.f;
    #pragma unroll
    for (int ks = 0; ks < 8; ks++) {
        int k0 = ks * 16;
        uint32_t aH[4], aL[4];
        int base = (wy * 16 + g) * 136 + k0;
        aH[0] = *(uint32_t*)&Wh[base + tig * 2];
        aH[1] = *(uint32_t*)&Wh[base + 8 * 136 + tig * 2];
        aH[2] = *(uint32_t*)&Wh[base + tig * 2 + 8];
        aH[3] = *(uint32_t*)&Wh[base + 8 * 136 + tig * 2 + 8];
        aL[0] = *(uint32_t*)&Wl[base + tig * 2];
        aL[1] = *(uint32_t*)&Wl[base + 8 * 136 + tig * 2];
        aL[2] = *(uint32_t*)&Wl[base + tig * 2 + 8];
        aL[3] = *(uint32_t*)&Wl[base + 8 * 136 + tig * 2 + 8];
        #pragma unroll
        for (int vt = 0; vt < 4; vt++) {
            int basev = (wx * 32 + vt * 8 + g) * 136 + k0;
            uint32_t bH[2] = {*(uint32_t*)&Bh[basev + tig * 2], *(uint32_t*)&Bh[basev + tig * 2 + 8]};
            uint32_t bL[2] = {*(uint32_t*)&Bl[basev + tig * 2], *(uint32_t*)&Bl[basev + tig * 2 + 8]};
            mma16816(c[vt], aH, bH);
            mma16816(c[vt], aH, bL);
            mma16816(c[vt], aL, bH);
        }
    }
    #pragma unroll
    for (int vt = 0; vt < 4; vt++) {
        int r0 = wy * 16 + g;
        int cc = wx * 32 + vt * 8 + tig * 2;
        int base0 = (r0 < 16) ? r0 * 128 : 2048 + (r0 - 16) * 128;
        int r1 = r0 + 8;
        int base1 = (r1 < 16) ? r1 * 128 : 2048 + (r1 - 16) * 128;
        *(float2*)&g_S[(size_t)zi * 4096 + base0 + cc] = make_float2(c[vt][0], c[vt][1]);
        *(float2*)&g_S[(size_t)zi * 4096 + base1 + cc] = make_float2(c[vt][2], c[vt][3]);
    }
}

__global__ void __launch_bounds__(256) k_trq() {
    __shared__ float tile[32][33];
    int zh = blockIdx.x;
    int ti = blockIdx.y >> 2, tj = blockIdx.y & 3;
    int t = threadIdx.x;
    int r = t >> 5, c = t & 31;
    const float* src = g_qhn + ((size_t)zh << 14);
    float* dst = g_qhnT + ((size_t)zh << 14);
    #pragma unroll
    for (int q = 0; q < 4; q++)
        tile[r + q * 8][c] = src[(ti * 32 + r + q * 8) * 128 + tj * 32 + c];
    __syncthreads();
    #pragma unroll
    for (int q = 0; q < 4; q++)
        dst[(tj * 32 + r + q * 8) * 128 + ti * 32 + c] = tile[c][r + q * 8];
}

__global__ void k_sered() {
    int count = g_mcount;
    int pos = blockIdx.x;
    if (pos >= count) return;
    int ntiles = (count + 127) >> 7;
    int mt = pos >> 7, row = pos & 127;
    int gb0 = (mt * 148 + ntiles - 1) / ntiles;
    int gb1 = ((mt + 1) * 148 + ntiles - 1) / ntiles;
    int d = threadIdx.x;
    float num = 0.f, den = 0.f;
    for (int bb = gb0; bb < gb1; bb++) {
        num += g_SEpart[((size_t)bb * 128 + row) * 128 + d];
        den += g_SEsum[bb * 128 + row];
    }
    g_SE[pos * 128 + d] = num / den;
}

__global__ void k_zupd(const float* __restrict__ x, const int* __restrict__ mask,
                       const int* __restrict__ mmask, int useSE) {
    int zi = blockIdx.x, d = threadIdx.x;
    __shared__ float r1[4], r2[4];
    float g = 0.f;
    #pragma unroll 8
    for (int p = 0; p < 32; p++) g += g_Gpart[((size_t)p * 512 + zi) * 128 + d];
    float mm = (float)mmask[zi];
    float se = 0.f;
    if (mm != 0.f) {
        if (useSE) {
            int pos = g_mpos[zi];
            if (pos >= 0) se = g_SE[pos * 128 + d];
        } else se = g_emean[d];
    }
    float raw = x[zi * 128 + d] * (1.f - mm) + se * mm + g;
    float keep = mask[zi] ? 1.f : 0.f;
    float p_ = softmax128(raw, r1, r2);
    g_qz[zi * 128 + d] = p_ * keep;
}

// ==================== fused SE via mma ====================
#define SH_T 17408
#define SEFH_SMEM (6 * SH_T * 2 + 1024)

__global__ void __launch_bounds__(256) k_sef_h() {
    int count = g_mcount;
    if (count == 0) return;
    int ntiles = (count + 127) >> 7;
    int b = blockIdx.x;
    int mt_ = (b * ntiles) / 148;
    int gb0 = (mt_ * 148 + ntiles - 1) / ntiles;
    int gb1 = ((mt_ + 1) * 148 + ntiles - 1) / ntiles;
    int gsz = gb1 - gb0, li = b - gb0;
    int ustart = (li * 250) / gsz;
    int ucount = ((li + 1) * 250) / gsz - ustart;
    int m0 = mt_ * 128;

    extern __shared__ __nv_bfloat16 shb[];
    __nv_bfloat16* Ah = shb;
    __nv_bfloat16* Al = shb + SH_T;
    __nv_bfloat16* Bh = shb + 2 * SH_T;
    __nv_bfloat16* Bl = shb + 3 * SH_T;
    __nv_bfloat16* Ph = shb + 4 * SH_T;
    __nv_bfloat16* Pl = shb + 5 * SH_T;
    float* psum_s = (float*)(shb + 6 * SH_T);

    int t = threadIdx.x;
    {
        int row = t >> 1, half = t & 1;
        int pos = m0 + row;
        int zi = (pos < count) ? g_midx[pos] : 0;
        const float* src = g_qz + (size_t)zi * 128 + half * 64;
        int dof = row * 136 + half * 64;
        #pragma unroll
        for (int q = 0; q < 16; q++) {
            float4 v = *(const float4*)(src + q * 4);
            __nv_bfloat162 h01, l01, h23, l23;
            split2(v.x, v.y, h01, l01);
            split2(v.z, v.w, h23, l23);
            *(__nv_bfloat162*)&Ah[dof + q * 4]     = h01;
            *(__nv_bfloat162*)&Ah[dof + q * 4 + 2] = h23;
            *(__nv_bfloat162*)&Al[dof + q * 4]     = l01;
            *(__nv_bfloat162*)&Al[dof + q * 4 + 2] = l23;
        }
    }

    int lane = t & 31, warp = t >> 5;
    int wy = warp >> 1, wx = warp & 1;
    int g = lane >> 2, tig = lane & 3;
    float c2[2][8][4];
    #pragma unroll
    for (int i = 0; i < 2; i++)
        #pragma unroll
        for (int j = 0; j < 8; j++)
            #pragma unroll
            for (int q = 0; q < 4; q++) c2[i][j][q] = 0.f;
    float psr[2][2] = {{0.f, 0.f}, {0.f, 0.f}};

    for (int tile = 0; tile < ucount; tile++) {
        int vg = (ustart + tile) * 128;
        __syncthreads();
        load_preB(Bh, Bl, g_Ehi + (size_t)vg * 128, g_Elo + (size_t)vg * 128, 128, t);
        __syncthreads();
        float c1[2][8][4];
        #pragma unroll
        for (int i = 0; i < 2; i++)
            #pragma unroll
            for (int j = 0; j < 8; j++)
                #pragma unroll
                for (int q = 0; q < 4; q++) c1[i][j][q] = 0.f;
        mma_core(c1, Ah, Al, Bh, Bl, lane, warp);
        #pragma unroll
        for (int mt = 0; mt < 2; mt++)
            #pragma unroll
            for (int vt = 0; vt < 8; vt++) {
                float e0 = fexp(c1[mt][vt][0]), e1 = fexp(c1[mt][vt][1]);
                float e2 = fexp(c1[mt][vt][2]), e3 = fexp(c1[mt][vt][3]);
                psr[mt][0] += e0 + e1;
                psr[mt][1] += e2 + e3;
                int r0 = wy * 32 + mt * 16 + g;
                int col = wx * 64 + vt * 8 + tig * 2;
                __nv_bfloat162 h01, l01, h23, l23;
                split2(e0, e1, h01, l01);
                split2(e2, e3, h23, l23);
                *(__nv_bfloat162*)&Ph[r0 * 136 + col] = h01;
                *(__nv_bfloat162*)&Pl[r0 * 136 + col] = l01;
                *(__nv_bfloat162*)&Ph[(r0 + 8) * 136 + col] = h23;
                *(__nv_bfloat162*)&Pl[(r0 + 8) * 136 + col] = l23;
            }
        __syncthreads();
        load_preB(Bh, Bl, g_EThi + vg, g_ETlo + vg, 32000, t);
        __syncthreads();
        mma_core(c2, Ph, Pl, Bh, Bl, lane, warp);
    }
    #pragma unroll
    for (int mt = 0; mt < 2; mt++)
        #pragma unroll
        for (int dt = 0; dt < 8; dt++) {
            int r0 = wy * 32 + mt * 16 + g;
            int col = wx * 64 + dt * 8 + tig * 2;
            *(float2*)&g_SEpart[((size_t)b * 128 + r0) * 128 + col] =
                make_float2(c2[mt][dt][0], c2[mt][dt][1]);
            *(float2*)&g_SEpart[((size_t)b * 128 + r0 + 8) * 128 + col] =
                make_float2(c2[mt][dt][2], c2[mt][dt][3]);
        }
    #pragma unroll
    for (int mt = 0; mt < 2; mt++)
        #pragma unroll
        for (int h = 0; h < 2; h++) {
            float v = psr[mt][h];
            v += __shfl_xor_sync(~0u, v, 1);
            v += __shfl_xor_sync(~0u, v, 2);
            psr[mt][h] = v;
        }
    if (tig == 0) {
        #pragma unroll
        for (int mt = 0; mt < 2; mt++)
            #pragma unroll
            for (int h = 0; h < 2; h++)
                psum_s[wx * 128 + wy * 32 + mt * 16 + g + h * 8] = psr[mt][h];
    }
    __syncthreads();
    if (t < 128) g_SEsum[b * 128 + t] = psum_s[t] + psum_s[128 + t];
}

// ==================== final out = qz @ E^T ====================
__global__ void __launch_bounds__(256) k_msg_h(float* __restrict__ out) {
    extern __shared__ __nv_bfloat16 smh[];
    __nv_bfloat16 *Ah = smh, *Al = smh + 128 * 136, *Bh = smh + 2 * 128 * 136, *Bl = smh + 3 * 128 * 136;
    int t = threadIdx.x;
    int v0 = blockIdx.x * 128, m0 = blockIdx.y * 128;
    load_splitA(Ah, Al, g_qz + (size_t)m0 * 128, 128, t);
    load_preB(Bh, Bl, g_Ehi + (size_t)v0 * 128, g_Elo + (size_t)v0 * 128, 128, t);
    __syncthreads();
    int lane = t & 31, warp = t >> 5;
    float c[2][8][4];
    #pragma unroll
    for (int i = 0; i < 2; i++)
        #pragma unroll
        for (int j = 0; j < 8; j++)
            #pragma unroll
            for (int q = 0; q < 4; q++) c[i][j][q] = 0.f;
    mma_core(c, Ah, Al, Bh, Bl, lane, warp);
    int wy = warp >> 1, wx = warp & 1, g = lane >> 2, tig = lane & 3;
    #pragma unroll
    for (int mt = 0; mt < 2; mt++)
        #pragma unroll
        for (int vt = 0; vt < 8; vt++) {
            int r0 = m0 + wy * 32 + mt * 16 + g;
            int cc = v0 + wx * 64 + vt * 8 + tig * 2;
            *(float2*)&out[(size_t)r0 * 32000 + cc]       = make_float2(c[mt][vt][0], c[mt][vt][1]);
            *(float2*)&out[(size_t)(r0 + 8) * 32000 + cc] = make_float2(c[mt][vt][2], c[mt][vt][3]);
        }
}

// ==================== launch ====================
extern "C" void kernel_launch(void* const* d_in, const int* in_sizes, int n_in,
                              void* d_out, int out_size) {
    const float* x    = (const float*)d_in[0];
    const int*   mask = (const int*)d_in[1];
    const float* E    = (const float*)d_in[2];
    const int*   mm   = (const int*)d_in[3];
    const float* T    = (const float*)d_in[4];
    float* out = (float*)d_out;

    static cudaStream_t s2 = nullptr;
    static cudaEvent_t eF = nullptr, eJ = nullptr;
    if (!s2) {
        cudaStreamCreate(&s2);
        cudaEventCreateWithFlags(&eF, cudaEventDisableTiming);
        cudaEventCreateWithFlags(&eJ, cudaEventDisableTiming);
        cudaFuncSetAttribute(k_sef_h, cudaFuncAttributeMaxDynamicSharedMemorySize, SEFH_SMEM);
        cudaFuncSetAttribute(k_msg_h, cudaFuncAttributeMaxDynamicSharedMemorySize, STD_SMEM);
        cudaFuncSetAttribute(k_U_h,   cudaFuncAttributeMaxDynamicSharedMemorySize, STD_SMEM);
        cudaFuncSetAttribute(k_Fg,    cudaFuncAttributeMaxDynamicSharedMemorySize, STD_SMEM);
        cudaFuncSetAttribute(k_g_h,   cudaFuncAttributeMaxDynamicSharedMemorySize, STD_SMEM);
        cudaFuncSetAttribute(k_S_h,   cudaFuncAttributeMaxDynamicSharedMemorySize, SH2_SMEM);
    }
    cudaStream_t s0 = 0;

    cudaEventRecord(eF, s0);
    cudaStreamWaitEvent(s2, eF, 0);
    k_transE<<<dim3(250, 4), 256, 0, s2>>>(E);
    k_splitE<<<250, 256, 0, s2>>>(E);

    k_emean_part<<<64, 256, 0, s0>>>(E);
    k_emean_red<<<1, 128, 0, s0>>>();
    k_bmat<<<2048, 256, 0, s0>>>(T);
    k_trB<<<dim3(128, 4), 256, 0, s0>>>();
    k_trT<<<dim3(32, 4, 2), 256, 0, s0>>>(T);
    k_midx<<<1, 512, 0, s0>>>(mask, mm);
    k_init_qz<<<512, 128, 0, s0>>>(x, mask, mm);

    for (int it = 0; it < 4; it++) {
        k_U_h<<<dim3(8, 4, 2), 256, STD_SMEM, s0>>>();
        k_trU<<<1024, 128, 0, s0>>>();
        k_Fg<<<dim3(8, 4, 2), 256, STD_SMEM, s0>>>();
        k_Fsm<<<512, 256, 0, s0>>>(mask);
        k_trq<<<dim3(32, 16), 256, 0, s0>>>();
        k_trqz<<<dim3(4, 16), 256, 0, s0>>>();
        k_S_h<<<512, 256, SH2_SMEM, s0>>>();
        k_g_h<<<dim3(4, 32), 256, STD_SMEM, s0>>>();
        if (it > 0) cudaStreamWaitEvent(s0, eJ, 0);
        k_zupd<<<512, 128, 0, s0>>>(x, mask, mm, it > 0);
        if (it < 3) {
            cudaEventRecord(eF, s0);
            cudaStreamWaitEvent(s2, eF, 0);
            k_sef_h<<<148, 256, SEFH_SMEM, s2>>>();
            k_sered<<<512, 128, 0, s2>>>();
            cudaEventRecord(eJ, s2);
        } else {
            k_msg_h<<<dim3(250, 4), 256, STD_SMEM, s0>>>(out);
        }
    }
}

// round 17
// speedup vs baseline: 1.5863x; 1.0153x over previous
#include <cuda_runtime.h>
#include <cuda_bf16.h>
#include <math.h>
#include <stdint.h>

#define NEGC 1.0e9f
typedef unsigned long long ull;

// ==================== static scratch ====================
__device__ float g_epart[64 * 128];
__device__ float g_emean[128];
__device__ float g_Bmat[4096 * 128];
__device__ float g_qz[512 * 128];
__device__ __nv_bfloat16 g_Ufhi[2 * 4 * 1024 * 128];
__device__ __nv_bfloat16 g_Uflo[2 * 4 * 1024 * 128];
__device__ float g_F[2 * 4 * 1024 * 128];
__device__ float g_qhn[4 * 8 * 128 * 128];
__device__ float g_qhnT[4 * 8 * 128 * 128];
__device__ float g_S[512 * 4096];
__device__ float g_Gpart[32 * 512 * 128];
__device__ __nv_bfloat16 g_Ehi[32000 * 128];
__device__ __nv_bfloat16 g_Elo[32000 * 128];
__device__ __nv_bfloat16 g_EThi[128 * 32000];
__device__ __nv_bfloat16 g_ETlo[128 * 32000];
__device__ __nv_bfloat16 g_TThi[2 * 1024 * 128];
__device__ __nv_bfloat16 g_TTlo[2 * 1024 * 128];
__device__ __nv_bfloat16 g_BThi[128 * 4096];
__device__ __nv_bfloat16 g_BTlo[128 * 4096];
__device__ __nv_bfloat16 g_qzThi[4 * 128 * 128];
__device__ __nv_bfloat16 g_qzTlo[4 * 128 * 128];
__device__ float g_SEpart[148 * 128 * 128];
__device__ float g_SEsum[148 * 128];
__device__ float g_SE[512 * 128];
__device__ int   g_midx[512];
__device__ int   g_mpos[512];
__device__ int   g_mcount;

// ---- helpers ----
__device__ __forceinline__ void mma16816(float c[4], const uint32_t a[4], const uint32_t b[2]) {
    asm volatile("mma.sync.aligned.m16n8k16.row.col.f32.bf16.bf16.f32 "
        "{%0,%1,%2,%3}, {%4,%5,%6,%7}, {%8,%9}, {%0,%1,%2,%3};"
        : "+f"(c[0]), "+f"(c[1]), "+f"(c[2]), "+f"(c[3])
        : "r"(a[0]), "r"(a[1]), "r"(a[2]), "r"(a[3]), "r"(b[0]), "r"(b[1]));
}
__device__ __forceinline__ float fexp(float x) {
    float z = x * 1.4426950408889634f;
    float m = z + 12582912.0f;
    int ni = __float_as_int(m) - 0x4B400000;
    float f = z - (m - 12582912.0f);
    float p = 0.0013333558f;
    p = fmaf(p, f, 0.0096181291f);
    p = fmaf(p, f, 0.0555041087f);
    p = fmaf(p, f, 0.2402265070f);
    p = fmaf(p, f, 0.6931471806f);
    p = fmaf(p, f, 1.0f);
    return p * __int_as_float((ni + 127) << 23);
}
__device__ __forceinline__ float fexp_s(float x) { return fexp(fmaxf(x, -80.f)); }
__device__ __forceinline__ void split2(float a, float b, __nv_bfloat162 &h, __nv_bfloat162 &l) {
    h = __floats2bfloat162_rn(a, b);
    l = __floats2bfloat162_rn(a - __bfloat162float(h.x), b - __bfloat162float(h.y));
}

// ==================== setup ====================
__global__ void k_emean_part(const float* __restrict__ E) {
    int b = blockIdx.x, t = threadIdx.x;
    int d = t & 127, h = t >> 7;
    float s = 0.f;
    for (int v = b * 500 + h; v < b * 500 + 500; v += 2) s += E[v * 128 + d];
    __shared__ float sh[256];
    sh[t] = s; __syncthreads();
    if (t < 128) g_epart[b * 128 + t] = sh[t] + sh[t + 128];
}
__global__ void k_emean_red() {
    int t = threadIdx.x;
    float s = 0.f;
    for (int b = 0; b < 64; b++) s += g_epart[b * 128 + t];
    g_emean[t] = s * (1.0f / 32000.0f);
}

__global__ void k_bmat(const float* __restrict__ T) {
    int idx = blockIdx.x * 256 + threadIdx.x;
    if (idx >= 4096 * 128) return;
    int r = idx >> 7, col = idx & 127;
    float val;
    if (r < 2048) {
        int k = r >> 10, c = (r >> 7) & 7, b = r & 127;
        val = T[((k * 128 + col) * 128 + b) * 8 + c];
    } else {
        int r2 = r - 2048;
        int k = r2 >> 10, c = (r2 >> 7) & 7, a = r2 & 127;
        val = T[((k * 128 + a) * 128 + col) * 8 + c];
    }
    g_Bmat[idx] = val;
}

__global__ void k_trB() {
    __shared__ float tile[32][33];
    int x = blockIdx.x, y = blockIdx.y, t = threadIdx.x;
    int r = t >> 5, c = t & 31;
    #pragma unroll
    for (int q = 0; q < 4; q++)
        tile[r + q * 8][c] = g_Bmat[(x * 32 + r + q * 8) * 128 + y * 32 + c];
    __syncthreads();
    #pragma unroll
    for (int q = 0; q < 4; q++) {
        float v = tile[c][r + q * 8];
        __nv_bfloat16 h = __float2bfloat16(v);
        size_t off = (size_t)(y * 32 + r + q * 8) * 4096 + x * 32 + c;
        g_BThi[off] = h;
        g_BTlo[off] = __float2bfloat16(v - __bfloat162float(h));
    }
}

__global__ void k_trT(const float* __restrict__ T) {
    __shared__ float tile[32][33];
    int x = blockIdx.x, y = blockIdx.y, k = blockIdx.z, t = threadIdx.x;
    int r = t >> 5, c = t & 31;
    const float* src = T + k * 131072;
    #pragma unroll
    for (int q = 0; q < 4; q++)
        tile[r + q * 8][c] = src[(y * 32 + r + q * 8) * 1024 + x * 32 + c];
    __syncthreads();
    #pragma unroll
    for (int q = 0; q < 4; q++) {
        float v = tile[c][r + q * 8];
        __nv_bfloat16 h = __float2bfloat16(v);
        size_t off = (size_t)k * 131072 + (size_t)(x * 32 + r + q * 8) * 128 + y * 32 + c;
        g_TThi[off] = h;
        g_TTlo[off] = __float2bfloat16(v - __bfloat162float(h));
    }
}

__global__ void k_transE(const float* __restrict__ E) {
    __shared__ float tile[128][33];
    int v0 = blockIdx.x * 128, d0 = blockIdx.y * 32, t = threadIdx.x;
    for (int idx = t; idx < 4096; idx += 256) {
        int r = idx >> 5, c = idx & 31;
        tile[r][c] = E[(size_t)(v0 + r) * 128 + d0 + c];
    }
    __syncthreads();
    for (int idx = t; idx < 4096; idx += 256) {
        int d = idx >> 7, vv = idx & 127;
        float x = tile[vv][d];
        __nv_bfloat16 h = __float2bfloat16(x);
        g_EThi[(size_t)(d0 + d) * 32000 + v0 + vv] = h;
        g_ETlo[(size_t)(d0 + d) * 32000 + v0 + vv] = __float2bfloat16(x - __bfloat162float(h));
    }
}

__global__ void k_splitE(const float* __restrict__ E) {
    int v0 = blockIdx.x * 128, t = threadIdx.x;
    int row = t >> 1, half = t & 1;
    const float* src = E + (size_t)(v0 + row) * 128 + half * 64;
    size_t dstoff = (size_t)(v0 + row) * 128 + half * 64;
    #pragma unroll
    for (int q = 0; q < 16; q++) {
        float4 v = *(const float4*)(src + q * 4);
        __nv_bfloat162 h01, l01, h23, l23;
        split2(v.x, v.y, h01, l01);
        split2(v.z, v.w, h23, l23);
        *(__nv_bfloat162*)&g_Ehi[dstoff + q * 4]     = h01;
        *(__nv_bfloat162*)&g_Ehi[dstoff + q * 4 + 2] = h23;
        *(__nv_bfloat162*)&g_Elo[dstoff + q * 4]     = l01;
        *(__nv_bfloat162*)&g_Elo[dstoff + q * 4 + 2] = l23;
    }
}

__global__ void k_midx(const int* __restrict__ mask, const int* __restrict__ mmask) {
    __shared__ int pref[512];
    int t = threadIdx.x;
    int f = (mmask[t] != 0 && mask[t] != 0) ? 1 : 0;
    pref[t] = f;
    __syncthreads();
    for (int o = 1; o < 512; o <<= 1) {
        int v = (t >= o) ? pref[t - o] : 0;
        __syncthreads();
        pref[t] += v;
        __syncthreads();
    }
    if (f) { int pos = pref[t] - 1; g_midx[pos] = t; g_mpos[t] = pos; }
    else g_mpos[t] = -1;
    if (t == 511) g_mcount = pref[511];
}

__device__ __forceinline__ float softmax128(float raw, float* r1, float* r2) {
    int lane = threadIdx.x & 31, w = threadIdx.x >> 5;
    float m = raw;
    #pragma unroll
    for (int o = 16; o; o >>= 1) m = fmaxf(m, __shfl_xor_sync(~0u, m, o));
    if (lane == 0) r1[w] = m;
    __syncthreads();
    m = fmaxf(fmaxf(r1[0], r1[1]), fmaxf(r1[2], r1[3]));
    float e = fexp_s(raw - m), s = e;
    #pragma unroll
    for (int o = 16; o; o >>= 1) s += __shfl_xor_sync(~0u, s, o);
    if (lane == 0) r2[w] = s;
    __syncthreads();
    return e / (r2[0] + r2[1] + r2[2] + r2[3]);
}

// init qz + fused qzT emission
__global__ void k_init_qz(const float* __restrict__ x, const int* __restrict__ mask,
                          const int* __restrict__ mmask) {
    int zi = blockIdx.x, a = threadIdx.x;
    __shared__ float r1[4], r2[4];
    float keep = mask[zi] ? 1.f : 0.f;
    float mm = (float)mmask[zi];
    float raw = (x[zi * 128 + a] * (1.f - mm) + g_emean[a] * mm) * keep;
    float p = softmax128(raw, r1, r2);
    float v = p * keep;
    g_qz[zi * 128 + a] = v;
    int z = zi >> 7, i = zi & 127;
    __nv_bfloat16 h = __float2bfloat16(v);
    g_qzThi[z * 16384 + a * 128 + i] = h;
    g_qzTlo[z * 16384 + a * 128 + i] = __float2bfloat16(v - __bfloat162float(h));
}

// ==================== generic mma helpers ====================
__device__ __forceinline__ void load_splitA(__nv_bfloat16* Ah, __nv_bfloat16* Al,
                                            const float* src0, size_t srcStride, int t) {
    int row = t >> 1, half = t & 1;
    const float* src = src0 + (size_t)row * srcStride + half * 64;
    int dof = row * 136 + half * 64;
    #pragma unroll
    for (int q = 0; q < 16; q++) {
        float4 v = *(const float4*)(src + q * 4);
        __nv_bfloat162 h01, l01, h23, l23;
        split2(v.x, v.y, h01, l01);
        split2(v.z, v.w, h23, l23);
        *(__nv_bfloat162*)&Ah[dof + q * 4]     = h01;
        *(__nv_bfloat162*)&Ah[dof + q * 4 + 2] = h23;
        *(__nv_bfloat162*)&Al[dof + q * 4]     = l01;
        *(__nv_bfloat162*)&Al[dof + q * 4 + 2] = l23;
    }
}
__device__ __forceinline__ void load_preB(__nv_bfloat16* Bh, __nv_bfloat16* Bl,
                                          const __nv_bfloat16* srcH, const __nv_bfloat16* srcL,
                                          size_t srcStride, int t) {
    int row = t >> 1, half = t & 1;
    size_t soff = (size_t)row * srcStride + half * 64;
    int dof = row * 136 + half * 64;
    #pragma unroll
    for (int q = 0; q < 8; q++) {
        *(uint4*)&Bh[dof + q * 8] = *(const uint4*)&srcH[soff + q * 8];
        *(uint4*)&Bl[dof + q * 8] = *(const uint4*)&srcL[soff + q * 8];
    }
}
__device__ __forceinline__ void mma_core(float c[2][8][4],
        const __nv_bfloat16* Ah, const __nv_bfloat16* Al,
        const __nv_bfloat16* Bh, const __nv_bfloat16* Bl, int lane, int warp) {
    int wy = warp >> 1, wx = warp & 1;
    int g = lane >> 2, tig = lane & 3;
    #pragma unroll
    for (int ks = 0; ks < 8; ks++) {
        int k0 = ks * 16;
        uint32_t aH[2][4], aL[2][4];
        #pragma unroll
        for (int mt = 0; mt < 2; mt++) {
            int base = (wy * 32 + mt * 16 + g) * 136 + k0;
            aH[mt][0] = *(uint32_t*)&Ah[base + tig * 2];
            aH[mt][1] = *(uint32_t*)&Ah[base + 8 * 136 + tig * 2];
            aH[mt][2] = *(uint32_t*)&Ah[base + tig * 2 + 8];
            aH[mt][3] = *(uint32_t*)&Ah[base + 8 * 136 + tig * 2 + 8];
            aL[mt][0] = *(uint32_t*)&Al[base + tig * 2];
            aL[mt][1] = *(uint32_t*)&Al[base + 8 * 136 + tig * 2];
            aL[mt][2] = *(uint32_t*)&Al[base + tig * 2 + 8];
            aL[mt][3] = *(uint32_t*)&Al[base + 8 * 136 + tig * 2 + 8];
        }
        #pragma unroll
        for (int vt = 0; vt < 8; vt++) {
            int basev = (wx * 64 + vt * 8 + g) * 136 + k0;
            uint32_t bH[2] = {*(uint32_t*)&Bh[basev + tig * 2], *(uint32_t*)&Bh[basev + tig * 2 + 8]};
            uint32_t bL[2] = {*(uint32_t*)&Bl[basev + tig * 2], *(uint32_t*)&Bl[basev + tig * 2 + 8]};
            #pragma unroll
            for (int mt = 0; mt < 2; mt++) {
                mma16816(c[mt][vt], aH[mt], bH);
                mma16816(c[mt][vt], aH[mt], bL);
                mma16816(c[mt][vt], aL[mt], bH);
            }
        }
    }
}

#define STD_SMEM (4 * 128 * 136 * 2)

// ---- U = qz @ T[k] with fused Uf-layout bf16 epilogue ----
__global__ void __launch_bounds__(256) k_U_h() {
    extern __shared__ __nv_bfloat16 sb[];
    __nv_bfloat16 *Ah = sb, *Al = sb + 128 * 136, *Bh = sb + 2 * 128 * 136, *Bl = sb + 3 * 128 * 136;
    int t = threadIdx.x;
    int n0 = blockIdx.x * 128, z = blockIdx.y, kk = blockIdx.z;
    int m0 = z * 128;
    load_splitA(Ah, Al, g_qz + (size_t)m0 * 128, 128, t);
    load_preB(Bh, Bl, g_TThi + (size_t)kk * 131072 + (size_t)n0 * 128,
                      g_TTlo + (size_t)kk * 131072 + (size_t)n0 * 128, 128, t);
    __syncthreads();
    int lane = t & 31, warp = t >> 5;
    float c[2][8][4];
    #pragma unroll
    for (int i = 0; i < 2; i++)
        #pragma unroll
        for (int j = 0; j < 8; j++)
            #pragma unroll
            for (int q = 0; q < 4; q++) c[i][j][q] = 0.f;
    mma_core(c, Ah, Al, Bh, Bl, lane, warp);
    __syncthreads();   // done reading smem operands
    // stage into Uf layout: sUf[(i*8+c)][b_loc] with pad 17
    float* sUf = (float*)sb;
    int wy = warp >> 1, wx = warp & 1, g = lane >> 2, tig = lane & 3;
    #pragma unroll
    for (int mt = 0; mt < 2; mt++)
        #pragma unroll
        for (int vt = 0; vt < 8; vt++) {
            int r0 = wy * 32 + mt * 16 + g;
            int cc = wx * 64 + vt * 8 + tig * 2;
            int b_ = cc >> 3, cA = cc & 7, cB = (cc + 1) & 7;
            sUf[(r0 * 8 + cA) * 17 + b_]       = c[mt][vt][0];
            sUf[(r0 * 8 + cB) * 17 + b_]       = c[mt][vt][1];
            sUf[((r0 + 8) * 8 + cA) * 17 + b_] = c[mt][vt][2];
            sUf[((r0 + 8) * 8 + cB) * 17 + b_] = c[mt][vt][3];
        }
    __syncthreads();
    size_t gbase = ((size_t)(kk * 4 + z) * 1024) * 128 + (n0 >> 3);
    for (int idx = t; idx < 16384; idx += 256) {
        int r = idx >> 4, j = idx & 15;
        float v = sUf[r * 17 + j];
        __nv_bfloat16 h = __float2bfloat16(v);
        size_t off = gbase + (size_t)r * 128 + j;
        g_Ufhi[off] = h;
        g_Uflo[off] = __float2bfloat16(v - __bfloat162float(h));
    }
}

// ---- F = Uf @ qz^T : grid (8 mtile, 4 z, 2 k) ----
__global__ void __launch_bounds__(256) k_Fg() {
    extern __shared__ __nv_bfloat16 sb[];
    __nv_bfloat16 *Ah = sb, *Al = sb + 128 * 136, *Bh = sb + 2 * 128 * 136, *Bl = sb + 3 * 128 * 136;
    int t = threadIdx.x;
    int m0 = blockIdx.x * 128, z = blockIdx.y, k = blockIdx.z;
    size_t ubase = ((size_t)(k * 4 + z) * 1024 + m0) * 128;
    load_preB(Ah, Al, g_Ufhi + ubase, g_Uflo + ubase, 128, t);
    load_splitA(Bh, Bl, g_qz + (size_t)z * 16384, 128, t);
    __syncthreads();
    int lane = t & 31, warp = t >> 5;
    float c[2][8][4];
    #pragma unroll
    for (int i = 0; i < 2; i++)
        #pragma unroll
        for (int j = 0; j < 8; j++)
            #pragma unroll
            for (int q = 0; q < 4; q++) c[i][j][q] = 0.f;
    mma_core(c, Ah, Al, Bh, Bl, lane, warp);
    int wy = warp >> 1, wx = warp & 1, g = lane >> 2, tig = lane & 3;
    float* C = g_F + (size_t)(k * 4 + z) * 131072;
    #pragma unroll
    for (int mt = 0; mt < 2; mt++)
        #pragma unroll
        for (int vt = 0; vt < 8; vt++) {
            int r0 = m0 + wy * 32 + mt * 16 + g;
            int cc = wx * 64 + vt * 8 + tig * 2;
            *(float2*)&C[(size_t)r0 * 128 + cc]       = make_float2(c[mt][vt][0], c[mt][vt][1]);
            *(float2*)&C[(size_t)(r0 + 8) * 128 + cc] = make_float2(c[mt][vt][2], c[mt][vt][3]);
        }
}

// ---- select + mask + row softmax -> qhn ----
__global__ void __launch_bounds__(256) k_Fsm(const int* __restrict__ mask) {
    int zi = blockIdx.x, z = zi >> 7, i = zi & 127;
    int t = threadIdx.x;
    __shared__ float qh_sh[8][128];
    __shared__ float smax[8], ssum[8];
    int j = t & 127, ch = t >> 7;
    bool vi = mask[z * 128 + i] != 0, vj = mask[z * 128 + j] != 0;
    int ksel = (j > i) ? 0 : 1;
    const float* Fb = g_F + (size_t)(ksel * 4 + z) * 131072 + (size_t)(i * 8) * 128;
    float vals[4];
    #pragma unroll
    for (int hh = 0; hh < 4; hh++) {
        int c = ch * 4 + hh;
        float v = Fb[c * 128 + j];
        if (i == j || !vi || !vj) v = -NEGC;
        vals[hh] = v;
        qh_sh[c][j] = v;
    }
    __syncthreads();
    int w = t >> 5, lane = t & 31;
    float v0 = qh_sh[w][lane], v1 = qh_sh[w][lane + 32];
    float v2 = qh_sh[w][lane + 64], v3 = qh_sh[w][lane + 96];
    float mx = fmaxf(fmaxf(v0, v1), fmaxf(v2, v3));
    #pragma unroll
    for (int o = 16; o; o >>= 1) mx = fmaxf(mx, __shfl_xor_sync(~0u, mx, o));
    float sum = fexp_s(v0 - mx) + fexp_s(v1 - mx) + fexp_s(v2 - mx) + fexp_s(v3 - mx);
    #pragma unroll
    for (int o = 16; o; o >>= 1) sum += __shfl_xor_sync(~0u, sum, o);
    if (lane == 0) { smax[w] = mx; ssum[w] = sum; }
    __syncthreads();
    #pragma unroll
    for (int hh = 0; hh < 4; hh++) {
        int h = ch * 4 + hh;
        float p = fexp_s(vals[hh] - smax[h]) / ssum[h];
        g_qhn[(((z * 8 + h) * 128 + i) << 7) + j] = p;
    }
}

// ---- Gpart = S @ BmatT (split-K 32) ----
__global__ void __launch_bounds__(256) k_g_h() {
    extern __shared__ __nv_bfloat16 sb[];
    __nv_bfloat16 *Ah = sb, *Al = sb + 128 * 136, *Bh = sb + 2 * 128 * 136, *Bl = sb + 3 * 128 * 136;
    int t = threadIdx.x;
    int m0 = blockIdx.x * 128, kb = blockIdx.y * 128;
    load_splitA(Ah, Al, g_S + (size_t)m0 * 4096 + kb, 4096, t);
    load_preB(Bh, Bl, g_BThi + kb, g_BTlo + kb, 4096, t);
    __syncthreads();
    int lane = t & 31, warp = t >> 5;
    float c[2][8][4];
    #pragma unroll
    for (int i = 0; i < 2; i++)
        #pragma unroll
        for (int j = 0; j < 8; j++)
            #pragma unroll
            for (int q = 0; q < 4; q++) c[i][j][q] = 0.f;
    mma_core(c, Ah, Al, Bh, Bl, lane, warp);
    int wy = warp >> 1, wx = warp & 1, g = lane >> 2, tig = lane & 3;
    #pragma unroll
    for (int mt = 0; mt < 2; mt++)
        #pragma unroll
        for (int vt = 0; vt < 8; vt++) {
            int r0 = m0 + wy * 32 + mt * 16 + g;
            int cc = wx * 64 + vt * 8 + tig * 2;
            *(float2*)&g_Gpart[((size_t)blockIdx.y * 512 + r0) * 128 + cc] =
                make_float2(c[mt][vt][0], c[mt][vt][1]);
            *(float2*)&g_Gpart[((size_t)blockIdx.y * 512 + r0 + 8) * 128 + cc] =
                make_float2(c[mt][vt][2], c[mt][vt][3]);
        }
}

// ---- S = W(32x128) @ qz(128x128) per zi ----
#define SH2_SMEM ((32 * 136 * 2 + 2 * 128 * 136) * 2)
__global__ void __launch_bounds__(256) k_S_h() {
    extern __shared__ __nv_bfloat16 sb[];
    __nv_bfloat16 *Wh = sb, *Wl = sb + 32 * 136;
    __nv_bfloat16 *Bh = sb + 64 * 136, *Bl = sb + 64 * 136 + 128 * 136;
    int zi = blockIdx.x, z = zi >> 7, i = zi & 127;
    int t = threadIdx.x;
    for (int idx = t; idx < 4096; idx += 256) {
        int r = idx >> 7, j = idx & 127;
        float v; bool m;
        if (r < 16) {
            int k = r >> 3, c = r & 7;
            v = g_qhn[(((z * 8 + c) * 128 + i) << 7) + j];
            m = (k == 0) ? (j > i) : (j < i);
        } else {
            int r2 = r - 16, k = r2 >> 3, c = r2 & 7;
            v = g_qhnT[(((z * 8 + c) * 128 + i) << 7) + j];
            m = (k == 0) ? (j < i) : (j > i);
        }
        v = m ? v : 0.f;
        __nv_bfloat16 h = __float2bfloat16(v);
        Wh[r * 136 + j] = h;
        Wl[r * 136 + j] = __float2bfloat16(v - __bfloat162float(h));
    }
    load_preB(Bh, Bl, g_qzThi + z * 16384, g_qzTlo + z * 16384, 128, t);
    __syncthreads();
    int lane = t & 31, warp = t >> 5;
    int wy = warp >> 2, wx = warp & 3;
    int g = lane >> 2, tig = lane & 3;
    float c[4][4];
    #pragma unroll
    for (int j = 0; j < 4; j++)
        #pragma unroll
        for (int q = 0; q < 4; q++) c[j][q] = 0.f;
    #pragma unroll
    for (int ks = 0; ks < 8; ks++) {
        int k0 = ks * 16;
        uint32_t aH[4], aL[4];
        int base = (wy * 16 + g) * 136 + k0;
        aH[0] = *(uint32_t*)&Wh[base + tig * 2];
        aH[1] = *(uint32_t*)&Wh[base + 8 * 136 + tig * 2];
        aH[2] = *(uint32_t*)&Wh[base + tig * 2 + 8];
        aH[3] = *(uint32_t*)&Wh[base + 8 * 136 + tig * 2 + 8];
        aL[0] = *(uint32_t*)&Wl[base + tig * 2];
        aL[1] = *(uint32_t*)&Wl[base + 8 * 136 + tig * 2];
        aL[2] = *(uint32_t*)&Wl[base + tig * 2 + 8];
        aL[3] = *(uint32_t*)&Wl[base + 8 * 136 + tig * 2 + 8];
        #pragma unroll
        for (int vt = 0; vt < 4; vt++) {
            int basev = (wx * 32 + vt * 8 + g) * 136 + k0;
            uint32_t bH[2] = {*(uint32_t*)&Bh[basev + tig * 2], *(uint32_t*)&Bh[basev + tig * 2 + 8]};
            uint32_t bL[2] = {*(uint32_t*)&Bl[basev + tig * 2], *(uint32_t*)&Bl[basev + tig * 2 + 8]};
            mma16816(c[vt], aH, bH);
            mma16816(c[vt], aH, bL);
            mma16816(c[vt], aL, bH);
        }
    }
    #pragma unroll
    for (int vt = 0; vt < 4; vt++) {
        int r0 = wy * 16 + g;
        int cc = wx * 32 + vt * 8 + tig * 2;
        int base0 = (r0 < 16) ? r0 * 128 : 2048 + (r0 - 16) * 128;
        int r1 = r0 + 8;
        int base1 = (r1 < 16) ? r1 * 128 : 2048 + (r1 - 16) * 128;
        *(float2*)&g_S[(size_t)zi * 4096 + base0 + cc] = make_float2(c[vt][0], c[vt][1]);
        *(float2*)&g_S[(size_t)zi * 4096 + base1 + cc] = make_float2(c[vt][2], c[vt][3]);
    }
}

__global__ void __launch_bounds__(256) k_trq() {
    __shared__ float tile[32][33];
    int zh = blockIdx.x;
    int ti = blockIdx.y >> 2, tj = blockIdx.y & 3;
    int t = threadIdx.x;
    int r = t >> 5, c = t & 31;
    const float* src = g_qhn + ((size_t)zh << 14);
    float* dst = g_qhnT + ((size_t)zh << 14);
    #pragma unroll
    for (int q = 0; q < 4; q++)
        tile[r + q * 8][c] = src[(ti * 32 + r + q * 8) * 128 + tj * 32 + c];
    __syncthreads();
    #pragma unroll
    for (int q = 0; q < 4; q++)
        dst[(tj * 32 + r + q * 8) * 128 + ti * 32 + c] = tile[c][r + q * 8];
}

__global__ void k_sered() {
    int count = g_mcount;
    int pos = blockIdx.x;
    if (pos >= count) return;
    int ntiles = (count + 127) >> 7;
    int mt = pos >> 7, row = pos & 127;
    int gb0 = (mt * 148 + ntiles - 1) / ntiles;
    int gb1 = ((mt + 1) * 148 + ntiles - 1) / ntiles;
    int d = threadIdx.x;
    float num = 0.f, den = 0.f;
    for (int bb = gb0; bb < gb1; bb++) {
        num += g_SEpart[((size_t)bb * 128 + row) * 128 + d];
        den += g_SEsum[bb * 128 + row];
    }
    g_SE[pos * 128 + d] = num / den;
}

// z update + fused qzT emission
__global__ void k_zupd(const float* __restrict__ x, const int* __restrict__ mask,
                       const int* __restrict__ mmask, int useSE) {
    int zi = blockIdx.x, d = threadIdx.x;
    __shared__ float r1[4], r2[4];
    float g = 0.f;
    #pragma unroll 8
    for (int p = 0; p < 32; p++) g += g_Gpart[((size_t)p * 512 + zi) * 128 + d];
    float mm = (float)mmask[zi];
    float se = 0.f;
    if (mm != 0.f) {
        if (useSE) {
            int pos = g_mpos[zi];
            if (pos >= 0) se = g_SE[pos * 128 + d];
        } else se = g_emean[d];
    }
    float raw = x[zi * 128 + d] * (1.f - mm) + se * mm + g;
    float keep = mask[zi] ? 1.f : 0.f;
    float p_ = softmax128(raw, r1, r2);
    float v = p_ * keep;
    g_qz[zi * 128 + d] = v;
    int z = zi >> 7, i = zi & 127;
    __nv_bfloat16 h = __float2bfloat16(v);
    g_qzThi[z * 16384 + d * 128 + i] = h;
    g_qzTlo[z * 16384 + d * 128 + i] = __float2bfloat16(v - __bfloat162float(h));
}

// ==================== fused SE via mma ====================
#define SH_T 17408
#define SEFH_SMEM (6 * SH_T * 2 + 1024)

__global__ void __launch_bounds__(256) k_sef_h() {
    int count = g_mcount;
    if (count == 0) return;
    int ntiles = (count + 127) >> 7;
    int b = blockIdx.x;
    int mt_ = (b * ntiles) / 148;
    int gb0 = (mt_ * 148 + ntiles - 1) / ntiles;
    int gb1 = ((mt_ + 1) * 148 + ntiles - 1) / ntiles;
    int gsz = gb1 - gb0, li = b - gb0;
    int ustart = (li * 250) / gsz;
    int ucount = ((li + 1) * 250) / gsz - ustart;
    int m0 = mt_ * 128;

    extern __shared__ __nv_bfloat16 shb[];
    __nv_bfloat16* Ah = shb;
    __nv_bfloat16* Al = shb + SH_T;
    __nv_bfloat16* Bh = shb + 2 * SH_T;
    __nv_bfloat16* Bl = shb + 3 * SH_T;
    __nv_bfloat16* Ph = shb + 4 * SH_T;
    __nv_bfloat16* Pl = shb + 5 * SH_T;
    float* psum_s = (float*)(shb + 6 * SH_T);

    int t = threadIdx.x;
    {
        int row = t >> 1, half = t & 1;
        int pos = m0 + row;
        int zi = (pos < count) ? g_midx[pos] : 0;
        const float* src = g_qz + (size_t)zi * 128 + half * 64;
        int dof = row * 136 + half * 64;
        #pragma unroll
        for (int q = 0; q < 16; q++) {
            float4 v = *(const float4*)(src + q * 4);
            __nv_bfloat162 h01, l01, h23, l23;
            split2(v.x, v.y, h01, l01);
            split2(v.z, v.w, h23, l23);
            *(__nv_bfloat162*)&Ah[dof + q * 4]     = h01;
            *(__nv_bfloat162*)&Ah[dof + q * 4 + 2] = h23;
            *(__nv_bfloat162*)&Al[dof + q * 4]     = l01;
            *(__nv_bfloat162*)&Al[dof + q * 4 + 2] = l23;
        }
    }

    int lane = t & 31, warp = t >> 5;
    int wy = warp >> 1, wx = warp & 1;
    int g = lane >> 2, tig = lane & 3;
    float c2[2][8][4];
    #pragma unroll
    for (int i = 0; i < 2; i++)
        #pragma unroll
        for (int j = 0; j < 8; j++)
            #pragma unroll
            for (int q = 0; q < 4; q++) c2[i][j][q] = 0.f;
    float psr[2][2] = {{0.f, 0.f}, {0.f, 0.f}};

    for (int tile = 0; tile < ucount; tile++) {
        int vg = (ustart + tile) * 128;
        __syncthreads();
        load_preB(Bh, Bl, g_Ehi + (size_t)vg * 128, g_Elo + (size_t)vg * 128, 128, t);
        __syncthreads();
        float c1[2][8][4];
        #pragma unroll
        for (int i = 0; i < 2; i++)
            #pragma unroll
            for (int j = 0; j < 8; j++)
                #pragma unroll
                for (int q = 0; q < 4; q++) c1[i][j][q] = 0.f;
        mma_core(c1, Ah, Al, Bh, Bl, lane, warp);
        #pragma unroll
        for (int mt = 0; mt < 2; mt++)
            #pragma unroll
            for (int vt = 0; vt < 8; vt++) {
                float e0 = fexp(c1[mt][vt][0]), e1 = fexp(c1[mt][vt][1]);
                float e2 = fexp(c1[mt][vt][2]), e3 = fexp(c1[mt][vt][3]);
                psr[mt][0] += e0 + e1;
                psr[mt][1] += e2 + e3;
                int r0 = wy * 32 + mt * 16 + g;
                int col = wx * 64 + vt * 8 + tig * 2;
                __nv_bfloat162 h01, l01, h23, l23;
                split2(e0, e1, h01, l01);
                split2(e2, e3, h23, l23);
                *(__nv_bfloat162*)&Ph[r0 * 136 + col] = h01;
                *(__nv_bfloat162*)&Pl[r0 * 136 + col] = l01;
                *(__nv_bfloat162*)&Ph[(r0 + 8) * 136 + col] = h23;
                *(__nv_bfloat162*)&Pl[(r0 + 8) * 136 + col] = l23;
            }
        __syncthreads();
        load_preB(Bh, Bl, g_EThi + vg, g_ETlo + vg, 32000, t);
        __syncthreads();
        mma_core(c2, Ph, Pl, Bh, Bl, lane, warp);
    }
    #pragma unroll
    for (int mt = 0; mt < 2; mt++)
        #pragma unroll
        for (int dt = 0; dt < 8; dt++) {
            int r0 = wy * 32 + mt * 16 + g;
            int col = wx * 64 + dt * 8 + tig * 2;
            *(float2*)&g_SEpart[((size_t)b * 128 + r0) * 128 + col] =
                make_float2(c2[mt][dt][0], c2[mt][dt][1]);
            *(float2*)&g_SEpart[((size_t)b * 128 + r0 + 8) * 128 + col] =
                make_float2(c2[mt][dt][2], c2[mt][dt][3]);
        }
    #pragma unroll
    for (int mt = 0; mt < 2; mt++)
        #pragma unroll
        for (int h = 0; h < 2; h++) {
            float v = psr[mt][h];
            v += __shfl_xor_sync(~0u, v, 1);
            v += __shfl_xor_sync(~0u, v, 2);
            psr[mt][h] = v;
        }
    if (tig == 0) {
        #pragma unroll
        for (int mt = 0; mt < 2; mt++)
            #pragma unroll
            for (int h = 0; h < 2; h++)
                psum_s[wx * 128 + wy * 32 + mt * 16 + g + h * 8] = psr[mt][h];
    }
    __syncthreads();
    if (t < 128) g_SEsum[b * 128 + t] = psum_s[t] + psum_s[128 + t];
}

// ==================== final out = qz @ E^T ====================
__global__ void __launch_bounds__(256) k_msg_h(float* __restrict__ out) {
    extern __shared__ __nv_bfloat16 smh[];
    __nv_bfloat16 *Ah = smh, *Al = smh + 128 * 136, *Bh = smh + 2 * 128 * 136, *Bl = smh + 3 * 128 * 136;
    int t = threadIdx.x;
    int v0 = blockIdx.x * 128, m0 = blockIdx.y * 128;
    load_splitA(Ah, Al, g_qz + (size_t)m0 * 128, 128, t);
    load_preB(Bh, Bl, g_Ehi + (size_t)v0 * 128, g_Elo + (size_t)v0 * 128, 128, t);
    __syncthreads();
    int lane = t & 31, warp = t >> 5;
    float c[2][8][4];
    #pragma unroll
    for (int i = 0; i < 2; i++)
        #pragma unroll
        for (int j = 0; j < 8; j++)
            #pragma unroll
            for (int q = 0; q < 4; q++) c[i][j][q] = 0.f;
    mma_core(c, Ah, Al, Bh, Bl, lane, warp);
    int wy = warp >> 1, wx = warp & 1, g = lane >> 2, tig = lane & 3;
    #pragma unroll
    for (int mt = 0; mt < 2; mt++)
        #pragma unroll
        for (int vt = 0; vt < 8; vt++) {
            int r0 = m0 + wy * 32 + mt * 16 + g;
            int cc = v0 + wx * 64 + vt * 8 + tig * 2;
            *(float2*)&out[(size_t)r0 * 32000 + cc]       = make_float2(c[mt][vt][0], c[mt][vt][1]);
            *(float2*)&out[(size_t)(r0 + 8) * 32000 + cc] = make_float2(c[mt][vt][2], c[mt][vt][3]);
        }
}

// ==================== launch ====================
extern "C" void kernel_launch(void* const* d_in, const int* in_sizes, int n_in,
                              void* d_out, int out_size) {
    const float* x    = (const float*)d_in[0];
    const int*   mask = (const int*)d_in[1];
    const float* E    = (const float*)d_in[2];
    const int*   mm   = (const int*)d_in[3];
    const float* T    = (const float*)d_in[4];
    float* out = (float*)d_out;

    static cudaStream_t s2 = nullptr;
    static cudaEvent_t eF = nullptr, eJ = nullptr;
    if (!s2) {
        cudaStreamCreate(&s2);
        cudaEventCreateWithFlags(&eF, cudaEventDisableTiming);
        cudaEventCreateWithFlags(&eJ, cudaEventDisableTiming);
        cudaFuncSetAttribute(k_sef_h, cudaFuncAttributeMaxDynamicSharedMemorySize, SEFH_SMEM);
        cudaFuncSetAttribute(k_msg_h, cudaFuncAttributeMaxDynamicSharedMemorySize, STD_SMEM);
        cudaFuncSetAttribute(k_U_h,   cudaFuncAttributeMaxDynamicSharedMemorySize, STD_SMEM);
        cudaFuncSetAttribute(k_Fg,    cudaFuncAttributeMaxDynamicSharedMemorySize, STD_SMEM);
        cudaFuncSetAttribute(k_g_h,   cudaFuncAttributeMaxDynamicSharedMemorySize, STD_SMEM);
        cudaFuncSetAttribute(k_S_h,   cudaFuncAttributeMaxDynamicSharedMemorySize, SH2_SMEM);
    }
    cudaStream_t s0 = 0;

    cudaEventRecord(eF, s0);
    cudaStreamWaitEvent(s2, eF, 0);
    k_transE<<<dim3(250, 4), 256, 0, s2>>>(E);
    k_splitE<<<250, 256, 0, s2>>>(E);

    k_emean_part<<<64, 256, 0, s0>>>(E);
    k_emean_red<<<1, 128, 0, s0>>>();
    k_bmat<<<2048, 256, 0, s0>>>(T);
    k_trB<<<dim3(128, 4), 256, 0, s0>>>();
    k_trT<<<dim3(32, 4, 2), 256, 0, s0>>>(T);
    k_midx<<<1, 512, 0, s0>>>(mask, mm);
    k_init_qz<<<512, 128, 0, s0>>>(x, mask, mm);

    for (int it = 0; it < 4; it++) {
        k_U_h<<<dim3(8, 4, 2), 256, STD_SMEM, s0>>>();
        k_Fg<<<dim3(8, 4, 2), 256, STD_SMEM, s0>>>();
        k_Fsm<<<512, 256, 0, s0>>>(mask);
        k_trq<<<dim3(32, 16), 256, 0, s0>>>();
        k_S_h<<<512, 256, SH2_SMEM, s0>>>();
        k_g_h<<<dim3(4, 32), 256, STD_SMEM, s0>>>();
        if (it > 0) cudaStreamWaitEvent(s0, eJ, 0);
        k_zupd<<<512, 128, 0, s0>>>(x, mask, mm, it > 0);
        if (it < 3) {
            cudaEventRecord(eF, s0);
            cudaStreamWaitEvent(s2, eF, 0);
            k_sef_h<<<148, 256, SEFH_SMEM, s2>>>();
            k_sered<<<512, 128, 0, s2>>>();
            cudaEventRecord(eJ, s2);
        } else {
            k_msg_h<<<dim3(250, 4), 256, STD_SMEM, s0>>>(out);
        }
    }
}